// round 6
// baseline (speedup 1.0000x reference)
#include <cuda_runtime.h>
#include <math.h>

#define NPTS 131072

typedef unsigned long long ull;

// ------------- global scratch -------------
__device__ float g_origin[2];
__device__ float g_y[NPTS * 2];
__device__ float g_jinv[NPTS * 4];
__device__ float g_xdh[NPTS * 2];

__device__ __forceinline__ float eluf(float v) { return v > 0.f ? v : expm1f(v); }
__device__ __forceinline__ float softplusf(float p) {
    return fmaxf(p, 0.f) + log1pf(expf(-fabsf(p)));
}

// ---- packed f32x2 helpers (Blackwell FFMA2 via PTX fma.rn.f32x2) ----
__device__ __forceinline__ ull pk2(float a, float b) {
    ull r; asm("mov.b64 %0,{%1,%2};" : "=l"(r) : "f"(a), "f"(b)); return r;
}
__device__ __forceinline__ ull bc2(float a) { return pk2(a, a); }
__device__ __forceinline__ void upk2(ull v, float& a, float& b) {
    asm("mov.b64 {%0,%1},%2;" : "=f"(a), "=f"(b) : "l"(v));
}
__device__ __forceinline__ void fma2(ull& d, ull a, ull b) {
    asm("fma.rn.f32x2 %0, %1, %2, %0;" : "+l"(d) : "l"(a), "l"(b));
}

#define GS2(r, AB, U0, U1)            \
    fma2(acc[r][0], AB, U0.x);        \
    fma2(acc[r][1], AB, U0.y);        \
    fma2(acc[r][2], AB, U1.x);        \
    fma2(acc[r][3], AB, U1.y);

// ========================= K0: origin = taskmap(0) =========================
__global__ void k_origin(const float* __restrict__ w1, const float* __restrict__ b1,
                         const float* __restrict__ w2, const float* __restrict__ b2,
                         const float* __restrict__ w3, const float* __restrict__ b3,
                         const float* __restrict__ w4, const float* __restrict__ b4,
                         const float* __restrict__ w5, const float* __restrict__ b5,
                         const float* __restrict__ w6, const float* __restrict__ b6) {
    __shared__ float h[100], h2[100], y1s[2];
    int j = threadIdx.x;
    if (j < 100) h[j] = tanhf(b1[j]);
    __syncthreads();
    if (j < 100) {
        float a = b2[j];
        for (int k = 0; k < 100; k++) a = fmaf(h[k], w2[k * 100 + j], a);
        h2[j] = tanhf(a);
    }
    __syncthreads();
    if (j < 2) {
        float a = b3[j];
        for (int k = 0; k < 100; k++) a = fmaf(h2[k], w3[k * 2 + j], a);
        y1s[j] = a;
    }
    __syncthreads();
    if (j < 100) {
        float a = fmaf(y1s[0], w4[j], fmaf(y1s[1], w4[100 + j], b4[j]));
        h[j] = eluf(a);
    }
    __syncthreads();
    if (j < 100) {
        float a = b5[j];
        for (int k = 0; k < 100; k++) a = fmaf(h[k], w5[k * 100 + j], a);
        h2[j] = eluf(a);
    }
    __syncthreads();
    if (j < 2) {
        float a = b6[j];
        for (int k = 0; k < 100; k++) a = fmaf(h2[k], w6[k * 2 + j], a);
        float s = softplusf(a);
        g_origin[j] = (1.f + s) * y1s[j];
    }
}

// ========================= K1: taskmap + Jacobian ==========================
template <int ACT>  // 0 = tanh, 1 = elu
__device__ __forceinline__ void tm_mid(const float* __restrict__ W, const float* __restrict__ b,
                                       float* ws, float* bp, const float* inb, float* outb,
                                       int tid, bool active, int rg, int og) {
    for (int i = tid; i < 10400; i += 320) {
        int k = i / 104, j = i % 104;
        ws[i] = (j < 100) ? W[k * 100 + j] : 0.f;
    }
    if (tid < 104) bp[tid] = (tid < 100) ? b[tid] : 0.f;
    __syncthreads();

    const int row0 = rg * 8;
    const int jb = og * 8;
    const int comp = rg >> 3;

    ull acc[8][4];
#pragma unroll
    for (int r = 0; r < 8; r++)
#pragma unroll
        for (int q = 0; q < 4; q++) acc[r][q] = 0ULL;

    if (active) {
        for (int k = 0; k < 100; k += 4) {
            ulonglong2 wA0 = *(const ulonglong2*)(ws + (k + 0) * 104 + jb);
            ulonglong2 wA1 = *(const ulonglong2*)(ws + (k + 0) * 104 + jb + 4);
            ulonglong2 wB0 = *(const ulonglong2*)(ws + (k + 1) * 104 + jb);
            ulonglong2 wB1 = *(const ulonglong2*)(ws + (k + 1) * 104 + jb + 4);
            ulonglong2 wC0 = *(const ulonglong2*)(ws + (k + 2) * 104 + jb);
            ulonglong2 wC1 = *(const ulonglong2*)(ws + (k + 2) * 104 + jb + 4);
            ulonglong2 wD0 = *(const ulonglong2*)(ws + (k + 3) * 104 + jb);
            ulonglong2 wD1 = *(const ulonglong2*)(ws + (k + 3) * 104 + jb + 4);
#pragma unroll
            for (int r = 0; r < 8; r++) {
                float4 a = *(const float4*)(inb + (row0 + r) * 108 + k);
                GS2(r, bc2(a.x), wA0, wA1)
                GS2(r, bc2(a.y), wB0, wB1)
                GS2(r, bc2(a.z), wC0, wC1)
                GS2(r, bc2(a.w), wD0, wD1)
            }
        }
    }
    if (active && comp == 0) {
#pragma unroll
        for (int r = 0; r < 8; r++)
#pragma unroll
            for (int q = 0; q < 4; q++) {
                float v0, v1; upk2(acc[r][q], v0, v1);
                v0 += bp[jb + 2 * q];
                v1 += bp[jb + 2 * q + 1];
                outb[(row0 + r) * 108 + jb + 2 * q]     = (ACT == 0) ? tanhf(v0) : eluf(v0);
                outb[(row0 + r) * 108 + jb + 2 * q + 1] = (ACT == 0) ? tanhf(v1) : eluf(v1);
            }
    }
    __syncthreads();
    if (active && comp != 0) {
        const int pbase = row0 - comp * 64;
#pragma unroll
        for (int r = 0; r < 8; r++)
#pragma unroll
            for (int q = 0; q < 4; q++) {
                float v0, v1; upk2(acc[r][q], v0, v1);
                float h0 = outb[(pbase + r) * 108 + jb + 2 * q];
                float h1 = outb[(pbase + r) * 108 + jb + 2 * q + 1];
                float d0 = (ACT == 0) ? (1.f - h0 * h0) : (h0 > 0.f ? 1.f : h0 + 1.f);
                float d1 = (ACT == 0) ? (1.f - h1 * h1) : (h1 > 0.f ? 1.f : h1 + 1.f);
                outb[(row0 + r) * 108 + jb + 2 * q]     = v0 * d0;
                outb[(row0 + r) * 108 + jb + 2 * q + 1] = v1 * d1;
            }
    }
    __syncthreads();
}

__global__ __launch_bounds__(320, 1) void k_taskmap(
    const float* __restrict__ x,
    const float* __restrict__ w1, const float* __restrict__ b1,
    const float* __restrict__ w2, const float* __restrict__ b2,
    const float* __restrict__ w3, const float* __restrict__ b3,
    const float* __restrict__ w4, const float* __restrict__ b4,
    const float* __restrict__ w5, const float* __restrict__ b5,
    const float* __restrict__ w6, const float* __restrict__ b6) {
    extern __shared__ float sm[];
    float* ws   = sm;                  // 10400
    float* bufA = ws + 10400;          // 192*108 = 20736
    float* bufB = bufA + 20736;        // 20736
    float* xs   = bufB + 20736;        // 128
    float* v2   = xs + 128;            // 384
    float* ss   = v2 + 384;            // 128
    float* sg   = ss + 128;            // 128
    float* Jsh  = sg + 128;            // 256
    float* accb = Jsh + 256;           // 384
    float* bp   = accb + 384;          // 104  (cum 53384, even)
    ull* w3u    = (ull*)(bp + 104);    // 100 ull = 200 floats
    ull* w6u    = (ull*)(bp + 304);    // 100 ull = 200 floats

    const int tid = threadIdx.x;
    const bool active = tid < 312;
    const int rg = tid / 13;
    const int og = tid % 13;
    const int gbase = blockIdx.x * 64;

    if (tid < 128) xs[tid] = x[blockIdx.x * 128 + tid];
    if (tid >= 128 && tid < 228) w3u[tid - 128] = ((const ull*)w3)[tid - 128];
    if (tid >= 228 && tid < 320 + 8) { }
    if (tid >= 228 && tid < 320) w6u[tid - 228] = ((const ull*)w6)[tid - 228];
    if (tid < 8) w6u[92 + tid] = ((const ull*)w6)[92 + tid];
    __syncthreads();

    // ---- tm1 L1 (2 -> 100, tanh); value then tangent ----
    for (int i = tid; i < 6400; i += 320) {
        int p = i / 100, j = i % 100;
        float h = tanhf(fmaf(xs[p * 2], w1[j], fmaf(xs[p * 2 + 1], w1[100 + j], b1[j])));
        bufA[p * 108 + j] = h;
    }
    __syncthreads();
    for (int i = tid; i < 12800; i += 320) {
        int c = i / 6400, rem = i % 6400, p = rem / 100, j = rem % 100;
        float h = bufA[p * 108 + j];
        bufA[(64 + c * 64 + p) * 108 + j] = w1[c * 100 + j] * (1.f - h * h);
    }
    __syncthreads();

    // ---- tm1 L2 (100x100, tanh) ----
    tm_mid<0>(w2, b2, ws, bp, bufA, bufB, tid, active, rg, og);

    // ---- tm1 L3 (100 -> 2) packed, + residual / identity ----
    if (tid < 192) {
        int r = tid;
        const float* row = bufB + r * 108;
        ull a2 = 0ULL, a2b = 0ULL;
        for (int k = 0; k < 100; k += 4) {
            fma2(a2,  bc2(row[k + 0]), w3u[k + 0]);
            fma2(a2b, bc2(row[k + 1]), w3u[k + 1]);
            fma2(a2,  bc2(row[k + 2]), w3u[k + 2]);
            fma2(a2b, bc2(row[k + 3]), w3u[k + 3]);
        }
        float A0, A1, B0, B1; upk2(a2, A0, A1); upk2(a2b, B0, B1);
        A0 += B0; A1 += B1;
        int cmp = r / 64, p = r % 64;
        if (cmp == 0) {
            v2[r * 2 + 0] = A0 + b3[0] + xs[p * 2 + 0];
            v2[r * 2 + 1] = A1 + b3[1] + xs[p * 2 + 1];
        } else {
            v2[r * 2 + 0] = A0 + ((cmp - 1) == 0 ? 1.f : 0.f);
            v2[r * 2 + 1] = A1 + ((cmp - 1) == 1 ? 1.f : 0.f);
        }
    }
    __syncthreads();

    // ---- tm2 L1 (2 -> 100, elu); value then tangent ----
    for (int i = tid; i < 6400; i += 320) {
        int p = i / 100, j = i % 100;
        float a = fmaf(v2[p * 2], w4[j], fmaf(v2[p * 2 + 1], w4[100 + j], b4[j]));
        bufA[p * 108 + j] = eluf(a);
    }
    __syncthreads();
    for (int i = tid; i < 12800; i += 320) {
        int c = i / 6400, rem = i % 6400, p = rem / 100, j = rem % 100;
        int r = 64 + c * 64 + p;
        float raw = fmaf(v2[r * 2], w4[j], v2[r * 2 + 1] * w4[100 + j]);
        float h = bufA[p * 108 + j];
        bufA[r * 108 + j] = raw * (h > 0.f ? 1.f : h + 1.f);
    }
    __syncthreads();

    // ---- tm2 L2 (100x100, elu) ----
    tm_mid<1>(w5, b5, ws, bp, bufA, bufB, tid, active, rg, og);

    // ---- tm2 L3 (100 -> 2) packed + softplus gate + y + J + pinv ----
    if (tid < 192) {
        int r = tid;
        const float* row = bufB + r * 108;
        ull a2 = 0ULL, a2b = 0ULL;
        for (int k = 0; k < 100; k += 4) {
            fma2(a2,  bc2(row[k + 0]), w6u[k + 0]);
            fma2(a2b, bc2(row[k + 1]), w6u[k + 1]);
            fma2(a2,  bc2(row[k + 2]), w6u[k + 2]);
            fma2(a2b, bc2(row[k + 3]), w6u[k + 3]);
        }
        float A0, A1, B0, B1; upk2(a2, A0, A1); upk2(a2b, B0, B1);
        A0 += B0; A1 += B1;
        if (r < 64) {
            float pv0 = A0 + b6[0], pv1 = A1 + b6[1];
            float s0 = softplusf(pv0), s1 = softplusf(pv1);
            ss[r * 2 + 0] = s0; ss[r * 2 + 1] = s1;
            sg[r * 2 + 0] = 1.f / (1.f + expf(-pv0));
            sg[r * 2 + 1] = 1.f / (1.f + expf(-pv1));
            g_y[(gbase + r) * 2 + 0] = (1.f + s0) * v2[r * 2 + 0] - g_origin[0];
            g_y[(gbase + r) * 2 + 1] = (1.f + s1) * v2[r * 2 + 1] - g_origin[1];
        } else {
            accb[r * 2 + 0] = A0;
            accb[r * 2 + 1] = A1;
        }
    }
    __syncthreads();
    if (tid < 256) {
        int r = 64 + (tid >> 1), i = tid & 1;
        int c = r / 64 - 1, p = r % 64;
        float acc = accb[r * 2 + i];
        float s = ss[p * 2 + i];
        float ds = sg[p * 2 + i] * acc;
        Jsh[p * 4 + i * 2 + c] = fmaf(ds, v2[p * 2 + i], (1.f + s) * v2[r * 2 + i]);
    }
    __syncthreads();
    if (tid < 64) {
        int p = tid, gp = gbase + p;
        float a = Jsh[p * 4 + 0], b_ = Jsh[p * 4 + 1];
        float c = Jsh[p * 4 + 2], d = Jsh[p * 4 + 3];
        float det = a * d - b_ * c;
        float n2 = a * a + b_ * b_ + c * c + d * d;
        float ia, ib, ic, id;
        if (fabsf(det) > 1e-10f * n2) {
            float inv = 1.f / det;
            ia = d * inv; ib = -b_ * inv; ic = -c * inv; id = a * inv;
        } else {
            float inv = (n2 > 0.f) ? 1.f / n2 : 0.f;
            ia = a * inv; ib = c * inv; ic = b_ * inv; id = d * inv;
        }
        float4 o; o.x = ia; o.y = ib; o.z = ic; o.w = id;
        *reinterpret_cast<float4*>(g_jinv + gp * 4) = o;
    }
}

// ====================== K2: vv net + yd + J^-1 * yd_n ======================
__global__ __launch_bounds__(320, 1) void k_vv(
    const float* __restrict__ w1, const float* __restrict__ b1, const float* __restrict__ a1p,
    const float* __restrict__ w2, const float* __restrict__ b2, const float* __restrict__ a2p,
    const float* __restrict__ w3, const float* __restrict__ b3) {
    extern __shared__ float sm[];
    float* ws   = sm;                  // 100*304 = 30400
    float* bufA = ws + 30400;          // 64*308 = 19712
    float* ys   = bufA + 19712;        // 128
    float* b2p  = ys + 128;            // 304   (cum 50544, even)
    ull* w3u    = (ull*)(b2p + 304);   // 304 ull = 608 floats
    float* dsum = b2p + 304 + 608;     // 128

    const int tid = threadIdx.x;
    const bool active = tid < 304;
    const int rg = tid / 38;
    const int og = tid % 38;
    const int row0 = rg * 8;
    const int jb = og * 8;
    const int gbase = blockIdx.x * 64;

    if (tid < 128) ys[tid] = g_y[blockIdx.x * 128 + tid];
    for (int i = tid; i < 304; i += 320) {
        b2p[i] = (i < 300) ? b2[i] : 0.f;
        w3u[i] = (i < 300) ? ((const ull*)w3)[i] : 0ULL;
    }
    if (tid < 128) dsum[tid] = b3[tid & 1];
    const float al1 = a1p[0], al2 = a2p[0];
    __syncthreads();

    // L1: 2 -> 300, PReLU
    for (int i = tid; i < 19200; i += 320) {
        int p = i / 300, j = i % 300;
        float v = fmaf(ys[p * 2], w1[j], fmaf(ys[p * 2 + 1], w1[300 + j], b1[j]));
        bufA[p * 308 + j] = (v >= 0.f) ? v : al1 * v;
    }
    __syncthreads();

    // L2: 300x300 GEMM, 3 K-chunks of 100
    ull acc[8][4];
#pragma unroll
    for (int r = 0; r < 8; r++)
#pragma unroll
        for (int q = 0; q < 4; q++) acc[r][q] = 0ULL;

    for (int c = 0; c < 3; c++) {
        for (int i = tid; i < 30400; i += 320) {
            int kk = i / 304, j = i % 304;
            ws[i] = (j < 300) ? w2[(c * 100 + kk) * 300 + j] : 0.f;
        }
        __syncthreads();
        if (active) {
            const int kb = c * 100;
            for (int k = 0; k < 100; k += 4) {
                ulonglong2 wA0 = *(const ulonglong2*)(ws + (k + 0) * 304 + jb);
                ulonglong2 wA1 = *(const ulonglong2*)(ws + (k + 0) * 304 + jb + 4);
                ulonglong2 wB0 = *(const ulonglong2*)(ws + (k + 1) * 304 + jb);
                ulonglong2 wB1 = *(const ulonglong2*)(ws + (k + 1) * 304 + jb + 4);
                ulonglong2 wC0 = *(const ulonglong2*)(ws + (k + 2) * 304 + jb);
                ulonglong2 wC1 = *(const ulonglong2*)(ws + (k + 2) * 304 + jb + 4);
                ulonglong2 wD0 = *(const ulonglong2*)(ws + (k + 3) * 304 + jb);
                ulonglong2 wD1 = *(const ulonglong2*)(ws + (k + 3) * 304 + jb + 4);
#pragma unroll
                for (int r = 0; r < 8; r++) {
                    float4 a = *(const float4*)(bufA + (row0 + r) * 308 + kb + k);
                    GS2(r, bc2(a.x), wA0, wA1)
                    GS2(r, bc2(a.y), wB0, wB1)
                    GS2(r, bc2(a.z), wC0, wC1)
                    GS2(r, bc2(a.w), wD0, wD1)
                }
            }
        }
        __syncthreads();
    }

    // PReLU + fused L3 partial dots (packed: lanes carry (d0,d1))
    if (active) {
#pragma unroll
        for (int r = 0; r < 8; r++) {
            ull d01 = 0ULL;
#pragma unroll
            for (int q = 0; q < 4; q++) {
                float h0, h1; upk2(acc[r][q], h0, h1);
                int j = jb + 2 * q;
                h0 += b2p[j]; h1 += b2p[j + 1];
                h0 = (h0 >= 0.f) ? h0 : al2 * h0;
                h1 = (h1 >= 0.f) ? h1 : al2 * h1;
                fma2(d01, bc2(h0), w3u[j]);
                fma2(d01, bc2(h1), w3u[j + 1]);
            }
            float d0, d1; upk2(d01, d0, d1);
            atomicAdd(&dsum[(row0 + r) * 2 + 0], d0);
            atomicAdd(&dsum[(row0 + r) * 2 + 1], d1);
        }
    }
    __syncthreads();

    if (tid < 64) {
        int p = tid, gp = gbase + p;
        float d0 = dsum[p * 2 + 0], d1 = dsum[p * 2 + 1];
        float y0 = ys[p * 2 + 0], y1 = ys[p * 2 + 1];
        float lsv = d0 * y0 + d1 * y1;
        float Vy = y0 * y0 + y1 * y1;
        float rl = fmaxf(fmaf(1e-4f, Vy, lsv), 0.f);
        float sc = rl / (Vy + 1e-12f);
        float yd0 = d0 - sc * y0, yd1 = d1 - sc * y1;
        float nrm = sqrtf(yd0 * yd0 + yd1 * yd1);
        float innv = 1.f / fmaxf(nrm, 1e-12f);
        float n0 = yd0 * innv, n1 = yd1 * innv;
        float4 Ji = *reinterpret_cast<const float4*>(g_jinv + gp * 4);
        g_xdh[gp * 2 + 0] = Ji.x * n0 + Ji.y * n1;
        g_xdh[gp * 2 + 1] = Ji.z * n0 + Ji.w * n1;
    }
}

// =================== K3: vel-scalar net + final scaling ====================
__global__ __launch_bounds__(224, 2) void k_vs(
    const float* __restrict__ x,
    const float* __restrict__ w1, const float* __restrict__ b1,
    const float* __restrict__ w2, const float* __restrict__ b2,
    const float* __restrict__ w3, const float* __restrict__ b3,
    float* __restrict__ out) {
    extern __shared__ float sm[];
    float* ws   = sm;                  // 100*104 = 10400
    float* bufA = ws + 10400;          // 128*108 = 13824
    float* xs   = bufA + 13824;        // 256
    float* b2p  = xs + 256;            // 104  (cum 24584, even)
    ull* w3u    = (ull*)(b2p + 104);   // 52 ull = 104 floats (pairs of w3)
    float* dsum = b2p + 104 + 104;     // 128

    const int tid = threadIdx.x;
    const bool active = tid < 208;
    const int rg = tid / 13;
    const int og = tid % 13;
    const int row0 = rg * 8;
    const int jb = og * 8;
    const int gbase = blockIdx.x * 128;

    for (int i = tid; i < 256; i += 224) xs[i] = x[blockIdx.x * 256 + i];
    for (int i = tid; i < 10400; i += 224) {
        int k = i / 104, j = i % 104;
        ws[i] = (j < 100) ? w2[k * 100 + j] : 0.f;
    }
    if (tid < 104) b2p[tid] = (tid < 100) ? b2[tid] : 0.f;
    if (tid < 52) w3u[tid] = (tid < 50) ? ((const ull*)w3)[tid] : 0ULL;
    if (tid < 128) dsum[tid] = b3[0];
    __syncthreads();

    // L1: 2 -> 100, leaky
    for (int i = tid; i < 12800; i += 224) {
        int p = i / 100, j = i % 100;
        float v = fmaf(xs[p * 2], w1[j], fmaf(xs[p * 2 + 1], w1[100 + j], b1[j]));
        bufA[p * 108 + j] = (v >= 0.f) ? v : 0.01f * v;
    }
    __syncthreads();

    // L2: 100x100 GEMM
    ull acc[8][4];
#pragma unroll
    for (int r = 0; r < 8; r++)
#pragma unroll
        for (int q = 0; q < 4; q++) acc[r][q] = 0ULL;
    if (active) {
        for (int k = 0; k < 100; k += 4) {
            ulonglong2 wA0 = *(const ulonglong2*)(ws + (k + 0) * 104 + jb);
            ulonglong2 wA1 = *(const ulonglong2*)(ws + (k + 0) * 104 + jb + 4);
            ulonglong2 wB0 = *(const ulonglong2*)(ws + (k + 1) * 104 + jb);
            ulonglong2 wB1 = *(const ulonglong2*)(ws + (k + 1) * 104 + jb + 4);
            ulonglong2 wC0 = *(const ulonglong2*)(ws + (k + 2) * 104 + jb);
            ulonglong2 wC1 = *(const ulonglong2*)(ws + (k + 2) * 104 + jb + 4);
            ulonglong2 wD0 = *(const ulonglong2*)(ws + (k + 3) * 104 + jb);
            ulonglong2 wD1 = *(const ulonglong2*)(ws + (k + 3) * 104 + jb + 4);
#pragma unroll
            for (int r = 0; r < 8; r++) {
                float4 a = *(const float4*)(bufA + (row0 + r) * 108 + k);
                GS2(r, bc2(a.x), wA0, wA1)
                GS2(r, bc2(a.y), wB0, wB1)
                GS2(r, bc2(a.z), wC0, wC1)
                GS2(r, bc2(a.w), wD0, wD1)
            }
        }
        // leaky + fused L3 partial dot (lanes then horizontal add)
#pragma unroll
        for (int r = 0; r < 8; r++) {
            ull dp2 = 0ULL;
#pragma unroll
            for (int q = 0; q < 4; q++) {
                float h0, h1; upk2(acc[r][q], h0, h1);
                int j = jb + 2 * q;
                h0 += b2p[j]; h1 += b2p[j + 1];
                h0 = (h0 >= 0.f) ? h0 : 0.01f * h0;
                h1 = (h1 >= 0.f) ? h1 : 0.01f * h1;
                fma2(dp2, pk2(h0, h1), w3u[j >> 1]);
            }
            float s0, s1; upk2(dp2, s0, s1);
            atomicAdd(&dsum[row0 + r], s0 + s1);
        }
    }
    __syncthreads();

    if (tid < 128) {
        int p = tid, gp = gbase + p;
        float t = dsum[p];
        float x0 = xs[p * 2 + 0], x1 = xs[p * 2 + 1];
        out[gp * 2 + 0] = (expf(t + x0) + 1e-12f) * g_xdh[gp * 2 + 0];
        out[gp * 2 + 1] = (expf(t + x1) + 1e-12f) * g_xdh[gp * 2 + 1];
    }
}

// ============================== launch =====================================
extern "C" void kernel_launch(void* const* d_in, const int* in_sizes, int n_in,
                              void* d_out, int out_size) {
    const float* x     = (const float*)d_in[0];
    const float* t1w1  = (const float*)d_in[1];
    const float* t1b1  = (const float*)d_in[2];
    const float* t1w2  = (const float*)d_in[3];
    const float* t1b2  = (const float*)d_in[4];
    const float* t1w3  = (const float*)d_in[5];
    const float* t1b3  = (const float*)d_in[6];
    const float* t2w1  = (const float*)d_in[7];
    const float* t2b1  = (const float*)d_in[8];
    const float* t2w2  = (const float*)d_in[9];
    const float* t2b2  = (const float*)d_in[10];
    const float* t2w3  = (const float*)d_in[11];
    const float* t2b3  = (const float*)d_in[12];
    const float* vvw1  = (const float*)d_in[13];
    const float* vvb1  = (const float*)d_in[14];
    const float* vva1  = (const float*)d_in[15];
    const float* vvw2  = (const float*)d_in[16];
    const float* vvb2  = (const float*)d_in[17];
    const float* vva2  = (const float*)d_in[18];
    const float* vvw3  = (const float*)d_in[19];
    const float* vvb3  = (const float*)d_in[20];
    const float* vsw1  = (const float*)d_in[21];
    const float* vsb1  = (const float*)d_in[22];
    const float* vsw2  = (const float*)d_in[23];
    const float* vsb2  = (const float*)d_in[24];
    const float* vsw3  = (const float*)d_in[25];
    const float* vsb3  = (const float*)d_in[26];

    const int SM1 = (10400 + 2 * 20736 + 128 + 384 + 128 + 128 + 256 + 384 + 104 + 400) * 4;  // 215,136
    const int SM2 = (30400 + 19712 + 128 + 304 + 608 + 128) * 4;                              // 205,120
    const int SM3 = (10400 + 13824 + 256 + 104 + 104 + 128) * 4;                              //  99,264

    cudaFuncSetAttribute(k_taskmap, cudaFuncAttributeMaxDynamicSharedMemorySize, SM1);
    cudaFuncSetAttribute(k_vv, cudaFuncAttributeMaxDynamicSharedMemorySize, SM2);
    cudaFuncSetAttribute(k_vs, cudaFuncAttributeMaxDynamicSharedMemorySize, SM3);

    k_origin<<<1, 128>>>(t1w1, t1b1, t1w2, t1b2, t1w3, t1b3,
                         t2w1, t2b1, t2w2, t2b2, t2w3, t2b3);
    k_taskmap<<<NPTS / 64, 320, SM1>>>(x, t1w1, t1b1, t1w2, t1b2, t1w3, t1b3,
                                       t2w1, t2b1, t2w2, t2b2, t2w3, t2b3);
    k_vv<<<NPTS / 64, 320, SM2>>>(vvw1, vvb1, vva1, vvw2, vvb2, vva2, vvw3, vvb3);
    k_vs<<<NPTS / 128, 224, SM3>>>(x, vsw1, vsb1, vsw2, vsb2, vsw3, vsb3,
                                   (float*)d_out);
}

// round 8
// speedup vs baseline: 1.0860x; 1.0860x over previous
#include <cuda_runtime.h>
#include <cuda_bf16.h>
#include <math.h>
#include <stdint.h>

#define NPTS 131072
typedef unsigned long long ull;

__device__ float g_origin[2];
__device__ float g_y[NPTS * 2];
__device__ float g_jinv[NPTS * 4];
__device__ float g_xdh[NPTS * 2];
// W2^T (vv) as bf16 hi/lo, flat [5 K-chunks][304 n-rows x 72 k-stride]
__device__ __nv_bfloat16 g_BH[5][304 * 72];
__device__ __nv_bfloat16 g_BL[5][304 * 72];

__device__ __forceinline__ float eluf(float v) { return v > 0.f ? v : expm1f(v); }
__device__ __forceinline__ float softplusf(float p) {
    return fmaxf(p, 0.f) + log1pf(expf(-fabsf(p)));
}

// ---- packed f32x2 helpers ----
__device__ __forceinline__ ull pk2(float a, float b) {
    ull r; asm("mov.b64 %0,{%1,%2};" : "=l"(r) : "f"(a), "f"(b)); return r;
}
__device__ __forceinline__ ull bc2(float a) { return pk2(a, a); }
__device__ __forceinline__ void upk2(ull v, float& a, float& b) {
    asm("mov.b64 {%0,%1},%2;" : "=f"(a), "=f"(b) : "l"(v));
}
__device__ __forceinline__ void fma2(ull& d, ull a, ull b) {
    asm("fma.rn.f32x2 %0, %1, %2, %0;" : "+l"(d) : "l"(a), "l"(b));
}
#define GS2(r, AB, U0, U1)            \
    fma2(acc[r][0], AB, U0.x);        \
    fma2(acc[r][1], AB, U0.y);        \
    fma2(acc[r][2], AB, U1.x);        \
    fma2(acc[r][3], AB, U1.y);

__device__ __forceinline__ uint32_t smem_u32(const void* p) {
    uint32_t a;
    asm("{ .reg .u64 t; cvta.to.shared.u64 t, %1; cvt.u32.u64 %0, t; }" : "=r"(a) : "l"(p));
    return a;
}
// ---- HMMA helpers (base-target mma.sync / ldmatrix) ----
__device__ __forceinline__ void ldsm_x4(uint32_t& r0, uint32_t& r1, uint32_t& r2, uint32_t& r3,
                                        uint32_t addr) {
    asm volatile("ldmatrix.sync.aligned.m8n8.x4.shared.b16 {%0,%1,%2,%3}, [%4];"
                 : "=r"(r0), "=r"(r1), "=r"(r2), "=r"(r3) : "r"(addr));
}
__device__ __forceinline__ void ldsm_x2(uint32_t& r0, uint32_t& r1, uint32_t addr) {
    asm volatile("ldmatrix.sync.aligned.m8n8.x2.shared.b16 {%0,%1}, [%2];"
                 : "=r"(r0), "=r"(r1) : "r"(addr));
}
__device__ __forceinline__ void mma_bf16(float* c, const uint32_t* a, const uint32_t* b) {
    asm volatile(
        "mma.sync.aligned.m16n8k16.row.col.f32.bf16.bf16.f32 "
        "{%0,%1,%2,%3}, {%4,%5,%6,%7}, {%8,%9}, {%0,%1,%2,%3};"
        : "+f"(c[0]), "+f"(c[1]), "+f"(c[2]), "+f"(c[3])
        : "r"(a[0]), "r"(a[1]), "r"(a[2]), "r"(a[3]), "r"(b[0]), "r"(b[1]));
}

// ========================= K0: origin = taskmap(0) =========================
__global__ void k_origin(const float* __restrict__ w1, const float* __restrict__ b1,
                         const float* __restrict__ w2, const float* __restrict__ b2,
                         const float* __restrict__ w3, const float* __restrict__ b3,
                         const float* __restrict__ w4, const float* __restrict__ b4,
                         const float* __restrict__ w5, const float* __restrict__ b5,
                         const float* __restrict__ w6, const float* __restrict__ b6) {
    __shared__ float h[100], h2[100], y1s[2];
    int j = threadIdx.x;
    if (j < 100) h[j] = tanhf(b1[j]);
    __syncthreads();
    if (j < 100) {
        float a = b2[j];
        for (int k = 0; k < 100; k++) a = fmaf(h[k], w2[k * 100 + j], a);
        h2[j] = tanhf(a);
    }
    __syncthreads();
    if (j < 2) {
        float a = b3[j];
        for (int k = 0; k < 100; k++) a = fmaf(h2[k], w3[k * 2 + j], a);
        y1s[j] = a;
    }
    __syncthreads();
    if (j < 100) {
        float a = fmaf(y1s[0], w4[j], fmaf(y1s[1], w4[100 + j], b4[j]));
        h[j] = eluf(a);
    }
    __syncthreads();
    if (j < 100) {
        float a = b5[j];
        for (int k = 0; k < 100; k++) a = fmaf(h[k], w5[k * 100 + j], a);
        h2[j] = eluf(a);
    }
    __syncthreads();
    if (j < 2) {
        float a = b6[j];
        for (int k = 0; k < 100; k++) a = fmaf(h2[k], w6[k * 2 + j], a);
        float s = softplusf(a);
        g_origin[j] = (1.f + s) * y1s[j];
    }
}

// ====== K prep: W2 (vv) -> transposed bf16 hi/lo images [n][k] ======
__global__ void k_prep(const float* __restrict__ w2) {
    int i = blockIdx.x * blockDim.x + threadIdx.x;
    if (i >= 5 * 304 * 64) return;
    int kc = i / (304 * 64);
    int r = i % (304 * 64);
    int n = r / 64, kl = r % 64;
    int kg = kc * 64 + kl;
    float v = (kg < 300 && n < 300) ? w2[kg * 300 + n] : 0.f;
    __nv_bfloat16 hi = __float2bfloat16(v);
    __nv_bfloat16 lo = __float2bfloat16(v - __bfloat162float(hi));
    g_BH[kc][n * 72 + kl] = hi;
    g_BL[kc][n * 72 + kl] = lo;
}

// ========================= K1: taskmap + Jacobian ==========================
template <int ACT>
__device__ __forceinline__ void tm_mid(const float* __restrict__ W, const float* __restrict__ b,
                                       float* ws, float* bp, const float* inb, float* outb,
                                       int tid, bool active, int rg, int og) {
    for (int i = tid; i < 10400; i += 320) {
        int k = i / 104, j = i % 104;
        ws[i] = (j < 100) ? W[k * 100 + j] : 0.f;
    }
    if (tid < 104) bp[tid] = (tid < 100) ? b[tid] : 0.f;
    __syncthreads();
    const int row0 = rg * 8, jb = og * 8, comp = rg >> 3;
    ull acc[8][4];
#pragma unroll
    for (int r = 0; r < 8; r++)
#pragma unroll
        for (int q = 0; q < 4; q++) acc[r][q] = 0ULL;
    if (active) {
        for (int k = 0; k < 100; k += 4) {
            ulonglong2 wA0 = *(const ulonglong2*)(ws + (k + 0) * 104 + jb);
            ulonglong2 wA1 = *(const ulonglong2*)(ws + (k + 0) * 104 + jb + 4);
            ulonglong2 wB0 = *(const ulonglong2*)(ws + (k + 1) * 104 + jb);
            ulonglong2 wB1 = *(const ulonglong2*)(ws + (k + 1) * 104 + jb + 4);
            ulonglong2 wC0 = *(const ulonglong2*)(ws + (k + 2) * 104 + jb);
            ulonglong2 wC1 = *(const ulonglong2*)(ws + (k + 2) * 104 + jb + 4);
            ulonglong2 wD0 = *(const ulonglong2*)(ws + (k + 3) * 104 + jb);
            ulonglong2 wD1 = *(const ulonglong2*)(ws + (k + 3) * 104 + jb + 4);
#pragma unroll
            for (int r = 0; r < 8; r++) {
                float4 a = *(const float4*)(inb + (row0 + r) * 108 + k);
                GS2(r, bc2(a.x), wA0, wA1)
                GS2(r, bc2(a.y), wB0, wB1)
                GS2(r, bc2(a.z), wC0, wC1)
                GS2(r, bc2(a.w), wD0, wD1)
            }
        }
    }
    if (active && comp == 0) {
#pragma unroll
        for (int r = 0; r < 8; r++)
#pragma unroll
            for (int q = 0; q < 4; q++) {
                float v0, v1; upk2(acc[r][q], v0, v1);
                v0 += bp[jb + 2 * q]; v1 += bp[jb + 2 * q + 1];
                outb[(row0 + r) * 108 + jb + 2 * q]     = (ACT == 0) ? tanhf(v0) : eluf(v0);
                outb[(row0 + r) * 108 + jb + 2 * q + 1] = (ACT == 0) ? tanhf(v1) : eluf(v1);
            }
    }
    __syncthreads();
    if (active && comp != 0) {
        const int pbase = row0 - comp * 64;
#pragma unroll
        for (int r = 0; r < 8; r++)
#pragma unroll
            for (int q = 0; q < 4; q++) {
                float v0, v1; upk2(acc[r][q], v0, v1);
                float h0 = outb[(pbase + r) * 108 + jb + 2 * q];
                float h1 = outb[(pbase + r) * 108 + jb + 2 * q + 1];
                float d0 = (ACT == 0) ? (1.f - h0 * h0) : (h0 > 0.f ? 1.f : h0 + 1.f);
                float d1 = (ACT == 0) ? (1.f - h1 * h1) : (h1 > 0.f ? 1.f : h1 + 1.f);
                outb[(row0 + r) * 108 + jb + 2 * q]     = v0 * d0;
                outb[(row0 + r) * 108 + jb + 2 * q + 1] = v1 * d1;
            }
    }
    __syncthreads();
}

__global__ __launch_bounds__(320, 1) void k_taskmap(
    const float* __restrict__ x,
    const float* __restrict__ w1, const float* __restrict__ b1,
    const float* __restrict__ w2, const float* __restrict__ b2,
    const float* __restrict__ w3, const float* __restrict__ b3,
    const float* __restrict__ w4, const float* __restrict__ b4,
    const float* __restrict__ w5, const float* __restrict__ b5,
    const float* __restrict__ w6, const float* __restrict__ b6) {
    extern __shared__ float sm[];
    float* ws   = sm;
    float* bufA = ws + 10400;
    float* bufB = bufA + 20736;
    float* xs   = bufB + 20736;
    float* v2   = xs + 128;
    float* ss   = v2 + 384;
    float* sg   = ss + 128;
    float* Jsh  = sg + 128;
    float* accb = Jsh + 256;
    float* bp   = accb + 384;
    ull* w3u    = (ull*)(bp + 104);
    ull* w6u    = (ull*)(bp + 304);

    const int tid = threadIdx.x;
    const bool active = tid < 312;
    const int rg = tid / 13, og = tid % 13;
    const int gbase = blockIdx.x * 64;

    if (tid < 128) xs[tid] = x[blockIdx.x * 128 + tid];
    if (tid >= 128 && tid < 228) w3u[tid - 128] = ((const ull*)w3)[tid - 128];
    if (tid >= 228 && tid < 320) w6u[tid - 228] = ((const ull*)w6)[tid - 228];
    if (tid < 8) w6u[92 + tid] = ((const ull*)w6)[92 + tid];
    __syncthreads();

    for (int i = tid; i < 6400; i += 320) {
        int p = i / 100, j = i % 100;
        float h = tanhf(fmaf(xs[p * 2], w1[j], fmaf(xs[p * 2 + 1], w1[100 + j], b1[j])));
        bufA[p * 108 + j] = h;
    }
    __syncthreads();
    for (int i = tid; i < 12800; i += 320) {
        int c = i / 6400, rem = i % 6400, p = rem / 100, j = rem % 100;
        float h = bufA[p * 108 + j];
        bufA[(64 + c * 64 + p) * 108 + j] = w1[c * 100 + j] * (1.f - h * h);
    }
    __syncthreads();

    tm_mid<0>(w2, b2, ws, bp, bufA, bufB, tid, active, rg, og);

    if (tid < 192) {
        int r = tid;
        const float* row = bufB + r * 108;
        ull a2 = 0ULL, a2b = 0ULL;
        for (int k = 0; k < 100; k += 4) {
            fma2(a2,  bc2(row[k + 0]), w3u[k + 0]);
            fma2(a2b, bc2(row[k + 1]), w3u[k + 1]);
            fma2(a2,  bc2(row[k + 2]), w3u[k + 2]);
            fma2(a2b, bc2(row[k + 3]), w3u[k + 3]);
        }
        float A0, A1, B0, B1; upk2(a2, A0, A1); upk2(a2b, B0, B1);
        A0 += B0; A1 += B1;
        int cmp = r / 64, p = r % 64;
        if (cmp == 0) {
            v2[r * 2 + 0] = A0 + b3[0] + xs[p * 2 + 0];
            v2[r * 2 + 1] = A1 + b3[1] + xs[p * 2 + 1];
        } else {
            v2[r * 2 + 0] = A0 + ((cmp - 1) == 0 ? 1.f : 0.f);
            v2[r * 2 + 1] = A1 + ((cmp - 1) == 1 ? 1.f : 0.f);
        }
    }
    __syncthreads();

    for (int i = tid; i < 6400; i += 320) {
        int p = i / 100, j = i % 100;
        float a = fmaf(v2[p * 2], w4[j], fmaf(v2[p * 2 + 1], w4[100 + j], b4[j]));
        bufA[p * 108 + j] = eluf(a);
    }
    __syncthreads();
    for (int i = tid; i < 12800; i += 320) {
        int c = i / 6400, rem = i % 6400, p = rem / 100, j = rem % 100;
        int r = 64 + c * 64 + p;
        float raw = fmaf(v2[r * 2], w4[j], v2[r * 2 + 1] * w4[100 + j]);
        float h = bufA[p * 108 + j];
        bufA[r * 108 + j] = raw * (h > 0.f ? 1.f : h + 1.f);
    }
    __syncthreads();

    tm_mid<1>(w5, b5, ws, bp, bufA, bufB, tid, active, rg, og);

    if (tid < 192) {
        int r = tid;
        const float* row = bufB + r * 108;
        ull a2 = 0ULL, a2b = 0ULL;
        for (int k = 0; k < 100; k += 4) {
            fma2(a2,  bc2(row[k + 0]), w6u[k + 0]);
            fma2(a2b, bc2(row[k + 1]), w6u[k + 1]);
            fma2(a2,  bc2(row[k + 2]), w6u[k + 2]);
            fma2(a2b, bc2(row[k + 3]), w6u[k + 3]);
        }
        float A0, A1, B0, B1; upk2(a2, A0, A1); upk2(a2b, B0, B1);
        A0 += B0; A1 += B1;
        if (r < 64) {
            float pv0 = A0 + b6[0], pv1 = A1 + b6[1];
            float s0 = softplusf(pv0), s1 = softplusf(pv1);
            ss[r * 2 + 0] = s0; ss[r * 2 + 1] = s1;
            sg[r * 2 + 0] = 1.f / (1.f + expf(-pv0));
            sg[r * 2 + 1] = 1.f / (1.f + expf(-pv1));
            g_y[(gbase + r) * 2 + 0] = (1.f + s0) * v2[r * 2 + 0] - g_origin[0];
            g_y[(gbase + r) * 2 + 1] = (1.f + s1) * v2[r * 2 + 1] - g_origin[1];
        } else {
            accb[r * 2 + 0] = A0;
            accb[r * 2 + 1] = A1;
        }
    }
    __syncthreads();
    if (tid < 256) {
        int r = 64 + (tid >> 1), i = tid & 1;
        int c = r / 64 - 1, p = r % 64;
        float acc = accb[r * 2 + i];
        float s = ss[p * 2 + i];
        float ds = sg[p * 2 + i] * acc;
        Jsh[p * 4 + i * 2 + c] = fmaf(ds, v2[p * 2 + i], (1.f + s) * v2[r * 2 + i]);
    }
    __syncthreads();
    if (tid < 64) {
        int p = tid, gp = gbase + p;
        float a = Jsh[p * 4 + 0], b_ = Jsh[p * 4 + 1];
        float c = Jsh[p * 4 + 2], d = Jsh[p * 4 + 3];
        float det = a * d - b_ * c;
        float n2 = a * a + b_ * b_ + c * c + d * d;
        float ia, ib, ic, id;
        if (fabsf(det) > 1e-10f * n2) {
            float inv = 1.f / det;
            ia = d * inv; ib = -b_ * inv; ic = -c * inv; id = a * inv;
        } else {
            float inv = (n2 > 0.f) ? 1.f / n2 : 0.f;
            ia = a * inv; ib = c * inv; ic = b_ * inv; id = d * inv;
        }
        float4 o; o.x = ia; o.y = ib; o.z = ic; o.w = id;
        *reinterpret_cast<float4*>(g_jinv + gp * 4) = o;
    }
}

// ============ K2 (HMMA): vv net via bf16-split mma.sync ====================
// 512 thr/CTA, 128 pts. Warp (w&7) -> rows 16*(w&7); (w>>3) -> N-half of 152.
// K = 5 chunks of 64 (4 k-tiles of 16 each). D = AhiBhi + AhiBlo + AloBhi.
__global__ __launch_bounds__(512, 1) void k_vv_mma(
    const float* __restrict__ w1, const float* __restrict__ b1, const float* __restrict__ a1p,
    const float* __restrict__ b2, const float* __restrict__ a2p,
    const float* __restrict__ w3, const float* __restrict__ b3) {
    extern __shared__ char smem[];
    const int OF_AH = 0;        // 128*72 bf16 = 18432 B
    const int OF_AL = 18432;
    const int OF_BH = 36864;    // 304*72 bf16 = 43776 B
    const int OF_BL = 80640;
    const int OF_YS = 124416;   // 256 floats
    const int OF_B2 = 125440;   // 304 floats
    const int OF_W3 = 126656;   // 608 floats
    const int OF_DS = 129088;   // 256 floats
    uint32_t sbase = smem_u32(smem);
    float* ys  = (float*)(smem + OF_YS);
    float* b2p = (float*)(smem + OF_B2);
    float* w3p = (float*)(smem + OF_W3);
    float* dsum = (float*)(smem + OF_DS);

    const int tid = threadIdx.x;
    const int wid = tid >> 5, lane = tid & 31;
    const int wrow = (wid & 7) * 16;
    const int nh = wid >> 3;
    const int g = lane >> 2, tg = lane & 3;

    if (tid < 256) ys[tid] = g_y[blockIdx.x * 256 + tid];
    for (int i = tid; i < 304; i += 512) b2p[i] = (i < 300) ? b2[i] : 0.f;
    for (int i = tid; i < 608; i += 512) w3p[i] = (i < 600) ? w3[i] : 0.f;
    if (tid < 256) dsum[tid] = b3[tid & 1];
    const float al1 = a1p[0];

    // ldmatrix lane-address components
    const int at = lane >> 3, ar = lane & 7;
    const int arow = wrow + (at & 1) * 8 + ar;     // A row for x4
    const int acol = (at >> 1) * 8;                // A col block for x4
    const int bl = lane & 15;
    const int brow_off = bl & 7;                   // B row within n-tile
    const int bcol = (bl >> 3) * 8;                // B col block for x2

    float c[19][4];
#pragma unroll
    for (int nt = 0; nt < 19; nt++)
#pragma unroll
        for (int q = 0; q < 4; q++) c[nt][q] = 0.f;

    for (int kc = 0; kc < 5; kc++) {
        __syncthreads();   // protect smem from previous iteration's readers
        {   // stage B hi/lo (flat copy: 2736 uint4 each)
            uint4* dH = (uint4*)(smem + OF_BH);
            uint4* dL = (uint4*)(smem + OF_BL);
            const uint4* sH = (const uint4*)g_BH[kc];
            const uint4* sL = (const uint4*)g_BL[kc];
            for (int i = tid; i < 2736; i += 512) { dH[i] = sH[i]; dL[i] = sL[i]; }
        }
        // stage A: L1 (2->300, PReLU) cols kc*64..+63 as bf16 hi/lo
        for (int idx = tid; idx < 8192; idx += 512) {
            int p = idx >> 6, kl = idx & 63;
            int kg = kc * 64 + kl;
            float v = 0.f;
            if (kg < 300) {
                v = fmaf(ys[p * 2], w1[kg], fmaf(ys[p * 2 + 1], w1[300 + kg], b1[kg]));
                v = (v >= 0.f) ? v : al1 * v;
            }
            __nv_bfloat16 hi = __float2bfloat16(v);
            __nv_bfloat16 lo = __float2bfloat16(v - __bfloat162float(hi));
            ((__nv_bfloat16*)(smem + OF_AH))[p * 72 + kl] = hi;
            ((__nv_bfloat16*)(smem + OF_AL))[p * 72 + kl] = lo;
        }
        __syncthreads();

#pragma unroll
        for (int kt = 0; kt < 4; kt++) {
            uint32_t ah[4], al4[4];
            uint32_t aoff = (uint32_t)((arow * 72 + kt * 16 + acol) * 2);
            ldsm_x4(ah[0], ah[1], ah[2], ah[3], sbase + OF_AH + aoff);
            ldsm_x4(al4[0], al4[1], al4[2], al4[3], sbase + OF_AL + aoff);
#pragma unroll
            for (int nt = 0; nt < 19; nt++) {
                int n0 = nh * 152 + nt * 8;
                uint32_t boff = (uint32_t)(((n0 + brow_off) * 72 + kt * 16 + bcol) * 2);
                uint32_t bh[2], bl2[2];
                ldsm_x2(bh[0], bh[1], sbase + OF_BH + boff);
                ldsm_x2(bl2[0], bl2[1], sbase + OF_BL + boff);
                mma_bf16(c[nt], ah, bh);
                mma_bf16(c[nt], ah, bl2);
                mma_bf16(c[nt], al4, bh);
            }
        }
    }

    // ---- epilogue: PReLU + L3 partial dots in-register ----
    {
        const float al2 = a2p[0];
        float d0a = 0.f, d1a = 0.f, d0b = 0.f, d1b = 0.f;
#pragma unroll
        for (int nt = 0; nt < 19; nt++) {
            int n = nh * 152 + nt * 8 + tg * 2;
            float bb0 = b2p[n], bb1 = b2p[n + 1];
            float wa0 = w3p[2 * n + 0], wa1 = w3p[2 * n + 1];
            float wb0 = w3p[2 * n + 2], wb1 = w3p[2 * n + 3];
            float h;
            h = c[nt][0] + bb0; h = (h >= 0.f) ? h : al2 * h;
            d0a = fmaf(h, wa0, d0a); d1a = fmaf(h, wa1, d1a);
            h = c[nt][1] + bb1; h = (h >= 0.f) ? h : al2 * h;
            d0a = fmaf(h, wb0, d0a); d1a = fmaf(h, wb1, d1a);
            h = c[nt][2] + bb0; h = (h >= 0.f) ? h : al2 * h;
            d0b = fmaf(h, wa0, d0b); d1b = fmaf(h, wa1, d1b);
            h = c[nt][3] + bb1; h = (h >= 0.f) ? h : al2 * h;
            d0b = fmaf(h, wb0, d0b); d1b = fmaf(h, wb1, d1b);
        }
        d0a += __shfl_xor_sync(0xffffffffu, d0a, 1); d0a += __shfl_xor_sync(0xffffffffu, d0a, 2);
        d1a += __shfl_xor_sync(0xffffffffu, d1a, 1); d1a += __shfl_xor_sync(0xffffffffu, d1a, 2);
        d0b += __shfl_xor_sync(0xffffffffu, d0b, 1); d0b += __shfl_xor_sync(0xffffffffu, d0b, 2);
        d1b += __shfl_xor_sync(0xffffffffu, d1b, 1); d1b += __shfl_xor_sync(0xffffffffu, d1b, 2);
        if (tg == 0) {
            int r0 = wrow + g, r1 = wrow + g + 8;
            atomicAdd(&dsum[r0 * 2 + 0], d0a); atomicAdd(&dsum[r0 * 2 + 1], d1a);
            atomicAdd(&dsum[r1 * 2 + 0], d0b); atomicAdd(&dsum[r1 * 2 + 1], d1b);
        }
    }
    __syncthreads();

    if (tid < 128) {
        int p = tid, gp = blockIdx.x * 128 + p;
        float d0 = dsum[p * 2 + 0], d1 = dsum[p * 2 + 1];
        float y0 = ys[p * 2 + 0], y1 = ys[p * 2 + 1];
        float lsv = d0 * y0 + d1 * y1;
        float Vy = y0 * y0 + y1 * y1;
        float rl = fmaxf(fmaf(1e-4f, Vy, lsv), 0.f);
        float sc = rl / (Vy + 1e-12f);
        float yd0 = d0 - sc * y0, yd1 = d1 - sc * y1;
        float nrm = sqrtf(yd0 * yd0 + yd1 * yd1);
        float innv = 1.f / fmaxf(nrm, 1e-12f);
        float n0 = yd0 * innv, n1 = yd1 * innv;
        float4 Ji = *reinterpret_cast<const float4*>(g_jinv + gp * 4);
        g_xdh[gp * 2 + 0] = Ji.x * n0 + Ji.y * n1;
        g_xdh[gp * 2 + 1] = Ji.z * n0 + Ji.w * n1;
    }
}

// =================== K3: vel-scalar net + final scaling ====================
__global__ __launch_bounds__(224, 2) void k_vs(
    const float* __restrict__ x,
    const float* __restrict__ w1, const float* __restrict__ b1,
    const float* __restrict__ w2, const float* __restrict__ b2,
    const float* __restrict__ w3, const float* __restrict__ b3,
    float* __restrict__ out) {
    extern __shared__ float sm[];
    float* ws   = sm;
    float* bufA = ws + 10400;
    float* xs   = bufA + 13824;
    float* b2p  = xs + 256;
    ull* w3u    = (ull*)(b2p + 104);
    float* dsum = b2p + 104 + 104;

    const int tid = threadIdx.x;
    const bool active = tid < 208;
    const int rg = tid / 13, og = tid % 13;
    const int row0 = rg * 8, jb = og * 8;
    const int gbase = blockIdx.x * 128;

    for (int i = tid; i < 256; i += 224) xs[i] = x[blockIdx.x * 256 + i];
    for (int i = tid; i < 10400; i += 224) {
        int k = i / 104, j = i % 104;
        ws[i] = (j < 100) ? w2[k * 100 + j] : 0.f;
    }
    if (tid < 104) b2p[tid] = (tid < 100) ? b2[tid] : 0.f;
    if (tid < 52) w3u[tid] = (tid < 50) ? ((const ull*)w3)[tid] : 0ULL;
    if (tid < 128) dsum[tid] = b3[0];
    __syncthreads();

    for (int i = tid; i < 12800; i += 224) {
        int p = i / 100, j = i % 100;
        float v = fmaf(xs[p * 2], w1[j], fmaf(xs[p * 2 + 1], w1[100 + j], b1[j]));
        bufA[p * 108 + j] = (v >= 0.f) ? v : 0.01f * v;
    }
    __syncthreads();

    ull acc[8][4];
#pragma unroll
    for (int r = 0; r < 8; r++)
#pragma unroll
        for (int q = 0; q < 4; q++) acc[r][q] = 0ULL;
    if (active) {
        for (int k = 0; k < 100; k += 4) {
            ulonglong2 wA0 = *(const ulonglong2*)(ws + (k + 0) * 104 + jb);
            ulonglong2 wA1 = *(const ulonglong2*)(ws + (k + 0) * 104 + jb + 4);
            ulonglong2 wB0 = *(const ulonglong2*)(ws + (k + 1) * 104 + jb);
            ulonglong2 wB1 = *(const ulonglong2*)(ws + (k + 1) * 104 + jb + 4);
            ulonglong2 wC0 = *(const ulonglong2*)(ws + (k + 2) * 104 + jb);
            ulonglong2 wC1 = *(const ulonglong2*)(ws + (k + 2) * 104 + jb + 4);
            ulonglong2 wD0 = *(const ulonglong2*)(ws + (k + 3) * 104 + jb);
            ulonglong2 wD1 = *(const ulonglong2*)(ws + (k + 3) * 104 + jb + 4);
#pragma unroll
            for (int r = 0; r < 8; r++) {
                float4 a = *(const float4*)(bufA + (row0 + r) * 108 + k);
                GS2(r, bc2(a.x), wA0, wA1)
                GS2(r, bc2(a.y), wB0, wB1)
                GS2(r, bc2(a.z), wC0, wC1)
                GS2(r, bc2(a.w), wD0, wD1)
            }
        }
#pragma unroll
        for (int r = 0; r < 8; r++) {
            ull dp2 = 0ULL;
#pragma unroll
            for (int q = 0; q < 4; q++) {
                float h0, h1; upk2(acc[r][q], h0, h1);
                int j = jb + 2 * q;
                h0 += b2p[j]; h1 += b2p[j + 1];
                h0 = (h0 >= 0.f) ? h0 : 0.01f * h0;
                h1 = (h1 >= 0.f) ? h1 : 0.01f * h1;
                fma2(dp2, pk2(h0, h1), w3u[j >> 1]);
            }
            float s0, s1; upk2(dp2, s0, s1);
            atomicAdd(&dsum[row0 + r], s0 + s1);
        }
    }
    __syncthreads();

    if (tid < 128) {
        int p = tid, gp = gbase + p;
        float t = dsum[p];
        float x0 = xs[p * 2 + 0], x1 = xs[p * 2 + 1];
        out[gp * 2 + 0] = (expf(t + x0) + 1e-12f) * g_xdh[gp * 2 + 0];
        out[gp * 2 + 1] = (expf(t + x1) + 1e-12f) * g_xdh[gp * 2 + 1];
    }
}

// ============================== launch =====================================
extern "C" void kernel_launch(void* const* d_in, const int* in_sizes, int n_in,
                              void* d_out, int out_size) {
    const float* x     = (const float*)d_in[0];
    const float* t1w1  = (const float*)d_in[1];
    const float* t1b1  = (const float*)d_in[2];
    const float* t1w2  = (const float*)d_in[3];
    const float* t1b2  = (const float*)d_in[4];
    const float* t1w3  = (const float*)d_in[5];
    const float* t1b3  = (const float*)d_in[6];
    const float* t2w1  = (const float*)d_in[7];
    const float* t2b1  = (const float*)d_in[8];
    const float* t2w2  = (const float*)d_in[9];
    const float* t2b2  = (const float*)d_in[10];
    const float* t2w3  = (const float*)d_in[11];
    const float* t2b3  = (const float*)d_in[12];
    const float* vvw1  = (const float*)d_in[13];
    const float* vvb1  = (const float*)d_in[14];
    const float* vva1  = (const float*)d_in[15];
    const float* vvw2  = (const float*)d_in[16];
    const float* vvb2  = (const float*)d_in[17];
    const float* vva2  = (const float*)d_in[18];
    const float* vvw3  = (const float*)d_in[19];
    const float* vvb3  = (const float*)d_in[20];
    const float* vsw1  = (const float*)d_in[21];
    const float* vsb1  = (const float*)d_in[22];
    const float* vsw2  = (const float*)d_in[23];
    const float* vsb2  = (const float*)d_in[24];
    const float* vsw3  = (const float*)d_in[25];
    const float* vsb3  = (const float*)d_in[26];

    const int SM1 = (10400 + 2 * 20736 + 128 + 384 + 128 + 128 + 256 + 384 + 104 + 400) * 4;
    const int SM2 = 130112;
    const int SM3 = (10400 + 13824 + 256 + 104 + 104 + 128) * 4;

    cudaFuncSetAttribute(k_taskmap, cudaFuncAttributeMaxDynamicSharedMemorySize, SM1);
    cudaFuncSetAttribute(k_vv_mma, cudaFuncAttributeMaxDynamicSharedMemorySize, SM2);
    cudaFuncSetAttribute(k_vs, cudaFuncAttributeMaxDynamicSharedMemorySize, SM3);

    k_origin<<<1, 128>>>(t1w1, t1b1, t1w2, t1b2, t1w3, t1b3,
                         t2w1, t2b1, t2w2, t2b2, t2w3, t2b3);
    k_prep<<<380, 256>>>(vvw2);
    k_taskmap<<<NPTS / 64, 320, SM1>>>(x, t1w1, t1b1, t1w2, t1b2, t1w3, t1b3,
                                       t2w1, t2b1, t2w2, t2b2, t2w3, t2b3);
    k_vv_mma<<<NPTS / 128, 512, SM2>>>(vvw1, vvb1, vva1, vvb2, vva2, vvw3, vvb3);
    k_vs<<<NPTS / 128, 224, SM3>>>(x, vsw1, vsb1, vsw2, vsb2, vsw3, vsb3,
                                   (float*)d_out);
}

// round 9
// speedup vs baseline: 1.4991x; 1.3804x over previous
#include <cuda_runtime.h>
#include <cuda_bf16.h>
#include <math.h>
#include <stdint.h>

#define NPTS 131072
typedef unsigned long long ull;

__device__ float g_origin[2];
__device__ float g_y[NPTS * 2];
__device__ float g_jinv[NPTS * 4];
__device__ float g_xdh[NPTS * 2];
// W2^T (vv) bf16 hi/lo, [5 K-chunks][304 x 72]
__device__ __nv_bfloat16 g_BH[5][304 * 72];
__device__ __nv_bfloat16 g_BL[5][304 * 72];
// taskmap mid-layer weights W^T bf16 hi/lo, [2 layers][104 n x 120 k]
__device__ __nv_bfloat16 g_TH[2][104 * 120];
__device__ __nv_bfloat16 g_TL[2][104 * 120];

__device__ __forceinline__ float eluf(float v) { return v > 0.f ? v : expm1f(v); }
__device__ __forceinline__ float softplusf(float p) {
    return fmaxf(p, 0.f) + log1pf(expf(-fabsf(p)));
}
__device__ __forceinline__ void bf16split(float v, __nv_bfloat16& hi, __nv_bfloat16& lo) {
    hi = __float2bfloat16(v);
    lo = __float2bfloat16(v - __bfloat162float(hi));
}

// ---- packed f32x2 helpers ----
__device__ __forceinline__ ull pk2(float a, float b) {
    ull r; asm("mov.b64 %0,{%1,%2};" : "=l"(r) : "f"(a), "f"(b)); return r;
}
__device__ __forceinline__ ull bc2(float a) { return pk2(a, a); }
__device__ __forceinline__ void upk2(ull v, float& a, float& b) {
    asm("mov.b64 {%0,%1},%2;" : "=f"(a), "=f"(b) : "l"(v));
}
__device__ __forceinline__ void fma2(ull& d, ull a, ull b) {
    asm("fma.rn.f32x2 %0, %1, %2, %0;" : "+l"(d) : "l"(a), "l"(b));
}
#define GS2(r, AB, U0, U1)            \
    fma2(acc[r][0], AB, U0.x);        \
    fma2(acc[r][1], AB, U0.y);        \
    fma2(acc[r][2], AB, U1.x);        \
    fma2(acc[r][3], AB, U1.y);

__device__ __forceinline__ uint32_t smem_u32(const void* p) {
    uint32_t a;
    asm("{ .reg .u64 t; cvta.to.shared.u64 t, %1; cvt.u32.u64 %0, t; }" : "=r"(a) : "l"(p));
    return a;
}
// ---- HMMA helpers ----
__device__ __forceinline__ void ldsm_x4(uint32_t& r0, uint32_t& r1, uint32_t& r2, uint32_t& r3,
                                        uint32_t addr) {
    asm volatile("ldmatrix.sync.aligned.m8n8.x4.shared.b16 {%0,%1,%2,%3}, [%4];"
                 : "=r"(r0), "=r"(r1), "=r"(r2), "=r"(r3) : "r"(addr));
}
__device__ __forceinline__ void ldsm_x2(uint32_t& r0, uint32_t& r1, uint32_t addr) {
    asm volatile("ldmatrix.sync.aligned.m8n8.x2.shared.b16 {%0,%1}, [%2];"
                 : "=r"(r0), "=r"(r1) : "r"(addr));
}
__device__ __forceinline__ void mma_bf16(float* c, const uint32_t* a, const uint32_t* b) {
    asm volatile(
        "mma.sync.aligned.m16n8k16.row.col.f32.bf16.bf16.f32 "
        "{%0,%1,%2,%3}, {%4,%5,%6,%7}, {%8,%9}, {%0,%1,%2,%3};"
        : "+f"(c[0]), "+f"(c[1]), "+f"(c[2]), "+f"(c[3])
        : "r"(a[0]), "r"(a[1]), "r"(a[2]), "r"(a[3]), "r"(b[0]), "r"(b[1]));
}

// ========================= K0: origin = taskmap(0) =========================
__global__ void k_origin(const float* __restrict__ w1, const float* __restrict__ b1,
                         const float* __restrict__ w2, const float* __restrict__ b2,
                         const float* __restrict__ w3, const float* __restrict__ b3,
                         const float* __restrict__ w4, const float* __restrict__ b4,
                         const float* __restrict__ w5, const float* __restrict__ b5,
                         const float* __restrict__ w6, const float* __restrict__ b6) {
    __shared__ float h[100], h2[100], y1s[2];
    int j = threadIdx.x;
    if (j < 100) h[j] = tanhf(b1[j]);
    __syncthreads();
    if (j < 100) {
        float a = b2[j];
        for (int k = 0; k < 100; k++) a = fmaf(h[k], w2[k * 100 + j], a);
        h2[j] = tanhf(a);
    }
    __syncthreads();
    if (j < 2) {
        float a = b3[j];
        for (int k = 0; k < 100; k++) a = fmaf(h2[k], w3[k * 2 + j], a);
        y1s[j] = a;
    }
    __syncthreads();
    if (j < 100) {
        float a = fmaf(y1s[0], w4[j], fmaf(y1s[1], w4[100 + j], b4[j]));
        h[j] = eluf(a);
    }
    __syncthreads();
    if (j < 100) {
        float a = b5[j];
        for (int k = 0; k < 100; k++) a = fmaf(h[k], w5[k * 100 + j], a);
        h2[j] = eluf(a);
    }
    __syncthreads();
    if (j < 2) {
        float a = b6[j];
        for (int k = 0; k < 100; k++) a = fmaf(h2[k], w6[k * 2 + j], a);
        float s = softplusf(a);
        g_origin[j] = (1.f + s) * y1s[j];
    }
}

// ====== prep: W2 (vv) -> [n][k] bf16 hi/lo ======
__global__ void k_prep(const float* __restrict__ w2) {
    int i = blockIdx.x * blockDim.x + threadIdx.x;
    if (i >= 5 * 304 * 64) return;
    int kc = i / (304 * 64);
    int r = i % (304 * 64);
    int n = r / 64, kl = r % 64;
    int kg = kc * 64 + kl;
    float v = (kg < 300 && n < 300) ? w2[kg * 300 + n] : 0.f;
    __nv_bfloat16 hi, lo; bf16split(v, hi, lo);
    g_BH[kc][n * 72 + kl] = hi;
    g_BL[kc][n * 72 + kl] = lo;
}
// ====== prep2: taskmap mid weights -> [n][k] bf16 hi/lo (stride 120) ======
__global__ void k_prep2(const float* __restrict__ w2, const float* __restrict__ w5) {
    int i = blockIdx.x * blockDim.x + threadIdx.x;
    if (i >= 2 * 104 * 120) return;
    int l = i / (104 * 120);
    int r = i % (104 * 120);
    int n = r / 120, k = r % 120;
    const float* W = l ? w5 : w2;
    float v = (n < 100 && k < 100) ? W[k * 100 + n] : 0.f;
    __nv_bfloat16 hi, lo; bf16split(v, hi, lo);
    g_TH[l][n * 120 + k] = hi;
    g_TL[l][n * 120 + k] = lo;
}

// ========================= K1: taskmap + Jacobian (HMMA) ===================
// 64 pts/block, 192 rows (64 value + 128 tangent), 384 threads = 12 warps.
// Mid layers: M=192 (12 mt), N=104 (13 nt), K=112 (7 kt), bf16-split (3 MMA).
#define OF_AH 0
#define OF_AL 46080
#define OF_WH 92160
#define OF_WL 117120
#define OF_HB 142080
#define OF_XS 168704
#define OF_V2 169216
#define OF_SS 170752
#define OF_SG 171264
#define OF_JS 171776
#define OF_BP 172800
#define OF_W3U 173248
#define OF_W6U 174048
#define OF_ACC 174848
#define SM1_BYTES 176384

template <int ACT>  // 0 = tanh, 1 = elu
__device__ __forceinline__ void mma_layer(char* smem, uint32_t sbase, int layer,
                                          const float* __restrict__ bvec) {
    const int tid = threadIdx.x;
    const int wid = tid >> 5, lane = tid & 31;
    float* bp = (float*)(smem + OF_BP);
    float* hbuf = (float*)(smem + OF_HB);
    __nv_bfloat16* AHp = (__nv_bfloat16*)(smem + OF_AH);
    __nv_bfloat16* ALp = (__nv_bfloat16*)(smem + OF_AL);

    // stage W hi/lo (flat) + bias
    {
        uint4* dH = (uint4*)(smem + OF_WH);
        uint4* dL = (uint4*)(smem + OF_WL);
        const uint4* sH = (const uint4*)g_TH[layer];
        const uint4* sL = (const uint4*)g_TL[layer];
        for (int i = tid; i < 1560; i += 384) { dH[i] = sH[i]; dL[i] = sL[i]; }
        if (tid < 104) bp[tid] = (tid < 100) ? bvec[tid] : 0.f;
    }
    __syncthreads();

    const int mrow = wid * 16;
    const int at = lane >> 3, ar = lane & 7;
    const int arow = mrow + (at & 1) * 8 + ar;
    const int acol = (at >> 1) * 8;
    const int bl = lane & 15;
    const int brow_off = bl & 7;
    const int bcol = (bl >> 3) * 8;
    const int g = lane >> 2, tg = lane & 3;

    float c[13][4];
#pragma unroll
    for (int nt = 0; nt < 13; nt++)
#pragma unroll
        for (int q = 0; q < 4; q++) c[nt][q] = 0.f;

#pragma unroll
    for (int kt = 0; kt < 7; kt++) {
        uint32_t ah[4], al4[4];
        uint32_t aoff = (uint32_t)((arow * 120 + kt * 16 + acol) * 2);
        ldsm_x4(ah[0], ah[1], ah[2], ah[3], sbase + OF_AH + aoff);
        ldsm_x4(al4[0], al4[1], al4[2], al4[3], sbase + OF_AL + aoff);
#pragma unroll
        for (int nt = 0; nt < 13; nt++) {
            uint32_t boff = (uint32_t)(((nt * 8 + brow_off) * 120 + kt * 16 + bcol) * 2);
            uint32_t bh[2], bl2[2];
            ldsm_x2(bh[0], bh[1], sbase + OF_WH + boff);
            ldsm_x2(bl2[0], bl2[1], sbase + OF_WL + boff);
            mma_bf16(c[nt], ah, bh);
            mma_bf16(c[nt], ah, bl2);
            mma_bf16(c[nt], al4, bh);
        }
    }
    __syncthreads();  // all A/W reads done

    if (wid < 4) {  // value rows: activate, store h (f32) + bf16 hi/lo
        int r0 = mrow + g, r1 = mrow + g + 8;
#pragma unroll
        for (int nt = 0; nt < 13; nt++) {
#pragma unroll
            for (int q = 0; q < 4; q++) {
                int row = (q < 2) ? r0 : r1;
                int col = nt * 8 + tg * 2 + (q & 1);
                float h = c[nt][q] + bp[col];
                h = (ACT == 0) ? tanhf(h) : eluf(h);
                hbuf[row * 104 + col] = h;
                __nv_bfloat16 hi, lo; bf16split(h, hi, lo);
                AHp[row * 120 + col] = hi;
                ALp[row * 120 + col] = lo;
            }
        }
    }
    __syncthreads();
    if (wid >= 4) {  // tangent rows: scale by act'(h) of value row
        int r0 = mrow + g, r1 = mrow + g + 8;
#pragma unroll
        for (int nt = 0; nt < 13; nt++) {
#pragma unroll
            for (int q = 0; q < 4; q++) {
                int row = (q < 2) ? r0 : r1;
                int col = nt * 8 + tg * 2 + (q & 1);
                float h = hbuf[(row & 63) * 104 + col];
                float d = (ACT == 0) ? (1.f - h * h) : (h > 0.f ? 1.f : h + 1.f);
                float v = c[nt][q] * d;
                __nv_bfloat16 hi, lo; bf16split(v, hi, lo);
                AHp[row * 120 + col] = hi;
                ALp[row * 120 + col] = lo;
            }
        }
    }
    __syncthreads();
}

__global__ __launch_bounds__(384, 1) void k_taskmap(
    const float* __restrict__ x,
    const float* __restrict__ w1, const float* __restrict__ b1,
    const float* __restrict__ b2,
    const float* __restrict__ w3, const float* __restrict__ b3,
    const float* __restrict__ w4, const float* __restrict__ b4,
    const float* __restrict__ b5,
    const float* __restrict__ w6, const float* __restrict__ b6) {
    extern __shared__ char smem[];
    uint32_t sbase = smem_u32(smem);
    __nv_bfloat16* AHp = (__nv_bfloat16*)(smem + OF_AH);
    __nv_bfloat16* ALp = (__nv_bfloat16*)(smem + OF_AL);
    float* hbuf = (float*)(smem + OF_HB);
    float* xs   = (float*)(smem + OF_XS);
    float* v2   = (float*)(smem + OF_V2);
    float* ss   = (float*)(smem + OF_SS);
    float* sg   = (float*)(smem + OF_SG);
    float* Jsh  = (float*)(smem + OF_JS);
    ull* w3u    = (ull*)(smem + OF_W3U);
    ull* w6u    = (ull*)(smem + OF_W6U);
    float* accb = (float*)(smem + OF_ACC);

    const int tid = threadIdx.x;
    const int gbase = blockIdx.x * 64;

    if (tid < 128) xs[tid] = x[blockIdx.x * 128 + tid];
    if (tid >= 128 && tid < 228) w3u[tid - 128] = ((const ull*)w3)[tid - 128];
    if (tid >= 228 && tid < 328) w6u[tid - 228] = ((const ull*)w6)[tid - 228];
    // zero-fill A pads cols 100..119 (stay zero across layers)
    for (int i = tid; i < 3840; i += 384) {
        int row = i / 20, col = 100 + i % 20;
        AHp[row * 120 + col] = __float2bfloat16(0.f);
        ALp[row * 120 + col] = __float2bfloat16(0.f);
    }
    __syncthreads();

    // ---- tm1 L1 (2 -> 100, tanh): value ----
    for (int i = tid; i < 6400; i += 384) {
        int p = i / 100, j = i % 100;
        float h = tanhf(fmaf(xs[p * 2], w1[j], fmaf(xs[p * 2 + 1], w1[100 + j], b1[j])));
        hbuf[p * 104 + j] = h;
        __nv_bfloat16 hi, lo; bf16split(h, hi, lo);
        AHp[p * 120 + j] = hi; ALp[p * 120 + j] = lo;
    }
    __syncthreads();
    // tangent rows: w1 row c scaled by (1-h^2)
    for (int i = tid; i < 12800; i += 384) {
        int c = i / 6400, rem = i % 6400, p = rem / 100, j = rem % 100;
        float h = hbuf[p * 104 + j];
        float v = w1[c * 100 + j] * (1.f - h * h);
        int row = 64 + c * 64 + p;
        __nv_bfloat16 hi, lo; bf16split(v, hi, lo);
        AHp[row * 120 + j] = hi; ALp[row * 120 + j] = lo;
    }
    __syncthreads();

    // ---- tm1 L2 (100x100, tanh) via HMMA ----
    mma_layer<0>(smem, sbase, 0, b2);

    // ---- tm1 L3 (100 -> 2) + residual / identity ----
    if (tid < 192) {
        int r = tid;
        ull a2 = 0ULL, a2b = 0ULL;
        const __nv_bfloat162* rh = (const __nv_bfloat162*)(AHp + r * 120);
        const __nv_bfloat162* rl = (const __nv_bfloat162*)(ALp + r * 120);
#pragma unroll 5
        for (int k = 0; k < 50; k++) {
            float2 h2 = __bfloat1622float2(rh[k]);
            float2 l2 = __bfloat1622float2(rl[k]);
            fma2(a2,  bc2(h2.x + l2.x), w3u[2 * k + 0]);
            fma2(a2b, bc2(h2.y + l2.y), w3u[2 * k + 1]);
        }
        float A0, A1, B0, B1; upk2(a2, A0, A1); upk2(a2b, B0, B1);
        A0 += B0; A1 += B1;
        int cmp = r / 64, p = r % 64;
        if (cmp == 0) {
            v2[r * 2 + 0] = A0 + b3[0] + xs[p * 2 + 0];
            v2[r * 2 + 1] = A1 + b3[1] + xs[p * 2 + 1];
        } else {
            v2[r * 2 + 0] = A0 + ((cmp - 1) == 0 ? 1.f : 0.f);
            v2[r * 2 + 1] = A1 + ((cmp - 1) == 1 ? 1.f : 0.f);
        }
    }
    __syncthreads();

    // ---- tm2 L1 (2 -> 100, elu): value then tangent ----
    for (int i = tid; i < 6400; i += 384) {
        int p = i / 100, j = i % 100;
        float a = fmaf(v2[p * 2], w4[j], fmaf(v2[p * 2 + 1], w4[100 + j], b4[j]));
        float h = eluf(a);
        hbuf[p * 104 + j] = h;
        __nv_bfloat16 hi, lo; bf16split(h, hi, lo);
        AHp[p * 120 + j] = hi; ALp[p * 120 + j] = lo;
    }
    __syncthreads();
    for (int i = tid; i < 12800; i += 384) {
        int c = i / 6400, rem = i % 6400, p = rem / 100, j = rem % 100;
        int row = 64 + c * 64 + p;
        float raw = fmaf(v2[row * 2], w4[j], v2[row * 2 + 1] * w4[100 + j]);
        float h = hbuf[p * 104 + j];
        float v = raw * (h > 0.f ? 1.f : h + 1.f);
        __nv_bfloat16 hi, lo; bf16split(v, hi, lo);
        AHp[row * 120 + j] = hi; ALp[row * 120 + j] = lo;
    }
    __syncthreads();

    // ---- tm2 L2 (100x100, elu) via HMMA ----
    mma_layer<1>(smem, sbase, 1, b5);

    // ---- tm2 L3 (100 -> 2) + softplus gate + y + J + pinv ----
    if (tid < 192) {
        int r = tid;
        ull a2 = 0ULL, a2b = 0ULL;
        const __nv_bfloat162* rh = (const __nv_bfloat162*)(AHp + r * 120);
        const __nv_bfloat162* rl = (const __nv_bfloat162*)(ALp + r * 120);
#pragma unroll 5
        for (int k = 0; k < 50; k++) {
            float2 h2 = __bfloat1622float2(rh[k]);
            float2 l2 = __bfloat1622float2(rl[k]);
            fma2(a2,  bc2(h2.x + l2.x), w6u[2 * k + 0]);
            fma2(a2b, bc2(h2.y + l2.y), w6u[2 * k + 1]);
        }
        float A0, A1, B0, B1; upk2(a2, A0, A1); upk2(a2b, B0, B1);
        A0 += B0; A1 += B1;
        if (r < 64) {
            float pv0 = A0 + b6[0], pv1 = A1 + b6[1];
            float s0 = softplusf(pv0), s1 = softplusf(pv1);
            ss[r * 2 + 0] = s0; ss[r * 2 + 1] = s1;
            sg[r * 2 + 0] = 1.f / (1.f + expf(-pv0));
            sg[r * 2 + 1] = 1.f / (1.f + expf(-pv1));
            g_y[(gbase + r) * 2 + 0] = (1.f + s0) * v2[r * 2 + 0] - g_origin[0];
            g_y[(gbase + r) * 2 + 1] = (1.f + s1) * v2[r * 2 + 1] - g_origin[1];
        } else {
            accb[r * 2 + 0] = A0;
            accb[r * 2 + 1] = A1;
        }
    }
    __syncthreads();
    if (tid < 256) {
        int r = 64 + (tid >> 1), i = tid & 1;
        int c = r / 64 - 1, p = r % 64;
        float acc = accb[r * 2 + i];
        float s = ss[p * 2 + i];
        float ds = sg[p * 2 + i] * acc;
        Jsh[p * 4 + i * 2 + c] = fmaf(ds, v2[p * 2 + i], (1.f + s) * v2[r * 2 + i]);
    }
    __syncthreads();
    if (tid < 64) {
        int p = tid, gp = gbase + p;
        float a = Jsh[p * 4 + 0], b_ = Jsh[p * 4 + 1];
        float c = Jsh[p * 4 + 2], d = Jsh[p * 4 + 3];
        float det = a * d - b_ * c;
        float n2 = a * a + b_ * b_ + c * c + d * d;
        float ia, ib, ic, id;
        if (fabsf(det) > 1e-10f * n2) {
            float inv = 1.f / det;
            ia = d * inv; ib = -b_ * inv; ic = -c * inv; id = a * inv;
        } else {
            float inv = (n2 > 0.f) ? 1.f / n2 : 0.f;
            ia = a * inv; ib = c * inv; ic = b_ * inv; id = d * inv;
        }
        float4 o; o.x = ia; o.y = ib; o.z = ic; o.w = id;
        *reinterpret_cast<float4*>(g_jinv + gp * 4) = o;
    }
}

// ============ K2 (HMMA): vv net via bf16-split mma.sync ====================
__global__ __launch_bounds__(512, 1) void k_vv_mma(
    const float* __restrict__ w1, const float* __restrict__ b1, const float* __restrict__ a1p,
    const float* __restrict__ b2, const float* __restrict__ a2p,
    const float* __restrict__ w3, const float* __restrict__ b3) {
    extern __shared__ char smem[];
    const int OF_AH2 = 0;
    const int OF_AL2 = 18432;
    const int OF_BH2 = 36864;
    const int OF_BL2 = 80640;
    const int OF_YS2 = 124416;
    const int OF_B22 = 125440;
    const int OF_W32 = 126656;
    const int OF_DS2 = 129088;
    uint32_t sbase = smem_u32(smem);
    float* ys  = (float*)(smem + OF_YS2);
    float* b2p = (float*)(smem + OF_B22);
    float* w3p = (float*)(smem + OF_W32);
    float* dsum = (float*)(smem + OF_DS2);

    const int tid = threadIdx.x;
    const int wid = tid >> 5, lane = tid & 31;
    const int wrow = (wid & 7) * 16;
    const int nh = wid >> 3;
    const int g = lane >> 2, tg = lane & 3;

    if (tid < 256) ys[tid] = g_y[blockIdx.x * 256 + tid];
    for (int i = tid; i < 304; i += 512) b2p[i] = (i < 300) ? b2[i] : 0.f;
    for (int i = tid; i < 608; i += 512) w3p[i] = (i < 600) ? w3[i] : 0.f;
    if (tid < 256) dsum[tid] = b3[tid & 1];
    const float al1 = a1p[0];

    const int at = lane >> 3, ar = lane & 7;
    const int arow = wrow + (at & 1) * 8 + ar;
    const int acol = (at >> 1) * 8;
    const int bl = lane & 15;
    const int brow_off = bl & 7;
    const int bcol = (bl >> 3) * 8;

    float c[19][4];
#pragma unroll
    for (int nt = 0; nt < 19; nt++)
#pragma unroll
        for (int q = 0; q < 4; q++) c[nt][q] = 0.f;

    for (int kc = 0; kc < 5; kc++) {
        __syncthreads();
        {
            uint4* dH = (uint4*)(smem + OF_BH2);
            uint4* dL = (uint4*)(smem + OF_BL2);
            const uint4* sH = (const uint4*)g_BH[kc];
            const uint4* sL = (const uint4*)g_BL[kc];
            for (int i = tid; i < 2736; i += 512) { dH[i] = sH[i]; dL[i] = sL[i]; }
        }
        for (int idx = tid; idx < 8192; idx += 512) {
            int p = idx >> 6, kl = idx & 63;
            int kg = kc * 64 + kl;
            float v = 0.f;
            if (kg < 300) {
                v = fmaf(ys[p * 2], w1[kg], fmaf(ys[p * 2 + 1], w1[300 + kg], b1[kg]));
                v = (v >= 0.f) ? v : al1 * v;
            }
            __nv_bfloat16 hi, lo; bf16split(v, hi, lo);
            ((__nv_bfloat16*)(smem + OF_AH2))[p * 72 + kl] = hi;
            ((__nv_bfloat16*)(smem + OF_AL2))[p * 72 + kl] = lo;
        }
        __syncthreads();

#pragma unroll
        for (int kt = 0; kt < 4; kt++) {
            uint32_t ah[4], al4[4];
            uint32_t aoff = (uint32_t)((arow * 72 + kt * 16 + acol) * 2);
            ldsm_x4(ah[0], ah[1], ah[2], ah[3], sbase + OF_AH2 + aoff);
            ldsm_x4(al4[0], al4[1], al4[2], al4[3], sbase + OF_AL2 + aoff);
#pragma unroll
            for (int nt = 0; nt < 19; nt++) {
                int n0 = nh * 152 + nt * 8;
                uint32_t boff = (uint32_t)(((n0 + brow_off) * 72 + kt * 16 + bcol) * 2);
                uint32_t bh[2], bl2[2];
                ldsm_x2(bh[0], bh[1], sbase + OF_BH2 + boff);
                ldsm_x2(bl2[0], bl2[1], sbase + OF_BL2 + boff);
                mma_bf16(c[nt], ah, bh);
                mma_bf16(c[nt], ah, bl2);
                mma_bf16(c[nt], al4, bh);
            }
        }
    }

    {
        const float al2 = a2p[0];
        float d0a = 0.f, d1a = 0.f, d0b = 0.f, d1b = 0.f;
#pragma unroll
        for (int nt = 0; nt < 19; nt++) {
            int n = nh * 152 + nt * 8 + tg * 2;
            float bb0 = b2p[n], bb1 = b2p[n + 1];
            float wa0 = w3p[2 * n + 0], wa1 = w3p[2 * n + 1];
            float wb0 = w3p[2 * n + 2], wb1 = w3p[2 * n + 3];
            float h;
            h = c[nt][0] + bb0; h = (h >= 0.f) ? h : al2 * h;
            d0a = fmaf(h, wa0, d0a); d1a = fmaf(h, wa1, d1a);
            h = c[nt][1] + bb1; h = (h >= 0.f) ? h : al2 * h;
            d0a = fmaf(h, wb0, d0a); d1a = fmaf(h, wb1, d1a);
            h = c[nt][2] + bb0; h = (h >= 0.f) ? h : al2 * h;
            d0b = fmaf(h, wa0, d0b); d1b = fmaf(h, wa1, d1b);
            h = c[nt][3] + bb1; h = (h >= 0.f) ? h : al2 * h;
            d0b = fmaf(h, wb0, d0b); d1b = fmaf(h, wb1, d1b);
        }
        d0a += __shfl_xor_sync(0xffffffffu, d0a, 1); d0a += __shfl_xor_sync(0xffffffffu, d0a, 2);
        d1a += __shfl_xor_sync(0xffffffffu, d1a, 1); d1a += __shfl_xor_sync(0xffffffffu, d1a, 2);
        d0b += __shfl_xor_sync(0xffffffffu, d0b, 1); d0b += __shfl_xor_sync(0xffffffffu, d0b, 2);
        d1b += __shfl_xor_sync(0xffffffffu, d1b, 1); d1b += __shfl_xor_sync(0xffffffffu, d1b, 2);
        if (tg == 0) {
            int r0 = wrow + g, r1 = wrow + g + 8;
            atomicAdd(&dsum[r0 * 2 + 0], d0a); atomicAdd(&dsum[r0 * 2 + 1], d1a);
            atomicAdd(&dsum[r1 * 2 + 0], d0b); atomicAdd(&dsum[r1 * 2 + 1], d1b);
        }
    }
    __syncthreads();

    if (tid < 128) {
        int p = tid, gp = blockIdx.x * 128 + p;
        float d0 = dsum[p * 2 + 0], d1 = dsum[p * 2 + 1];
        float y0 = ys[p * 2 + 0], y1 = ys[p * 2 + 1];
        float lsv = d0 * y0 + d1 * y1;
        float Vy = y0 * y0 + y1 * y1;
        float rl = fmaxf(fmaf(1e-4f, Vy, lsv), 0.f);
        float sc = rl / (Vy + 1e-12f);
        float yd0 = d0 - sc * y0, yd1 = d1 - sc * y1;
        float nrm = sqrtf(yd0 * yd0 + yd1 * yd1);
        float innv = 1.f / fmaxf(nrm, 1e-12f);
        float n0 = yd0 * innv, n1 = yd1 * innv;
        float4 Ji = *reinterpret_cast<const float4*>(g_jinv + gp * 4);
        g_xdh[gp * 2 + 0] = Ji.x * n0 + Ji.y * n1;
        g_xdh[gp * 2 + 1] = Ji.z * n0 + Ji.w * n1;
    }
}

// =================== K3: vel-scalar net + final scaling ====================
__global__ __launch_bounds__(224, 2) void k_vs(
    const float* __restrict__ x,
    const float* __restrict__ w1, const float* __restrict__ b1,
    const float* __restrict__ w2, const float* __restrict__ b2,
    const float* __restrict__ w3, const float* __restrict__ b3,
    float* __restrict__ out) {
    extern __shared__ float sm[];
    float* ws   = sm;
    float* bufA = ws + 10400;
    float* xs   = bufA + 13824;
    float* b2p  = xs + 256;
    ull* w3u    = (ull*)(b2p + 104);
    float* dsum = b2p + 104 + 104;

    const int tid = threadIdx.x;
    const bool active = tid < 208;
    const int rg = tid / 13, og = tid % 13;
    const int row0 = rg * 8, jb = og * 8;
    const int gbase = blockIdx.x * 128;

    for (int i = tid; i < 256; i += 224) xs[i] = x[blockIdx.x * 256 + i];
    for (int i = tid; i < 10400; i += 224) {
        int k = i / 104, j = i % 104;
        ws[i] = (j < 100) ? w2[k * 100 + j] : 0.f;
    }
    if (tid < 104) b2p[tid] = (tid < 100) ? b2[tid] : 0.f;
    if (tid < 52) w3u[tid] = (tid < 50) ? ((const ull*)w3)[tid] : 0ULL;
    if (tid < 128) dsum[tid] = b3[0];
    __syncthreads();

    for (int i = tid; i < 12800; i += 224) {
        int p = i / 100, j = i % 100;
        float v = fmaf(xs[p * 2], w1[j], fmaf(xs[p * 2 + 1], w1[100 + j], b1[j]));
        bufA[p * 108 + j] = (v >= 0.f) ? v : 0.01f * v;
    }
    __syncthreads();

    ull acc[8][4];
#pragma unroll
    for (int r = 0; r < 8; r++)
#pragma unroll
        for (int q = 0; q < 4; q++) acc[r][q] = 0ULL;
    if (active) {
        for (int k = 0; k < 100; k += 4) {
            ulonglong2 wA0 = *(const ulonglong2*)(ws + (k + 0) * 104 + jb);
            ulonglong2 wA1 = *(const ulonglong2*)(ws + (k + 0) * 104 + jb + 4);
            ulonglong2 wB0 = *(const ulonglong2*)(ws + (k + 1) * 104 + jb);
            ulonglong2 wB1 = *(const ulonglong2*)(ws + (k + 1) * 104 + jb + 4);
            ulonglong2 wC0 = *(const ulonglong2*)(ws + (k + 2) * 104 + jb);
            ulonglong2 wC1 = *(const ulonglong2*)(ws + (k + 2) * 104 + jb + 4);
            ulonglong2 wD0 = *(const ulonglong2*)(ws + (k + 3) * 104 + jb);
            ulonglong2 wD1 = *(const ulonglong2*)(ws + (k + 3) * 104 + jb + 4);
#pragma unroll
            for (int r = 0; r < 8; r++) {
                float4 a = *(const float4*)(bufA + (row0 + r) * 108 + k);
                GS2(r, bc2(a.x), wA0, wA1)
                GS2(r, bc2(a.y), wB0, wB1)
                GS2(r, bc2(a.z), wC0, wC1)
                GS2(r, bc2(a.w), wD0, wD1)
            }
        }
#pragma unroll
        for (int r = 0; r < 8; r++) {
            ull dp2 = 0ULL;
#pragma unroll
            for (int q = 0; q < 4; q++) {
                float h0, h1; upk2(acc[r][q], h0, h1);
                int j = jb + 2 * q;
                h0 += b2p[j]; h1 += b2p[j + 1];
                h0 = (h0 >= 0.f) ? h0 : 0.01f * h0;
                h1 = (h1 >= 0.f) ? h1 : 0.01f * h1;
                fma2(dp2, pk2(h0, h1), w3u[j >> 1]);
            }
            float s0, s1; upk2(dp2, s0, s1);
            atomicAdd(&dsum[row0 + r], s0 + s1);
        }
    }
    __syncthreads();

    if (tid < 128) {
        int p = tid, gp = gbase + p;
        float t = dsum[p];
        float x0 = xs[p * 2 + 0], x1 = xs[p * 2 + 1];
        out[gp * 2 + 0] = (expf(t + x0) + 1e-12f) * g_xdh[gp * 2 + 0];
        out[gp * 2 + 1] = (expf(t + x1) + 1e-12f) * g_xdh[gp * 2 + 1];
    }
}

// ============================== launch =====================================
extern "C" void kernel_launch(void* const* d_in, const int* in_sizes, int n_in,
                              void* d_out, int out_size) {
    const float* x     = (const float*)d_in[0];
    const float* t1w1  = (const float*)d_in[1];
    const float* t1b1  = (const float*)d_in[2];
    const float* t1w2  = (const float*)d_in[3];
    const float* t1b2  = (const float*)d_in[4];
    const float* t1w3  = (const float*)d_in[5];
    const float* t1b3  = (const float*)d_in[6];
    const float* t2w1  = (const float*)d_in[7];
    const float* t2b1  = (const float*)d_in[8];
    const float* t2w2  = (const float*)d_in[9];
    const float* t2b2  = (const float*)d_in[10];
    const float* t2w3  = (const float*)d_in[11];
    const float* t2b3  = (const float*)d_in[12];
    const float* vvw1  = (const float*)d_in[13];
    const float* vvb1  = (const float*)d_in[14];
    const float* vva1  = (const float*)d_in[15];
    const float* vvw2  = (const float*)d_in[16];
    const float* vvb2  = (const float*)d_in[17];
    const float* vva2  = (const float*)d_in[18];
    const float* vvw3  = (const float*)d_in[19];
    const float* vvb3  = (const float*)d_in[20];
    const float* vsw1  = (const float*)d_in[21];
    const float* vsb1  = (const float*)d_in[22];
    const float* vsw2  = (const float*)d_in[23];
    const float* vsb2  = (const float*)d_in[24];
    const float* vsw3  = (const float*)d_in[25];
    const float* vsb3  = (const float*)d_in[26];

    const int SM2 = 130112;
    const int SM3 = (10400 + 13824 + 256 + 104 + 104 + 128) * 4;

    cudaFuncSetAttribute(k_taskmap, cudaFuncAttributeMaxDynamicSharedMemorySize, SM1_BYTES);
    cudaFuncSetAttribute(k_vv_mma, cudaFuncAttributeMaxDynamicSharedMemorySize, SM2);
    cudaFuncSetAttribute(k_vs, cudaFuncAttributeMaxDynamicSharedMemorySize, SM3);

    k_origin<<<1, 128>>>(t1w1, t1b1, t1w2, t1b2, t1w3, t1b3,
                         t2w1, t2b1, t2w2, t2b2, t2w3, t2b3);
    k_prep<<<380, 256>>>(vvw2);
    k_prep2<<<98, 256>>>(t1w2, t2w2);
    k_taskmap<<<NPTS / 64, 384, SM1_BYTES>>>(x, t1w1, t1b1, t1b2, t1w3, t1b3,
                                             t2w1, t2b1, t2b2, t2w3, t2b3);
    k_vv_mma<<<NPTS / 128, 512, SM2>>>(vvw1, vvb1, vva1, vvb2, vva2, vvw3, vvb3);
    k_vs<<<NPTS / 128, 224, SM3>>>(x, vsw1, vsb1, vsw2, vsb2, vsw3, vsb3,
                                   (float*)d_out);
}

// round 10
// speedup vs baseline: 2.1590x; 1.4401x over previous
#include <cuda_runtime.h>
#include <cuda_bf16.h>
#include <math.h>
#include <stdint.h>

#define NPTS 131072
typedef unsigned long long ull;

__device__ float g_origin[2];
__device__ float g_y[NPTS * 2];
__device__ float g_jinv[NPTS * 4];
__device__ float g_xdh[NPTS * 2];
// W2^T (vv) bf16 hi/lo, [5 K-chunks][304 x 72]
__device__ __nv_bfloat16 g_BH[5][304 * 72];
__device__ __nv_bfloat16 g_BL[5][304 * 72];
// taskmap weights, bf16 hi/lo, transposed [n][k]:
__device__ __nv_bfloat16 g_TH[2 * 104 * 120];   // mid layers (stride 120)
__device__ __nv_bfloat16 g_TL[2 * 104 * 120];
__device__ __nv_bfloat16 g_T1H[2 * 104 * 40];   // L1 layers (stride 40, k<2)
__device__ __nv_bfloat16 g_T1L[2 * 104 * 40];
__device__ __nv_bfloat16 g_T3H[2 * 8 * 120];    // L3 layers (8 n-rows, stride 120)
__device__ __nv_bfloat16 g_T3L[2 * 8 * 120];

__device__ __forceinline__ float eluf(float v) { return v > 0.f ? v : expm1f(v); }
__device__ __forceinline__ float softplusf(float p) {
    return fmaxf(p, 0.f) + log1pf(expf(-fabsf(p)));
}
__device__ __forceinline__ void bf16split(float v, __nv_bfloat16& hi, __nv_bfloat16& lo) {
    hi = __float2bfloat16(v);
    lo = __float2bfloat16(v - __bfloat162float(hi));
}

// ---- packed f32x2 helpers ----
__device__ __forceinline__ ull pk2(float a, float b) {
    ull r; asm("mov.b64 %0,{%1,%2};" : "=l"(r) : "f"(a), "f"(b)); return r;
}
__device__ __forceinline__ ull bc2(float a) { return pk2(a, a); }
__device__ __forceinline__ void upk2(ull v, float& a, float& b) {
    asm("mov.b64 {%0,%1},%2;" : "=f"(a), "=f"(b) : "l"(v));
}
__device__ __forceinline__ void fma2(ull& d, ull a, ull b) {
    asm("fma.rn.f32x2 %0, %1, %2, %0;" : "+l"(d) : "l"(a), "l"(b));
}
#define GS2(r, AB, U0, U1)            \
    fma2(acc[r][0], AB, U0.x);        \
    fma2(acc[r][1], AB, U0.y);        \
    fma2(acc[r][2], AB, U1.x);        \
    fma2(acc[r][3], AB, U1.y);

__device__ __forceinline__ uint32_t smem_u32(const void* p) {
    uint32_t a;
    asm("{ .reg .u64 t; cvta.to.shared.u64 t, %1; cvt.u32.u64 %0, t; }" : "=r"(a) : "l"(p));
    return a;
}
// ---- HMMA helpers ----
__device__ __forceinline__ void ldsm_x4(uint32_t& r0, uint32_t& r1, uint32_t& r2, uint32_t& r3,
                                        uint32_t addr) {
    asm volatile("ldmatrix.sync.aligned.m8n8.x4.shared.b16 {%0,%1,%2,%3}, [%4];"
                 : "=r"(r0), "=r"(r1), "=r"(r2), "=r"(r3) : "r"(addr));
}
__device__ __forceinline__ void ldsm_x2(uint32_t& r0, uint32_t& r1, uint32_t addr) {
    asm volatile("ldmatrix.sync.aligned.m8n8.x2.shared.b16 {%0,%1}, [%2];"
                 : "=r"(r0), "=r"(r1) : "r"(addr));
}
__device__ __forceinline__ void mma_bf16(float* c, const uint32_t* a, const uint32_t* b) {
    asm volatile(
        "mma.sync.aligned.m16n8k16.row.col.f32.bf16.bf16.f32 "
        "{%0,%1,%2,%3}, {%4,%5,%6,%7}, {%8,%9}, {%0,%1,%2,%3};"
        : "+f"(c[0]), "+f"(c[1]), "+f"(c[2]), "+f"(c[3])
        : "r"(a[0]), "r"(a[1]), "r"(a[2]), "r"(a[3]), "r"(b[0]), "r"(b[1]));
}

// ========================= K0: origin = taskmap(0) =========================
__global__ void k_origin(const float* __restrict__ w1, const float* __restrict__ b1,
                         const float* __restrict__ w2, const float* __restrict__ b2,
                         const float* __restrict__ w3, const float* __restrict__ b3,
                         const float* __restrict__ w4, const float* __restrict__ b4,
                         const float* __restrict__ w5, const float* __restrict__ b5,
                         const float* __restrict__ w6, const float* __restrict__ b6) {
    __shared__ float h[100], h2[100], y1s[2];
    int j = threadIdx.x;
    if (j < 100) h[j] = tanhf(b1[j]);
    __syncthreads();
    if (j < 100) {
        float a = b2[j];
        for (int k = 0; k < 100; k++) a = fmaf(h[k], w2[k * 100 + j], a);
        h2[j] = tanhf(a);
    }
    __syncthreads();
    if (j < 2) {
        float a = b3[j];
        for (int k = 0; k < 100; k++) a = fmaf(h2[k], w3[k * 2 + j], a);
        y1s[j] = a;
    }
    __syncthreads();
    if (j < 100) {
        float a = fmaf(y1s[0], w4[j], fmaf(y1s[1], w4[100 + j], b4[j]));
        h[j] = eluf(a);
    }
    __syncthreads();
    if (j < 100) {
        float a = b5[j];
        for (int k = 0; k < 100; k++) a = fmaf(h[k], w5[k * 100 + j], a);
        h2[j] = eluf(a);
    }
    __syncthreads();
    if (j < 2) {
        float a = b6[j];
        for (int k = 0; k < 100; k++) a = fmaf(h2[k], w6[k * 2 + j], a);
        float s = softplusf(a);
        g_origin[j] = (1.f + s) * y1s[j];
    }
}

// ====== prep: W2 (vv) -> [n][k] bf16 hi/lo ======
__global__ void k_prep(const float* __restrict__ w2) {
    int i = blockIdx.x * blockDim.x + threadIdx.x;
    if (i >= 5 * 304 * 64) return;
    int kc = i / (304 * 64);
    int r = i % (304 * 64);
    int n = r / 64, kl = r % 64;
    int kg = kc * 64 + kl;
    float v = (kg < 300 && n < 300) ? w2[kg * 300 + n] : 0.f;
    __nv_bfloat16 hi, lo; bf16split(v, hi, lo);
    g_BH[kc][n * 72 + kl] = hi;
    g_BL[kc][n * 72 + kl] = lo;
}
// ====== prep2: taskmap L1/L2/L3 weights -> transposed bf16 hi/lo ======
__global__ void k_prep2(const float* __restrict__ w2, const float* __restrict__ w5,
                        const float* __restrict__ w1, const float* __restrict__ w4,
                        const float* __restrict__ w3, const float* __restrict__ w6) {
    int i = blockIdx.x * blockDim.x + threadIdx.x;
    if (i < 24960) {                        // mid: 2 x 104 x 120
        int l = i / 12480, r = i % 12480, n = r / 120, k = r % 120;
        const float* W = l ? w5 : w2;
        float v = (n < 100 && k < 100) ? W[k * 100 + n] : 0.f;
        __nv_bfloat16 hi, lo; bf16split(v, hi, lo);
        g_TH[l * 12480 + n * 120 + k] = hi;
        g_TL[l * 12480 + n * 120 + k] = lo;
    } else if (i < 24960 + 8320) {          // L1: 2 x 104 x 40
        int j = i - 24960;
        int l = j / 4160, r = j % 4160, n = r / 40, k = r % 40;
        const float* W = l ? w4 : w1;
        float v = (n < 100 && k < 2) ? W[k * 100 + n] : 0.f;
        __nv_bfloat16 hi, lo; bf16split(v, hi, lo);
        g_T1H[l * 4160 + n * 40 + k] = hi;
        g_T1L[l * 4160 + n * 40 + k] = lo;
    } else if (i < 24960 + 8320 + 1920) {   // L3: 2 x 8 x 120
        int j = i - 33280;
        int l = j / 960, r = j % 960, n = r / 120, k = r % 120;
        const float* W = l ? w6 : w3;
        float v = (n < 2 && k < 100) ? W[k * 2 + n] : 0.f;
        __nv_bfloat16 hi, lo; bf16split(v, hi, lo);
        g_T3H[l * 960 + n * 120 + k] = hi;
        g_T3L[l * 960 + n * 120 + k] = lo;
    }
}

// ========================= K1: taskmap + Jacobian (all-HMMA) ===============
// 64 pts/block, 192 rows (64 value + 128 tangent), 384 threads = 12 warps.
#define OF_AH 0
#define OF_AL 46080
#define OF_WH 92160
#define OF_WL 117120
#define OF_L1H 142080
#define OF_L1L 158720
#define OF_L3H 175360
#define OF_L3L 179200
#define OF_HB 183040
#define OF_XS 209664
#define OF_V2 210176
#define OF_SS 211712
#define OF_SG 212224
#define OF_JS 212736
#define OF_BP 213760
#define OF_ACC 214208
#define SM1_BYTES 215744

// Dense layer via HMMA: M=192, N=104 (13 nt), K = 16*NKT. bf16-split (3 MMA).
// Epilogue: value warps (0-3) activate + store h (bf16 hi/lo) + act'(h) in hbuf;
// tangent warps (4-11) scale raw fragments by act'(h) and store bf16 hi/lo.
template <int ACT, int NKT, int BSTRIDE>
__device__ __forceinline__ void mma_dense(char* smem, uint32_t sbase,
                                          uint32_t bh_off, uint32_t bl_off,
                                          const float* __restrict__ bvec,
                                          int stage_layer) {
    const int tid = threadIdx.x;
    const int wid = tid >> 5, lane = tid & 31;
    float* bp = (float*)(smem + OF_BP);
    float* hbuf = (float*)(smem + OF_HB);
    __nv_bfloat16* AHp = (__nv_bfloat16*)(smem + OF_AH);
    __nv_bfloat16* ALp = (__nv_bfloat16*)(smem + OF_AL);

    if (stage_layer >= 0) {
        uint4* dH = (uint4*)(smem + OF_WH);
        uint4* dL = (uint4*)(smem + OF_WL);
        const uint4* sH = (const uint4*)(g_TH + stage_layer * 12480);
        const uint4* sL = (const uint4*)(g_TL + stage_layer * 12480);
        for (int i = tid; i < 1560; i += 384) { dH[i] = sH[i]; dL[i] = sL[i]; }
    }
    if (tid < 104) bp[tid] = (tid < 100) ? bvec[tid] : 0.f;
    __syncthreads();

    const int mrow = wid * 16;
    const int at = lane >> 3, ar = lane & 7;
    const int arow = mrow + (at & 1) * 8 + ar;
    const int acol = (at >> 1) * 8;
    const int blx = lane & 15;
    const int brow = blx & 7;
    const int bcol = (blx >> 3) * 8;
    const int g = lane >> 2, tg = lane & 3;

    float c[13][4];
#pragma unroll
    for (int nt = 0; nt < 13; nt++)
#pragma unroll
        for (int q = 0; q < 4; q++) c[nt][q] = 0.f;

#pragma unroll
    for (int kt = 0; kt < NKT; kt++) {
        uint32_t ah[4], al4[4];
        uint32_t aoff = (uint32_t)((arow * 120 + kt * 16 + acol) * 2);
        ldsm_x4(ah[0], ah[1], ah[2], ah[3], sbase + OF_AH + aoff);
        ldsm_x4(al4[0], al4[1], al4[2], al4[3], sbase + OF_AL + aoff);
#pragma unroll
        for (int nt = 0; nt < 13; nt++) {
            uint32_t boff = (uint32_t)(((nt * 8 + brow) * BSTRIDE + kt * 16 + bcol) * 2);
            uint32_t bh[2], bl2[2];
            ldsm_x2(bh[0], bh[1], sbase + bh_off + boff);
            ldsm_x2(bl2[0], bl2[1], sbase + bl_off + boff);
            mma_bf16(c[nt], ah, bh);
            mma_bf16(c[nt], ah, bl2);
            mma_bf16(c[nt], al4, bh);
        }
    }
    __syncthreads();  // all A/B reads done before A rewrite

    if (wid < 4) {
        int r0 = mrow + g, r1 = mrow + g + 8;
#pragma unroll
        for (int nt = 0; nt < 13; nt++) {
#pragma unroll
            for (int q = 0; q < 4; q++) {
                int row = (q < 2) ? r0 : r1;
                int col = nt * 8 + tg * 2 + (q & 1);
                float h = c[nt][q] + bp[col];
                h = (ACT == 0) ? tanhf(h) : eluf(h);
                float d = (ACT == 0) ? (1.f - h * h) : (h > 0.f ? 1.f : h + 1.f);
                hbuf[row * 104 + col] = d;
                __nv_bfloat16 hi, lo; bf16split(h, hi, lo);
                AHp[row * 120 + col] = hi;
                ALp[row * 120 + col] = lo;
            }
        }
    }
    __syncthreads();
    if (wid >= 4) {
        int r0 = mrow + g, r1 = mrow + g + 8;
#pragma unroll
        for (int nt = 0; nt < 13; nt++) {
#pragma unroll
            for (int q = 0; q < 4; q++) {
                int row = (q < 2) ? r0 : r1;
                int col = nt * 8 + tg * 2 + (q & 1);
                float v = c[nt][q] * hbuf[(row & 63) * 104 + col];
                __nv_bfloat16 hi, lo; bf16split(v, hi, lo);
                AHp[row * 120 + col] = hi;
                ALp[row * 120 + col] = lo;
            }
        }
    }
    __syncthreads();
}

// L3 tail fragments: per warp, N-tile 0 only (cols 0..7), K=112.
__device__ __forceinline__ void mma_tail_frag(uint32_t sbase, uint32_t bh_off,
                                              uint32_t bl_off, float* c3) {
    const int tid = threadIdx.x;
    const int wid = tid >> 5, lane = tid & 31;
    const int mrow = wid * 16;
    const int at = lane >> 3, ar = lane & 7;
    const int arow = mrow + (at & 1) * 8 + ar;
    const int acol = (at >> 1) * 8;
    const int blx = lane & 15;
    const int brow = blx & 7;
    const int bcol = (blx >> 3) * 8;
    c3[0] = c3[1] = c3[2] = c3[3] = 0.f;
#pragma unroll
    for (int kt = 0; kt < 7; kt++) {
        uint32_t ah[4], al4[4];
        uint32_t aoff = (uint32_t)((arow * 120 + kt * 16 + acol) * 2);
        ldsm_x4(ah[0], ah[1], ah[2], ah[3], sbase + OF_AH + aoff);
        ldsm_x4(al4[0], al4[1], al4[2], al4[3], sbase + OF_AL + aoff);
        uint32_t boff = (uint32_t)((brow * 120 + kt * 16 + bcol) * 2);
        uint32_t bh[2], bl2[2];
        ldsm_x2(bh[0], bh[1], sbase + bh_off + boff);
        ldsm_x2(bl2[0], bl2[1], sbase + bl_off + boff);
        mma_bf16(c3, ah, bh);
        mma_bf16(c3, ah, bl2);
        mma_bf16(c3, al4, bh);
    }
}

__global__ __launch_bounds__(384, 1) void k_taskmap(
    const float* __restrict__ x,
    const float* __restrict__ b1, const float* __restrict__ b2, const float* __restrict__ b3,
    const float* __restrict__ b4, const float* __restrict__ b5, const float* __restrict__ b6) {
    extern __shared__ char smem[];
    uint32_t sbase = smem_u32(smem);
    __nv_bfloat16* AHp = (__nv_bfloat16*)(smem + OF_AH);
    __nv_bfloat16* ALp = (__nv_bfloat16*)(smem + OF_AL);
    float* xs   = (float*)(smem + OF_XS);
    float* v2   = (float*)(smem + OF_V2);
    float* ss   = (float*)(smem + OF_SS);
    float* sg   = (float*)(smem + OF_SG);
    float* Jsh  = (float*)(smem + OF_JS);
    float* accb = (float*)(smem + OF_ACC);

    const int tid = threadIdx.x;
    const int wid = tid >> 5, lane = tid & 31;
    const int g = lane >> 2, tg = lane & 3;
    const int gbase = blockIdx.x * 64;

    if (tid < 128) xs[tid] = x[blockIdx.x * 128 + tid];
    // stage L1 + L3 B tiles (both layers)
    {
        uint4* d1H = (uint4*)(smem + OF_L1H);
        uint4* d1L = (uint4*)(smem + OF_L1L);
        const uint4* s1H = (const uint4*)g_T1H;
        const uint4* s1L = (const uint4*)g_T1L;
        for (int i = tid; i < 1040; i += 384) { d1H[i] = s1H[i]; d1L[i] = s1L[i]; }
        uint4* d3H = (uint4*)(smem + OF_L3H);
        uint4* d3L = (uint4*)(smem + OF_L3L);
        const uint4* s3H = (const uint4*)g_T3H;
        const uint4* s3L = (const uint4*)g_T3L;
        for (int i = tid; i < 240; i += 384) { d3H[i] = s3H[i]; d3L[i] = s3L[i]; }
    }
    // zero A pad cols 100..119 (persist across layers)
    for (int i = tid; i < 3840; i += 384) {
        int row = i / 20, col = 100 + i % 20;
        AHp[row * 120 + col] = __float2bfloat16(0.f);
        ALp[row * 120 + col] = __float2bfloat16(0.f);
    }
    __syncthreads();

    // ---- build A for tm1 L1: value rows = [x0,x1,0..], tangent rows = e_c ----
    for (int i = tid; i < 3072; i += 384) {
        int row = i >> 4, col = i & 15;
        float v;
        if (row < 64) v = (col < 2) ? xs[row * 2 + col] : 0.f;
        else v = (col == ((row - 64) >> 6)) ? 1.f : 0.f;
        __nv_bfloat16 hi, lo; bf16split(v, hi, lo);
        AHp[row * 120 + col] = hi;
        ALp[row * 120 + col] = lo;
    }

    // ---- tm1 L1 (2->100, tanh) ----
    mma_dense<0, 1, 40>(smem, sbase, OF_L1H, OF_L1L, b1, -1);
    // ---- tm1 L2 (100x100, tanh) ----
    mma_dense<0, 7, 120>(smem, sbase, OF_WH, OF_WL, b2, 0);

    // ---- tm1 L3 (100->2) + residual / identity ----
    {
        float c3[4];
        mma_tail_frag(sbase, OF_L3H, OF_L3L, c3);
        if (tg == 0) {
            float b30 = b3[0], b31 = b3[1];
#pragma unroll
            for (int hh = 0; hh < 2; hh++) {
                int r = wid * 16 + g + hh * 8;
                float cv0 = c3[hh * 2 + 0], cv1 = c3[hh * 2 + 1];
                if (r < 64) {
                    v2[r * 2 + 0] = cv0 + b30 + xs[r * 2 + 0];
                    v2[r * 2 + 1] = cv1 + b31 + xs[r * 2 + 1];
                } else {
                    int cmp = (r >> 6) - 1;
                    v2[r * 2 + 0] = cv0 + (cmp == 0 ? 1.f : 0.f);
                    v2[r * 2 + 1] = cv1 + (cmp == 1 ? 1.f : 0.f);
                }
            }
        }
        __syncthreads();
    }

    // ---- build A for tm2 L1: all rows = [v2_0, v2_1, 0..] ----
    for (int i = tid; i < 3072; i += 384) {
        int row = i >> 4, col = i & 15;
        float v = (col < 2) ? v2[row * 2 + col] : 0.f;
        __nv_bfloat16 hi, lo; bf16split(v, hi, lo);
        AHp[row * 120 + col] = hi;
        ALp[row * 120 + col] = lo;
    }

    // ---- tm2 L1 (2->100, elu) ----
    mma_dense<1, 1, 40>(smem, sbase, OF_L1H + 8320, OF_L1L + 8320, b4, -1);
    // ---- tm2 L2 (100x100, elu) ----
    mma_dense<1, 7, 120>(smem, sbase, OF_WH, OF_WL, b5, 1);

    // ---- tm2 L3 (100->2): softplus gate + y / J accumulation ----
    {
        float c3[4];
        mma_tail_frag(sbase, OF_L3H + 1920, OF_L3L + 1920, c3);
        if (tg == 0) {
            float b60 = b6[0], b61 = b6[1];
#pragma unroll
            for (int hh = 0; hh < 2; hh++) {
                int r = wid * 16 + g + hh * 8;
                float cv0 = c3[hh * 2 + 0], cv1 = c3[hh * 2 + 1];
                if (r < 64) {
                    float pv0 = cv0 + b60, pv1 = cv1 + b61;
                    float s0 = softplusf(pv0), s1 = softplusf(pv1);
                    ss[r * 2 + 0] = s0; ss[r * 2 + 1] = s1;
                    sg[r * 2 + 0] = 1.f / (1.f + expf(-pv0));
                    sg[r * 2 + 1] = 1.f / (1.f + expf(-pv1));
                    g_y[(gbase + r) * 2 + 0] = (1.f + s0) * v2[r * 2 + 0] - g_origin[0];
                    g_y[(gbase + r) * 2 + 1] = (1.f + s1) * v2[r * 2 + 1] - g_origin[1];
                } else {
                    accb[r * 2 + 0] = cv0;
                    accb[r * 2 + 1] = cv1;
                }
            }
        }
        __syncthreads();
    }

    // ---- J assembly + 2x2 pinv ----
    if (tid < 256) {
        int r = 64 + (tid >> 1), i = tid & 1;
        int c = r / 64 - 1, p = r % 64;
        float acc = accb[r * 2 + i];
        float s = ss[p * 2 + i];
        float ds = sg[p * 2 + i] * acc;
        Jsh[p * 4 + i * 2 + c] = fmaf(ds, v2[p * 2 + i], (1.f + s) * v2[r * 2 + i]);
    }
    __syncthreads();
    if (tid < 64) {
        int p = tid, gp = gbase + p;
        float a = Jsh[p * 4 + 0], b_ = Jsh[p * 4 + 1];
        float c = Jsh[p * 4 + 2], d = Jsh[p * 4 + 3];
        float det = a * d - b_ * c;
        float n2 = a * a + b_ * b_ + c * c + d * d;
        float ia, ib, ic, id;
        if (fabsf(det) > 1e-10f * n2) {
            float inv = 1.f / det;
            ia = d * inv; ib = -b_ * inv; ic = -c * inv; id = a * inv;
        } else {
            float inv = (n2 > 0.f) ? 1.f / n2 : 0.f;
            ia = a * inv; ib = c * inv; ic = b_ * inv; id = d * inv;
        }
        float4 o; o.x = ia; o.y = ib; o.z = ic; o.w = id;
        *reinterpret_cast<float4*>(g_jinv + gp * 4) = o;
    }
}

// ============ K2 (HMMA): vv net via bf16-split mma.sync ====================
__global__ __launch_bounds__(512, 1) void k_vv_mma(
    const float* __restrict__ w1, const float* __restrict__ b1, const float* __restrict__ a1p,
    const float* __restrict__ b2, const float* __restrict__ a2p,
    const float* __restrict__ w3, const float* __restrict__ b3) {
    extern __shared__ char smem[];
    const int OF_AH2 = 0;
    const int OF_AL2 = 18432;
    const int OF_BH2 = 36864;
    const int OF_BL2 = 80640;
    const int OF_YS2 = 124416;
    const int OF_B22 = 125440;
    const int OF_W32 = 126656;
    const int OF_DS2 = 129088;
    uint32_t sbase = smem_u32(smem);
    float* ys  = (float*)(smem + OF_YS2);
    float* b2p = (float*)(smem + OF_B22);
    float* w3p = (float*)(smem + OF_W32);
    float* dsum = (float*)(smem + OF_DS2);

    const int tid = threadIdx.x;
    const int wid = tid >> 5, lane = tid & 31;
    const int wrow = (wid & 7) * 16;
    const int nh = wid >> 3;
    const int g = lane >> 2, tg = lane & 3;

    if (tid < 256) ys[tid] = g_y[blockIdx.x * 256 + tid];
    for (int i = tid; i < 304; i += 512) b2p[i] = (i < 300) ? b2[i] : 0.f;
    for (int i = tid; i < 608; i += 512) w3p[i] = (i < 600) ? w3[i] : 0.f;
    if (tid < 256) dsum[tid] = b3[tid & 1];
    const float al1 = a1p[0];

    const int at = lane >> 3, ar = lane & 7;
    const int arow = wrow + (at & 1) * 8 + ar;
    const int acol = (at >> 1) * 8;
    const int bl = lane & 15;
    const int brow_off = bl & 7;
    const int bcol = (bl >> 3) * 8;

    float c[19][4];
#pragma unroll
    for (int nt = 0; nt < 19; nt++)
#pragma unroll
        for (int q = 0; q < 4; q++) c[nt][q] = 0.f;

    for (int kc = 0; kc < 5; kc++) {
        __syncthreads();
        {
            uint4* dH = (uint4*)(smem + OF_BH2);
            uint4* dL = (uint4*)(smem + OF_BL2);
            const uint4* sH = (const uint4*)g_BH[kc];
            const uint4* sL = (const uint4*)g_BL[kc];
            for (int i = tid; i < 2736; i += 512) { dH[i] = sH[i]; dL[i] = sL[i]; }
        }
        for (int idx = tid; idx < 8192; idx += 512) {
            int p = idx >> 6, kl = idx & 63;
            int kg = kc * 64 + kl;
            float v = 0.f;
            if (kg < 300) {
                v = fmaf(ys[p * 2], w1[kg], fmaf(ys[p * 2 + 1], w1[300 + kg], b1[kg]));
                v = (v >= 0.f) ? v : al1 * v;
            }
            __nv_bfloat16 hi, lo; bf16split(v, hi, lo);
            ((__nv_bfloat16*)(smem + OF_AH2))[p * 72 + kl] = hi;
            ((__nv_bfloat16*)(smem + OF_AL2))[p * 72 + kl] = lo;
        }
        __syncthreads();

#pragma unroll
        for (int kt = 0; kt < 4; kt++) {
            uint32_t ah[4], al4[4];
            uint32_t aoff = (uint32_t)((arow * 72 + kt * 16 + acol) * 2);
            ldsm_x4(ah[0], ah[1], ah[2], ah[3], sbase + OF_AH2 + aoff);
            ldsm_x4(al4[0], al4[1], al4[2], al4[3], sbase + OF_AL2 + aoff);
#pragma unroll
            for (int nt = 0; nt < 19; nt++) {
                int n0 = nh * 152 + nt * 8;
                uint32_t boff = (uint32_t)(((n0 + brow_off) * 72 + kt * 16 + bcol) * 2);
                uint32_t bh[2], bl2[2];
                ldsm_x2(bh[0], bh[1], sbase + OF_BH2 + boff);
                ldsm_x2(bl2[0], bl2[1], sbase + OF_BL2 + boff);
                mma_bf16(c[nt], ah, bh);
                mma_bf16(c[nt], ah, bl2);
                mma_bf16(c[nt], al4, bh);
            }
        }
    }

    {
        const float al2 = a2p[0];
        float d0a = 0.f, d1a = 0.f, d0b = 0.f, d1b = 0.f;
#pragma unroll
        for (int nt = 0; nt < 19; nt++) {
            int n = nh * 152 + nt * 8 + tg * 2;
            float bb0 = b2p[n], bb1 = b2p[n + 1];
            float wa0 = w3p[2 * n + 0], wa1 = w3p[2 * n + 1];
            float wb0 = w3p[2 * n + 2], wb1 = w3p[2 * n + 3];
            float h;
            h = c[nt][0] + bb0; h = (h >= 0.f) ? h : al2 * h;
            d0a = fmaf(h, wa0, d0a); d1a = fmaf(h, wa1, d1a);
            h = c[nt][1] + bb1; h = (h >= 0.f) ? h : al2 * h;
            d0a = fmaf(h, wb0, d0a); d1a = fmaf(h, wb1, d1a);
            h = c[nt][2] + bb0; h = (h >= 0.f) ? h : al2 * h;
            d0b = fmaf(h, wa0, d0b); d1b = fmaf(h, wa1, d1b);
            h = c[nt][3] + bb1; h = (h >= 0.f) ? h : al2 * h;
            d0b = fmaf(h, wb0, d0b); d1b = fmaf(h, wb1, d1b);
        }
        d0a += __shfl_xor_sync(0xffffffffu, d0a, 1); d0a += __shfl_xor_sync(0xffffffffu, d0a, 2);
        d1a += __shfl_xor_sync(0xffffffffu, d1a, 1); d1a += __shfl_xor_sync(0xffffffffu, d1a, 2);
        d0b += __shfl_xor_sync(0xffffffffu, d0b, 1); d0b += __shfl_xor_sync(0xffffffffu, d0b, 2);
        d1b += __shfl_xor_sync(0xffffffffu, d1b, 1); d1b += __shfl_xor_sync(0xffffffffu, d1b, 2);
        if (tg == 0) {
            int r0 = wrow + g, r1 = wrow + g + 8;
            atomicAdd(&dsum[r0 * 2 + 0], d0a); atomicAdd(&dsum[r0 * 2 + 1], d1a);
            atomicAdd(&dsum[r1 * 2 + 0], d0b); atomicAdd(&dsum[r1 * 2 + 1], d1b);
        }
    }
    __syncthreads();

    if (tid < 128) {
        int p = tid, gp = blockIdx.x * 128 + p;
        float d0 = dsum[p * 2 + 0], d1 = dsum[p * 2 + 1];
        float y0 = ys[p * 2 + 0], y1 = ys[p * 2 + 1];
        float lsv = d0 * y0 + d1 * y1;
        float Vy = y0 * y0 + y1 * y1;
        float rl = fmaxf(fmaf(1e-4f, Vy, lsv), 0.f);
        float sc = rl / (Vy + 1e-12f);
        float yd0 = d0 - sc * y0, yd1 = d1 - sc * y1;
        float nrm = sqrtf(yd0 * yd0 + yd1 * yd1);
        float innv = 1.f / fmaxf(nrm, 1e-12f);
        float n0 = yd0 * innv, n1 = yd1 * innv;
        float4 Ji = *reinterpret_cast<const float4*>(g_jinv + gp * 4);
        g_xdh[gp * 2 + 0] = Ji.x * n0 + Ji.y * n1;
        g_xdh[gp * 2 + 1] = Ji.z * n0 + Ji.w * n1;
    }
}

// =================== K3: vel-scalar net + final scaling ====================
__global__ __launch_bounds__(224, 2) void k_vs(
    const float* __restrict__ x,
    const float* __restrict__ w1, const float* __restrict__ b1,
    const float* __restrict__ w2, const float* __restrict__ b2,
    const float* __restrict__ w3, const float* __restrict__ b3,
    float* __restrict__ out) {
    extern __shared__ float sm[];
    float* ws   = sm;
    float* bufA = ws + 10400;
    float* xs   = bufA + 13824;
    float* b2p  = xs + 256;
    ull* w3u    = (ull*)(b2p + 104);
    float* dsum = b2p + 104 + 104;

    const int tid = threadIdx.x;
    const bool active = tid < 208;
    const int rg = tid / 13, og = tid % 13;
    const int row0 = rg * 8, jb = og * 8;
    const int gbase = blockIdx.x * 128;

    for (int i = tid; i < 256; i += 224) xs[i] = x[blockIdx.x * 256 + i];
    for (int i = tid; i < 10400; i += 224) {
        int k = i / 104, j = i % 104;
        ws[i] = (j < 100) ? w2[k * 100 + j] : 0.f;
    }
    if (tid < 104) b2p[tid] = (tid < 100) ? b2[tid] : 0.f;
    if (tid < 52) w3u[tid] = (tid < 50) ? ((const ull*)w3)[tid] : 0ULL;
    if (tid < 128) dsum[tid] = b3[0];
    __syncthreads();

    for (int i = tid; i < 12800; i += 224) {
        int p = i / 100, j = i % 100;
        float v = fmaf(xs[p * 2], w1[j], fmaf(xs[p * 2 + 1], w1[100 + j], b1[j]));
        bufA[p * 108 + j] = (v >= 0.f) ? v : 0.01f * v;
    }
    __syncthreads();

    ull acc[8][4];
#pragma unroll
    for (int r = 0; r < 8; r++)
#pragma unroll
        for (int q = 0; q < 4; q++) acc[r][q] = 0ULL;
    if (active) {
        for (int k = 0; k < 100; k += 4) {
            ulonglong2 wA0 = *(const ulonglong2*)(ws + (k + 0) * 104 + jb);
            ulonglong2 wA1 = *(const ulonglong2*)(ws + (k + 0) * 104 + jb + 4);
            ulonglong2 wB0 = *(const ulonglong2*)(ws + (k + 1) * 104 + jb);
            ulonglong2 wB1 = *(const ulonglong2*)(ws + (k + 1) * 104 + jb + 4);
            ulonglong2 wC0 = *(const ulonglong2*)(ws + (k + 2) * 104 + jb);
            ulonglong2 wC1 = *(const ulonglong2*)(ws + (k + 2) * 104 + jb + 4);
            ulonglong2 wD0 = *(const ulonglong2*)(ws + (k + 3) * 104 + jb);
            ulonglong2 wD1 = *(const ulonglong2*)(ws + (k + 3) * 104 + jb + 4);
#pragma unroll
            for (int r = 0; r < 8; r++) {
                float4 a = *(const float4*)(bufA + (row0 + r) * 108 + k);
                GS2(r, bc2(a.x), wA0, wA1)
                GS2(r, bc2(a.y), wB0, wB1)
                GS2(r, bc2(a.z), wC0, wC1)
                GS2(r, bc2(a.w), wD0, wD1)
            }
        }
#pragma unroll
        for (int r = 0; r < 8; r++) {
            ull dp2 = 0ULL;
#pragma unroll
            for (int q = 0; q < 4; q++) {
                float h0, h1; upk2(acc[r][q], h0, h1);
                int j = jb + 2 * q;
                h0 += b2p[j]; h1 += b2p[j + 1];
                h0 = (h0 >= 0.f) ? h0 : 0.01f * h0;
                h1 = (h1 >= 0.f) ? h1 : 0.01f * h1;
                fma2(dp2, pk2(h0, h1), w3u[j >> 1]);
            }
            float s0, s1; upk2(dp2, s0, s1);
            atomicAdd(&dsum[row0 + r], s0 + s1);
        }
    }
    __syncthreads();

    if (tid < 128) {
        int p = tid, gp = gbase + p;
        float t = dsum[p];
        float x0 = xs[p * 2 + 0], x1 = xs[p * 2 + 1];
        out[gp * 2 + 0] = (expf(t + x0) + 1e-12f) * g_xdh[gp * 2 + 0];
        out[gp * 2 + 1] = (expf(t + x1) + 1e-12f) * g_xdh[gp * 2 + 1];
    }
}

// ============================== launch =====================================
extern "C" void kernel_launch(void* const* d_in, const int* in_sizes, int n_in,
                              void* d_out, int out_size) {
    const float* x     = (const float*)d_in[0];
    const float* t1w1  = (const float*)d_in[1];
    const float* t1b1  = (const float*)d_in[2];
    const float* t1w2  = (const float*)d_in[3];
    const float* t1b2  = (const float*)d_in[4];
    const float* t1w3  = (const float*)d_in[5];
    const float* t1b3  = (const float*)d_in[6];
    const float* t2w1  = (const float*)d_in[7];
    const float* t2b1  = (const float*)d_in[8];
    const float* t2w2  = (const float*)d_in[9];
    const float* t2b2  = (const float*)d_in[10];
    const float* t2w3  = (const float*)d_in[11];
    const float* t2b3  = (const float*)d_in[12];
    const float* vvw1  = (const float*)d_in[13];
    const float* vvb1  = (const float*)d_in[14];
    const float* vva1  = (const float*)d_in[15];
    const float* vvw2  = (const float*)d_in[16];
    const float* vvb2  = (const float*)d_in[17];
    const float* vva2  = (const float*)d_in[18];
    const float* vvw3  = (const float*)d_in[19];
    const float* vvb3  = (const float*)d_in[20];
    const float* vsw1  = (const float*)d_in[21];
    const float* vsb1  = (const float*)d_in[22];
    const float* vsw2  = (const float*)d_in[23];
    const float* vsb2  = (const float*)d_in[24];
    const float* vsw3  = (const float*)d_in[25];
    const float* vsb3  = (const float*)d_in[26];

    const int SM2 = 130112;
    const int SM3 = (10400 + 13824 + 256 + 104 + 104 + 128) * 4;

    cudaFuncSetAttribute(k_taskmap, cudaFuncAttributeMaxDynamicSharedMemorySize, SM1_BYTES);
    cudaFuncSetAttribute(k_vv_mma, cudaFuncAttributeMaxDynamicSharedMemorySize, SM2);
    cudaFuncSetAttribute(k_vs, cudaFuncAttributeMaxDynamicSharedMemorySize, SM3);

    k_origin<<<1, 128>>>(t1w1, t1b1, t1w2, t1b2, t1w3, t1b3,
                         t2w1, t2b1, t2w2, t2b2, t2w3, t2b3);
    k_prep<<<380, 256>>>(vvw2);
    k_prep2<<<138, 256>>>(t1w2, t2w2, t1w1, t2w1, t1w3, t2w3);
    k_taskmap<<<NPTS / 64, 384, SM1_BYTES>>>(x, t1b1, t1b2, t1b3,
                                             t2b1, t2b2, t2b3);
    k_vv_mma<<<NPTS / 128, 512, SM2>>>(vvw1, vvb1, vva1, vvb2, vva2, vvw3, vvb3);
    k_vs<<<NPTS / 128, 224, SM3>>>(x, vsw1, vsb1, vsw2, vsb2, vsw3, vsb3,
                                   (float*)d_out);
}

// round 11
// speedup vs baseline: 2.1957x; 1.0170x over previous
#include <cuda_runtime.h>
#include <cuda_bf16.h>
#include <math.h>
#include <stdint.h>

#define NPTS 131072
typedef unsigned long long ull;

__device__ float g_origin[2];
__device__ float g_y[NPTS * 2];
__device__ float g_jinv[NPTS * 4];
__device__ float g_xdh[NPTS * 2];
// W2^T (vv) bf16 hi/lo, [5 K-chunks][304 x 72]
__device__ __nv_bfloat16 g_BH[5][304 * 72];
__device__ __nv_bfloat16 g_BL[5][304 * 72];
// taskmap weights, bf16 hi/lo, transposed [n][k]:
__device__ __nv_bfloat16 g_TH[2 * 104 * 120];   // mid layers (stride 120)
__device__ __nv_bfloat16 g_TL[2 * 104 * 120];
__device__ __nv_bfloat16 g_T1H[2 * 104 * 40];   // L1 layers (stride 40, k<2)
__device__ __nv_bfloat16 g_T1L[2 * 104 * 40];
__device__ __nv_bfloat16 g_T3H[2 * 8 * 120];    // L3 layers (8 n-rows, stride 120)
__device__ __nv_bfloat16 g_T3L[2 * 8 * 120];

__device__ __forceinline__ float eluf(float v) { return v > 0.f ? v : expm1f(v); }
__device__ __forceinline__ float softplusf(float p) {
    return fmaxf(p, 0.f) + log1pf(expf(-fabsf(p)));
}
__device__ __forceinline__ void bf16split(float v, __nv_bfloat16& hi, __nv_bfloat16& lo) {
    hi = __float2bfloat16(v);
    lo = __float2bfloat16(v - __bfloat162float(hi));
}

// ---- packed f32x2 helpers ----
__device__ __forceinline__ ull pk2(float a, float b) {
    ull r; asm("mov.b64 %0,{%1,%2};" : "=l"(r) : "f"(a), "f"(b)); return r;
}
__device__ __forceinline__ ull bc2(float a) { return pk2(a, a); }
__device__ __forceinline__ void upk2(ull v, float& a, float& b) {
    asm("mov.b64 {%0,%1},%2;" : "=f"(a), "=f"(b) : "l"(v));
}
__device__ __forceinline__ void fma2(ull& d, ull a, ull b) {
    asm("fma.rn.f32x2 %0, %1, %2, %0;" : "+l"(d) : "l"(a), "l"(b));
}
#define GS2(r, AB, U0, U1)            \
    fma2(acc[r][0], AB, U0.x);        \
    fma2(acc[r][1], AB, U0.y);        \
    fma2(acc[r][2], AB, U1.x);        \
    fma2(acc[r][3], AB, U1.y);

__device__ __forceinline__ uint32_t smem_u32(const void* p) {
    uint32_t a;
    asm("{ .reg .u64 t; cvta.to.shared.u64 t, %1; cvt.u32.u64 %0, t; }" : "=r"(a) : "l"(p));
    return a;
}
// ---- HMMA helpers ----
__device__ __forceinline__ void ldsm_x4(uint32_t& r0, uint32_t& r1, uint32_t& r2, uint32_t& r3,
                                        uint32_t addr) {
    asm volatile("ldmatrix.sync.aligned.m8n8.x4.shared.b16 {%0,%1,%2,%3}, [%4];"
                 : "=r"(r0), "=r"(r1), "=r"(r2), "=r"(r3) : "r"(addr));
}
__device__ __forceinline__ void ldsm_x2(uint32_t& r0, uint32_t& r1, uint32_t addr) {
    asm volatile("ldmatrix.sync.aligned.m8n8.x2.shared.b16 {%0,%1}, [%2];"
                 : "=r"(r0), "=r"(r1) : "r"(addr));
}
__device__ __forceinline__ void mma_bf16(float* c, const uint32_t* a, const uint32_t* b) {
    asm volatile(
        "mma.sync.aligned.m16n8k16.row.col.f32.bf16.bf16.f32 "
        "{%0,%1,%2,%3}, {%4,%5,%6,%7}, {%8,%9}, {%0,%1,%2,%3};"
        : "+f"(c[0]), "+f"(c[1]), "+f"(c[2]), "+f"(c[3])
        : "r"(a[0]), "r"(a[1]), "r"(a[2]), "r"(a[3]), "r"(b[0]), "r"(b[1]));
}

// ========================= K0: origin = taskmap(0) =========================
__global__ void k_origin(const float* __restrict__ w1, const float* __restrict__ b1,
                         const float* __restrict__ w2, const float* __restrict__ b2,
                         const float* __restrict__ w3, const float* __restrict__ b3,
                         const float* __restrict__ w4, const float* __restrict__ b4,
                         const float* __restrict__ w5, const float* __restrict__ b5,
                         const float* __restrict__ w6, const float* __restrict__ b6) {
    __shared__ float h[100], h2[100], y1s[2];
    int j = threadIdx.x;
    if (j < 100) h[j] = tanhf(b1[j]);
    __syncthreads();
    if (j < 100) {
        float a = b2[j];
        for (int k = 0; k < 100; k++) a = fmaf(h[k], w2[k * 100 + j], a);
        h2[j] = tanhf(a);
    }
    __syncthreads();
    if (j < 2) {
        float a = b3[j];
        for (int k = 0; k < 100; k++) a = fmaf(h2[k], w3[k * 2 + j], a);
        y1s[j] = a;
    }
    __syncthreads();
    if (j < 100) {
        float a = fmaf(y1s[0], w4[j], fmaf(y1s[1], w4[100 + j], b4[j]));
        h[j] = eluf(a);
    }
    __syncthreads();
    if (j < 100) {
        float a = b5[j];
        for (int k = 0; k < 100; k++) a = fmaf(h[k], w5[k * 100 + j], a);
        h2[j] = eluf(a);
    }
    __syncthreads();
    if (j < 2) {
        float a = b6[j];
        for (int k = 0; k < 100; k++) a = fmaf(h2[k], w6[k * 2 + j], a);
        float s = softplusf(a);
        g_origin[j] = (1.f + s) * y1s[j];
    }
}

// ====== prep: W2 (vv) -> [n][k] bf16 hi/lo ======
__global__ void k_prep(const float* __restrict__ w2) {
    int i = blockIdx.x * blockDim.x + threadIdx.x;
    if (i >= 5 * 304 * 64) return;
    int kc = i / (304 * 64);
    int r = i % (304 * 64);
    int n = r / 64, kl = r % 64;
    int kg = kc * 64 + kl;
    float v = (kg < 300 && n < 300) ? w2[kg * 300 + n] : 0.f;
    __nv_bfloat16 hi, lo; bf16split(v, hi, lo);
    g_BH[kc][n * 72 + kl] = hi;
    g_BL[kc][n * 72 + kl] = lo;
}
// ====== prep2: taskmap L1/L2/L3 weights -> transposed bf16 hi/lo ======
__global__ void k_prep2(const float* __restrict__ w2, const float* __restrict__ w5,
                        const float* __restrict__ w1, const float* __restrict__ w4,
                        const float* __restrict__ w3, const float* __restrict__ w6) {
    int i = blockIdx.x * blockDim.x + threadIdx.x;
    if (i < 24960) {                        // mid: 2 x 104 x 120
        int l = i / 12480, r = i % 12480, n = r / 120, k = r % 120;
        const float* W = l ? w5 : w2;
        float v = (n < 100 && k < 100) ? W[k * 100 + n] : 0.f;
        __nv_bfloat16 hi, lo; bf16split(v, hi, lo);
        g_TH[l * 12480 + n * 120 + k] = hi;
        g_TL[l * 12480 + n * 120 + k] = lo;
    } else if (i < 24960 + 8320) {          // L1: 2 x 104 x 40
        int j = i - 24960;
        int l = j / 4160, r = j % 4160, n = r / 40, k = r % 40;
        const float* W = l ? w4 : w1;
        float v = (n < 100 && k < 2) ? W[k * 100 + n] : 0.f;
        __nv_bfloat16 hi, lo; bf16split(v, hi, lo);
        g_T1H[l * 4160 + n * 40 + k] = hi;
        g_T1L[l * 4160 + n * 40 + k] = lo;
    } else if (i < 24960 + 8320 + 1920) {   // L3: 2 x 8 x 120
        int j = i - 33280;
        int l = j / 960, r = j % 960, n = r / 120, k = r % 120;
        const float* W = l ? w6 : w3;
        float v = (n < 2 && k < 100) ? W[k * 2 + n] : 0.f;
        __nv_bfloat16 hi, lo; bf16split(v, hi, lo);
        g_T3H[l * 960 + n * 120 + k] = hi;
        g_T3L[l * 960 + n * 120 + k] = lo;
    }
}

// ========================= K1: taskmap + Jacobian (all-HMMA, 2 CTA/SM) =====
// 32 pts/block, 96 rows (32 value + 64 tangent), 192 threads = 6 warps.
// All B tiles staged through ONE shared buffer (WH/WL) per layer.
#define OF_AH 0
#define OF_AL 23040
#define OF_WH 46080
#define OF_WL 71040
#define OF_HB 96000
#define OF_SS  96000
#define OF_SG  96256
#define OF_ACC 96512
#define OF_JS  97280
#define OF_XS 109312
#define OF_V2 109568
#define OF_BP 110336
#define SM1_BYTES 110752

// Dense layer via HMMA: M=96 (6 warps), N=104 (13 nt), K=16*NKT, bf16-split.
// Value warps (0-1, rows 0..31): act + store h bf16 hi/lo + act'(h) into hbuf.
// Tangent warps (2-5, rows 32..95): scale raw frags by act'(h), store hi/lo.
template <int ACT, int NKT, int BSTRIDE>
__device__ __forceinline__ void mma_dense(char* smem, uint32_t sbase,
                                          const float* __restrict__ bvec,
                                          const uint4* srcH, const uint4* srcL, int n16) {
    const int tid = threadIdx.x;
    const int wid = tid >> 5, lane = tid & 31;
    float* bp = (float*)(smem + OF_BP);
    float* hbuf = (float*)(smem + OF_HB);
    __nv_bfloat16* AHp = (__nv_bfloat16*)(smem + OF_AH);
    __nv_bfloat16* ALp = (__nv_bfloat16*)(smem + OF_AL);

    {
        uint4* dH = (uint4*)(smem + OF_WH);
        uint4* dL = (uint4*)(smem + OF_WL);
        for (int i = tid; i < n16; i += 192) { dH[i] = srcH[i]; dL[i] = srcL[i]; }
    }
    if (tid < 104) bp[tid] = (tid < 100) ? bvec[tid] : 0.f;
    __syncthreads();

    const int mrow = wid * 16;
    const int at = lane >> 3, ar = lane & 7;
    const int arow = mrow + (at & 1) * 8 + ar;
    const int acol = (at >> 1) * 8;
    const int blx = lane & 15;
    const int brow = blx & 7;
    const int bcol = (blx >> 3) * 8;
    const int g = lane >> 2, tg = lane & 3;

    float c[13][4];
#pragma unroll
    for (int nt = 0; nt < 13; nt++)
#pragma unroll
        for (int q = 0; q < 4; q++) c[nt][q] = 0.f;

#pragma unroll
    for (int kt = 0; kt < NKT; kt++) {
        uint32_t ah[4], al4[4];
        uint32_t aoff = (uint32_t)((arow * 120 + kt * 16 + acol) * 2);
        ldsm_x4(ah[0], ah[1], ah[2], ah[3], sbase + OF_AH + aoff);
        ldsm_x4(al4[0], al4[1], al4[2], al4[3], sbase + OF_AL + aoff);
#pragma unroll
        for (int nt = 0; nt < 13; nt++) {
            uint32_t boff = (uint32_t)(((nt * 8 + brow) * BSTRIDE + kt * 16 + bcol) * 2);
            uint32_t bh[2], bl2[2];
            ldsm_x2(bh[0], bh[1], sbase + OF_WH + boff);
            ldsm_x2(bl2[0], bl2[1], sbase + OF_WL + boff);
            mma_bf16(c[nt], ah, bh);
            mma_bf16(c[nt], ah, bl2);
            mma_bf16(c[nt], al4, bh);
        }
    }
    __syncthreads();  // all A/B reads done before A rewrite

    if (wid < 2) {
        int r0 = mrow + g, r1 = mrow + g + 8;
#pragma unroll
        for (int nt = 0; nt < 13; nt++) {
#pragma unroll
            for (int q = 0; q < 4; q++) {
                int row = (q < 2) ? r0 : r1;
                int col = nt * 8 + tg * 2 + (q & 1);
                float h = c[nt][q] + bp[col];
                h = (ACT == 0) ? tanhf(h) : eluf(h);
                float d = (ACT == 0) ? (1.f - h * h) : (h > 0.f ? 1.f : h + 1.f);
                hbuf[row * 104 + col] = d;
                __nv_bfloat16 hi, lo; bf16split(h, hi, lo);
                AHp[row * 120 + col] = hi;
                ALp[row * 120 + col] = lo;
            }
        }
    }
    __syncthreads();
    if (wid >= 2) {
        int r0 = mrow + g, r1 = mrow + g + 8;
#pragma unroll
        for (int nt = 0; nt < 13; nt++) {
#pragma unroll
            for (int q = 0; q < 4; q++) {
                int row = (q < 2) ? r0 : r1;
                int col = nt * 8 + tg * 2 + (q & 1);
                float v = c[nt][q] * hbuf[(row & 31) * 104 + col];
                __nv_bfloat16 hi, lo; bf16split(v, hi, lo);
                AHp[row * 120 + col] = hi;
                ALp[row * 120 + col] = lo;
            }
        }
    }
    __syncthreads();
}

// L3 tail: stage 8x120 B hi/lo into WS, N-tile 0 only, K=112.
__device__ __forceinline__ void mma_tail_frag(char* smem, uint32_t sbase,
                                              const uint4* srcH, const uint4* srcL,
                                              float* c3) {
    const int tid = threadIdx.x;
    const int wid = tid >> 5, lane = tid & 31;
    {
        uint4* dH = (uint4*)(smem + OF_WH);
        uint4* dL = (uint4*)(smem + OF_WL);
        for (int i = tid; i < 120; i += 192) { dH[i] = srcH[i]; dL[i] = srcL[i]; }
    }
    __syncthreads();
    const int mrow = wid * 16;
    const int at = lane >> 3, ar = lane & 7;
    const int arow = mrow + (at & 1) * 8 + ar;
    const int acol = (at >> 1) * 8;
    const int blx = lane & 15;
    const int brow = blx & 7;
    const int bcol = (blx >> 3) * 8;
    c3[0] = c3[1] = c3[2] = c3[3] = 0.f;
#pragma unroll
    for (int kt = 0; kt < 7; kt++) {
        uint32_t ah[4], al4[4];
        uint32_t aoff = (uint32_t)((arow * 120 + kt * 16 + acol) * 2);
        ldsm_x4(ah[0], ah[1], ah[2], ah[3], sbase + OF_AH + aoff);
        ldsm_x4(al4[0], al4[1], al4[2], al4[3], sbase + OF_AL + aoff);
        uint32_t boff = (uint32_t)((brow * 120 + kt * 16 + bcol) * 2);
        uint32_t bh[2], bl2[2];
        ldsm_x2(bh[0], bh[1], sbase + OF_WH + boff);
        ldsm_x2(bl2[0], bl2[1], sbase + OF_WL + boff);
        mma_bf16(c3, ah, bh);
        mma_bf16(c3, ah, bl2);
        mma_bf16(c3, al4, bh);
    }
}

__global__ __launch_bounds__(192, 2) void k_taskmap(
    const float* __restrict__ x,
    const float* __restrict__ b1, const float* __restrict__ b2, const float* __restrict__ b3,
    const float* __restrict__ b4, const float* __restrict__ b5, const float* __restrict__ b6) {
    extern __shared__ char smem[];
    uint32_t sbase = smem_u32(smem);
    __nv_bfloat16* AHp = (__nv_bfloat16*)(smem + OF_AH);
    __nv_bfloat16* ALp = (__nv_bfloat16*)(smem + OF_AL);
    float* xs   = (float*)(smem + OF_XS);
    float* v2   = (float*)(smem + OF_V2);
    float* ss   = (float*)(smem + OF_SS);
    float* sg   = (float*)(smem + OF_SG);
    float* Jsh  = (float*)(smem + OF_JS);
    float* accb = (float*)(smem + OF_ACC);

    const int tid = threadIdx.x;
    const int wid = tid >> 5, lane = tid & 31;
    const int g = lane >> 2, tg = lane & 3;
    const int gbase = blockIdx.x * 32;

    if (tid < 64) xs[tid] = x[blockIdx.x * 64 + tid];
    // zero A pad cols 100..119 (persist across layers)
    for (int i = tid; i < 1920; i += 192) {
        int row = i / 20, col = 100 + i % 20;
        AHp[row * 120 + col] = __float2bfloat16(0.f);
        ALp[row * 120 + col] = __float2bfloat16(0.f);
    }
    __syncthreads();

    // ---- build A for tm1 L1: value rows = [x0,x1,0..], tangent rows = e_c ----
    for (int i = tid; i < 1536; i += 192) {
        int row = i >> 4, col = i & 15;
        float v;
        if (row < 32) v = (col < 2) ? xs[row * 2 + col] : 0.f;
        else v = (col == ((row - 32) >> 5)) ? 1.f : 0.f;
        __nv_bfloat16 hi, lo; bf16split(v, hi, lo);
        AHp[row * 120 + col] = hi;
        ALp[row * 120 + col] = lo;
    }

    // ---- tm1 L1 (2->100, tanh) ----
    mma_dense<0, 1, 40>(smem, sbase, b1, (const uint4*)g_T1H, (const uint4*)g_T1L, 520);
    // ---- tm1 L2 (100x100, tanh) ----
    mma_dense<0, 7, 120>(smem, sbase, b2, (const uint4*)g_TH, (const uint4*)g_TL, 1560);

    // ---- tm1 L3 (100->2) + residual / identity ----
    {
        float c3[4];
        mma_tail_frag(smem, sbase, (const uint4*)g_T3H, (const uint4*)g_T3L, c3);
        if (tg == 0) {
            float b30 = b3[0], b31 = b3[1];
#pragma unroll
            for (int hh = 0; hh < 2; hh++) {
                int r = wid * 16 + g + hh * 8;
                float cv0 = c3[hh * 2 + 0], cv1 = c3[hh * 2 + 1];
                if (r < 32) {
                    v2[r * 2 + 0] = cv0 + b30 + xs[r * 2 + 0];
                    v2[r * 2 + 1] = cv1 + b31 + xs[r * 2 + 1];
                } else {
                    int cmp = (r >> 5) - 1;
                    v2[r * 2 + 0] = cv0 + (cmp == 0 ? 1.f : 0.f);
                    v2[r * 2 + 1] = cv1 + (cmp == 1 ? 1.f : 0.f);
                }
            }
        }
        __syncthreads();
    }

    // ---- build A for tm2 L1: all rows = [v2_0, v2_1, 0..] ----
    for (int i = tid; i < 1536; i += 192) {
        int row = i >> 4, col = i & 15;
        float v = (col < 2) ? v2[row * 2 + col] : 0.f;
        __nv_bfloat16 hi, lo; bf16split(v, hi, lo);
        AHp[row * 120 + col] = hi;
        ALp[row * 120 + col] = lo;
    }

    // ---- tm2 L1 (2->100, elu) ----
    mma_dense<1, 1, 40>(smem, sbase, b4,
                        (const uint4*)(g_T1H + 4160), (const uint4*)(g_T1L + 4160), 520);
    // ---- tm2 L2 (100x100, elu) ----
    mma_dense<1, 7, 120>(smem, sbase, b5,
                         (const uint4*)(g_TH + 12480), (const uint4*)(g_TL + 12480), 1560);

    // ---- tm2 L3 (100->2): softplus gate + y / J accumulation ----
    {
        float c3[4];
        mma_tail_frag(smem, sbase, (const uint4*)(g_T3H + 960), (const uint4*)(g_T3L + 960), c3);
        if (tg == 0) {
            float b60 = b6[0], b61 = b6[1];
#pragma unroll
            for (int hh = 0; hh < 2; hh++) {
                int r = wid * 16 + g + hh * 8;
                float cv0 = c3[hh * 2 + 0], cv1 = c3[hh * 2 + 1];
                if (r < 32) {
                    float pv0 = cv0 + b60, pv1 = cv1 + b61;
                    float s0 = softplusf(pv0), s1 = softplusf(pv1);
                    ss[r * 2 + 0] = s0; ss[r * 2 + 1] = s1;
                    sg[r * 2 + 0] = 1.f / (1.f + expf(-pv0));
                    sg[r * 2 + 1] = 1.f / (1.f + expf(-pv1));
                    g_y[(gbase + r) * 2 + 0] = (1.f + s0) * v2[r * 2 + 0] - g_origin[0];
                    g_y[(gbase + r) * 2 + 1] = (1.f + s1) * v2[r * 2 + 1] - g_origin[1];
                } else {
                    accb[r * 2 + 0] = cv0;
                    accb[r * 2 + 1] = cv1;
                }
            }
        }
        __syncthreads();
    }

    // ---- J assembly + 2x2 pinv ----
    if (tid < 128) {
        int r = 32 + (tid >> 1), i = tid & 1;
        int c = (r >> 5) - 1, p = r & 31;
        float acc = accb[r * 2 + i];
        float s = ss[p * 2 + i];
        float ds = sg[p * 2 + i] * acc;
        Jsh[p * 4 + i * 2 + c] = fmaf(ds, v2[p * 2 + i], (1.f + s) * v2[r * 2 + i]);
    }
    __syncthreads();
    if (tid < 32) {
        int p = tid, gp = gbase + p;
        float a = Jsh[p * 4 + 0], b_ = Jsh[p * 4 + 1];
        float c = Jsh[p * 4 + 2], d = Jsh[p * 4 + 3];
        float det = a * d - b_ * c;
        float n2 = a * a + b_ * b_ + c * c + d * d;
        float ia, ib, ic, id;
        if (fabsf(det) > 1e-10f * n2) {
            float inv = 1.f / det;
            ia = d * inv; ib = -b_ * inv; ic = -c * inv; id = a * inv;
        } else {
            float inv = (n2 > 0.f) ? 1.f / n2 : 0.f;
            ia = a * inv; ib = c * inv; ic = b_ * inv; id = d * inv;
        }
        float4 o; o.x = ia; o.y = ib; o.z = ic; o.w = id;
        *reinterpret_cast<float4*>(g_jinv + gp * 4) = o;
    }
}

// ============ K2 (HMMA): vv net via bf16-split mma.sync ====================
__global__ __launch_bounds__(512, 1) void k_vv_mma(
    const float* __restrict__ w1, const float* __restrict__ b1, const float* __restrict__ a1p,
    const float* __restrict__ b2, const float* __restrict__ a2p,
    const float* __restrict__ w3, const float* __restrict__ b3) {
    extern __shared__ char smem[];
    const int OF_AH2 = 0;
    const int OF_AL2 = 18432;
    const int OF_BH2 = 36864;
    const int OF_BL2 = 80640;
    const int OF_YS2 = 124416;
    const int OF_B22 = 125440;
    const int OF_W32 = 126656;
    const int OF_DS2 = 129088;
    uint32_t sbase = smem_u32(smem);
    float* ys  = (float*)(smem + OF_YS2);
    float* b2p = (float*)(smem + OF_B22);
    float* w3p = (float*)(smem + OF_W32);
    float* dsum = (float*)(smem + OF_DS2);

    const int tid = threadIdx.x;
    const int wid = tid >> 5, lane = tid & 31;
    const int wrow = (wid & 7) * 16;
    const int nh = wid >> 3;
    const int g = lane >> 2, tg = lane & 3;

    if (tid < 256) ys[tid] = g_y[blockIdx.x * 256 + tid];
    for (int i = tid; i < 304; i += 512) b2p[i] = (i < 300) ? b2[i] : 0.f;
    for (int i = tid; i < 608; i += 512) w3p[i] = (i < 600) ? w3[i] : 0.f;
    if (tid < 256) dsum[tid] = b3[tid & 1];
    const float al1 = a1p[0];

    const int at = lane >> 3, ar = lane & 7;
    const int arow = wrow + (at & 1) * 8 + ar;
    const int acol = (at >> 1) * 8;
    const int bl = lane & 15;
    const int brow_off = bl & 7;
    const int bcol = (bl >> 3) * 8;

    float c[19][4];
#pragma unroll
    for (int nt = 0; nt < 19; nt++)
#pragma unroll
        for (int q = 0; q < 4; q++) c[nt][q] = 0.f;

    for (int kc = 0; kc < 5; kc++) {
        __syncthreads();
        {
            uint4* dH = (uint4*)(smem + OF_BH2);
            uint4* dL = (uint4*)(smem + OF_BL2);
            const uint4* sH = (const uint4*)g_BH[kc];
            const uint4* sL = (const uint4*)g_BL[kc];
            for (int i = tid; i < 2736; i += 512) { dH[i] = sH[i]; dL[i] = sL[i]; }
        }
        for (int idx = tid; idx < 8192; idx += 512) {
            int p = idx >> 6, kl = idx & 63;
            int kg = kc * 64 + kl;
            float v = 0.f;
            if (kg < 300) {
                v = fmaf(ys[p * 2], w1[kg], fmaf(ys[p * 2 + 1], w1[300 + kg], b1[kg]));
                v = (v >= 0.f) ? v : al1 * v;
            }
            __nv_bfloat16 hi, lo; bf16split(v, hi, lo);
            ((__nv_bfloat16*)(smem + OF_AH2))[p * 72 + kl] = hi;
            ((__nv_bfloat16*)(smem + OF_AL2))[p * 72 + kl] = lo;
        }
        __syncthreads();

#pragma unroll
        for (int kt = 0; kt < 4; kt++) {
            uint32_t ah[4], al4[4];
            uint32_t aoff = (uint32_t)((arow * 72 + kt * 16 + acol) * 2);
            ldsm_x4(ah[0], ah[1], ah[2], ah[3], sbase + OF_AH2 + aoff);
            ldsm_x4(al4[0], al4[1], al4[2], al4[3], sbase + OF_AL2 + aoff);
#pragma unroll
            for (int nt = 0; nt < 19; nt++) {
                int n0 = nh * 152 + nt * 8;
                uint32_t boff = (uint32_t)(((n0 + brow_off) * 72 + kt * 16 + bcol) * 2);
                uint32_t bh[2], bl2[2];
                ldsm_x2(bh[0], bh[1], sbase + OF_BH2 + boff);
                ldsm_x2(bl2[0], bl2[1], sbase + OF_BL2 + boff);
                mma_bf16(c[nt], ah, bh);
                mma_bf16(c[nt], ah, bl2);
                mma_bf16(c[nt], al4, bh);
            }
        }
    }

    {
        const float al2 = a2p[0];
        float d0a = 0.f, d1a = 0.f, d0b = 0.f, d1b = 0.f;
#pragma unroll
        for (int nt = 0; nt < 19; nt++) {
            int n = nh * 152 + nt * 8 + tg * 2;
            float bb0 = b2p[n], bb1 = b2p[n + 1];
            float wa0 = w3p[2 * n + 0], wa1 = w3p[2 * n + 1];
            float wb0 = w3p[2 * n + 2], wb1 = w3p[2 * n + 3];
            float h;
            h = c[nt][0] + bb0; h = (h >= 0.f) ? h : al2 * h;
            d0a = fmaf(h, wa0, d0a); d1a = fmaf(h, wa1, d1a);
            h = c[nt][1] + bb1; h = (h >= 0.f) ? h : al2 * h;
            d0a = fmaf(h, wb0, d0a); d1a = fmaf(h, wb1, d1a);
            h = c[nt][2] + bb0; h = (h >= 0.f) ? h : al2 * h;
            d0b = fmaf(h, wa0, d0b); d1b = fmaf(h, wa1, d1b);
            h = c[nt][3] + bb1; h = (h >= 0.f) ? h : al2 * h;
            d0b = fmaf(h, wb0, d0b); d1b = fmaf(h, wb1, d1b);
        }
        d0a += __shfl_xor_sync(0xffffffffu, d0a, 1); d0a += __shfl_xor_sync(0xffffffffu, d0a, 2);
        d1a += __shfl_xor_sync(0xffffffffu, d1a, 1); d1a += __shfl_xor_sync(0xffffffffu, d1a, 2);
        d0b += __shfl_xor_sync(0xffffffffu, d0b, 1); d0b += __shfl_xor_sync(0xffffffffu, d0b, 2);
        d1b += __shfl_xor_sync(0xffffffffu, d1b, 1); d1b += __shfl_xor_sync(0xffffffffu, d1b, 2);
        if (tg == 0) {
            int r0 = wrow + g, r1 = wrow + g + 8;
            atomicAdd(&dsum[r0 * 2 + 0], d0a); atomicAdd(&dsum[r0 * 2 + 1], d1a);
            atomicAdd(&dsum[r1 * 2 + 0], d0b); atomicAdd(&dsum[r1 * 2 + 1], d1b);
        }
    }
    __syncthreads();

    if (tid < 128) {
        int p = tid, gp = blockIdx.x * 128 + p;
        float d0 = dsum[p * 2 + 0], d1 = dsum[p * 2 + 1];
        float y0 = ys[p * 2 + 0], y1 = ys[p * 2 + 1];
        float lsv = d0 * y0 + d1 * y1;
        float Vy = y0 * y0 + y1 * y1;
        float rl = fmaxf(fmaf(1e-4f, Vy, lsv), 0.f);
        float sc = rl / (Vy + 1e-12f);
        float yd0 = d0 - sc * y0, yd1 = d1 - sc * y1;
        float nrm = sqrtf(yd0 * yd0 + yd1 * yd1);
        float innv = 1.f / fmaxf(nrm, 1e-12f);
        float n0 = yd0 * innv, n1 = yd1 * innv;
        float4 Ji = *reinterpret_cast<const float4*>(g_jinv + gp * 4);
        g_xdh[gp * 2 + 0] = Ji.x * n0 + Ji.y * n1;
        g_xdh[gp * 2 + 1] = Ji.z * n0 + Ji.w * n1;
    }
}

// =================== K3: vel-scalar net + final scaling ====================
__global__ __launch_bounds__(224, 2) void k_vs(
    const float* __restrict__ x,
    const float* __restrict__ w1, const float* __restrict__ b1,
    const float* __restrict__ w2, const float* __restrict__ b2,
    const float* __restrict__ w3, const float* __restrict__ b3,
    float* __restrict__ out) {
    extern __shared__ float sm[];
    float* ws   = sm;
    float* bufA = ws + 10400;
    float* xs   = bufA + 13824;
    float* b2p  = xs + 256;
    ull* w3u    = (ull*)(b2p + 104);
    float* dsum = b2p + 104 + 104;

    const int tid = threadIdx.x;
    const bool active = tid < 208;
    const int rg = tid / 13, og = tid % 13;
    const int row0 = rg * 8, jb = og * 8;
    const int gbase = blockIdx.x * 128;

    for (int i = tid; i < 256; i += 224) xs[i] = x[blockIdx.x * 256 + i];
    for (int i = tid; i < 10400; i += 224) {
        int k = i / 104, j = i % 104;
        ws[i] = (j < 100) ? w2[k * 100 + j] : 0.f;
    }
    if (tid < 104) b2p[tid] = (tid < 100) ? b2[tid] : 0.f;
    if (tid < 52) w3u[tid] = (tid < 50) ? ((const ull*)w3)[tid] : 0ULL;
    if (tid < 128) dsum[tid] = b3[0];
    __syncthreads();

    for (int i = tid; i < 12800; i += 224) {
        int p = i / 100, j = i % 100;
        float v = fmaf(xs[p * 2], w1[j], fmaf(xs[p * 2 + 1], w1[100 + j], b1[j]));
        bufA[p * 108 + j] = (v >= 0.f) ? v : 0.01f * v;
    }
    __syncthreads();

    ull acc[8][4];
#pragma unroll
    for (int r = 0; r < 8; r++)
#pragma unroll
        for (int q = 0; q < 4; q++) acc[r][q] = 0ULL;
    if (active) {
        for (int k = 0; k < 100; k += 4) {
            ulonglong2 wA0 = *(const ulonglong2*)(ws + (k + 0) * 104 + jb);
            ulonglong2 wA1 = *(const ulonglong2*)(ws + (k + 0) * 104 + jb + 4);
            ulonglong2 wB0 = *(const ulonglong2*)(ws + (k + 1) * 104 + jb);
            ulonglong2 wB1 = *(const ulonglong2*)(ws + (k + 1) * 104 + jb + 4);
            ulonglong2 wC0 = *(const ulonglong2*)(ws + (k + 2) * 104 + jb);
            ulonglong2 wC1 = *(const ulonglong2*)(ws + (k + 2) * 104 + jb + 4);
            ulonglong2 wD0 = *(const ulonglong2*)(ws + (k + 3) * 104 + jb);
            ulonglong2 wD1 = *(const ulonglong2*)(ws + (k + 3) * 104 + jb + 4);
#pragma unroll
            for (int r = 0; r < 8; r++) {
                float4 a = *(const float4*)(bufA + (row0 + r) * 108 + k);
                GS2(r, bc2(a.x), wA0, wA1)
                GS2(r, bc2(a.y), wB0, wB1)
                GS2(r, bc2(a.z), wC0, wC1)
                GS2(r, bc2(a.w), wD0, wD1)
            }
        }
#pragma unroll
        for (int r = 0; r < 8; r++) {
            ull dp2 = 0ULL;
#pragma unroll
            for (int q = 0; q < 4; q++) {
                float h0, h1; upk2(acc[r][q], h0, h1);
                int j = jb + 2 * q;
                h0 += b2p[j]; h1 += b2p[j + 1];
                h0 = (h0 >= 0.f) ? h0 : 0.01f * h0;
                h1 = (h1 >= 0.f) ? h1 : 0.01f * h1;
                fma2(dp2, pk2(h0, h1), w3u[j >> 1]);
            }
            float s0, s1; upk2(dp2, s0, s1);
            atomicAdd(&dsum[row0 + r], s0 + s1);
        }
    }
    __syncthreads();

    if (tid < 128) {
        int p = tid, gp = gbase + p;
        float t = dsum[p];
        float x0 = xs[p * 2 + 0], x1 = xs[p * 2 + 1];
        out[gp * 2 + 0] = (expf(t + x0) + 1e-12f) * g_xdh[gp * 2 + 0];
        out[gp * 2 + 1] = (expf(t + x1) + 1e-12f) * g_xdh[gp * 2 + 1];
    }
}

// ============================== launch =====================================
extern "C" void kernel_launch(void* const* d_in, const int* in_sizes, int n_in,
                              void* d_out, int out_size) {
    const float* x     = (const float*)d_in[0];
    const float* t1w1  = (const float*)d_in[1];
    const float* t1b1  = (const float*)d_in[2];
    const float* t1w2  = (const float*)d_in[3];
    const float* t1b2  = (const float*)d_in[4];
    const float* t1w3  = (const float*)d_in[5];
    const float* t1b3  = (const float*)d_in[6];
    const float* t2w1  = (const float*)d_in[7];
    const float* t2b1  = (const float*)d_in[8];
    const float* t2w2  = (const float*)d_in[9];
    const float* t2b2  = (const float*)d_in[10];
    const float* t2w3  = (const float*)d_in[11];
    const float* t2b3  = (const float*)d_in[12];
    const float* vvw1  = (const float*)d_in[13];
    const float* vvb1  = (const float*)d_in[14];
    const float* vva1  = (const float*)d_in[15];
    const float* vvw2  = (const float*)d_in[16];
    const float* vvb2  = (const float*)d_in[17];
    const float* vva2  = (const float*)d_in[18];
    const float* vvw3  = (const float*)d_in[19];
    const float* vvb3  = (const float*)d_in[20];
    const float* vsw1  = (const float*)d_in[21];
    const float* vsb1  = (const float*)d_in[22];
    const float* vsw2  = (const float*)d_in[23];
    const float* vsb2  = (const float*)d_in[24];
    const float* vsw3  = (const float*)d_in[25];
    const float* vsb3  = (const float*)d_in[26];

    const int SM2 = 130112;
    const int SM3 = (10400 + 13824 + 256 + 104 + 104 + 128) * 4;

    cudaFuncSetAttribute(k_taskmap, cudaFuncAttributeMaxDynamicSharedMemorySize, SM1_BYTES);
    cudaFuncSetAttribute(k_vv_mma, cudaFuncAttributeMaxDynamicSharedMemorySize, SM2);
    cudaFuncSetAttribute(k_vs, cudaFuncAttributeMaxDynamicSharedMemorySize, SM3);

    k_origin<<<1, 128>>>(t1w1, t1b1, t1w2, t1b2, t1w3, t1b3,
                         t2w1, t2b1, t2w2, t2b2, t2w3, t2b3);
    k_prep<<<380, 256>>>(vvw2);
    k_prep2<<<138, 256>>>(t1w2, t2w2, t1w1, t2w1, t1w3, t2w3);
    k_taskmap<<<NPTS / 32, 192, SM1_BYTES>>>(x, t1b1, t1b2, t1b3,
                                             t2b1, t2b2, t2b3);
    k_vv_mma<<<NPTS / 128, 512, SM2>>>(vvw1, vvb1, vva1, vvb2, vva2, vvw3, vvb3);
    k_vs<<<NPTS / 128, 224, SM3>>>(x, vsw1, vsb1, vsw2, vsb2, vsw3, vsb3,
                                   (float*)d_out);
}

// round 15
// speedup vs baseline: 2.5680x; 1.1695x over previous
#include <cuda_runtime.h>
#include <cuda_bf16.h>
#include <math.h>
#include <stdint.h>

#define NPTS 131072
typedef unsigned long long ull;

__device__ float g_origin[2];
__device__ float g_y[NPTS * 2];
__device__ float g_jinv[NPTS * 4];
__device__ float g_xdh[NPTS * 2];
// W2^T (vv) bf16 hi/lo, [5 K-chunks][304 x 72]
__device__ __nv_bfloat16 g_BH[5][304 * 72];
__device__ __nv_bfloat16 g_BL[5][304 * 72];
// taskmap weights, bf16 hi/lo, transposed [n][k]:
__device__ __nv_bfloat16 g_TH[2 * 104 * 120];   // mid layers (stride 120)
__device__ __nv_bfloat16 g_TL[2 * 104 * 120];
__device__ __nv_bfloat16 g_T1H[2 * 104 * 24];   // L1 layers (stride 24, k<2)
__device__ __nv_bfloat16 g_T1L[2 * 104 * 24];
__device__ __nv_bfloat16 g_T3H[2 * 8 * 120];    // L3 layers (8 n-rows, stride 120)
__device__ __nv_bfloat16 g_T3L[2 * 8 * 120];

__device__ __forceinline__ float eluf(float v) { return v > 0.f ? v : expm1f(v); }
__device__ __forceinline__ float softplusf(float p) {
    return fmaxf(p, 0.f) + log1pf(expf(-fabsf(p)));
}
__device__ __forceinline__ void bf16split(float v, __nv_bfloat16& hi, __nv_bfloat16& lo) {
    hi = __float2bfloat16(v);
    lo = __float2bfloat16(v - __bfloat162float(hi));
}

// ---- packed f32x2 helpers ----
__device__ __forceinline__ ull pk2(float a, float b) {
    ull r; asm("mov.b64 %0,{%1,%2};" : "=l"(r) : "f"(a), "f"(b)); return r;
}
__device__ __forceinline__ ull bc2(float a) { return pk2(a, a); }
__device__ __forceinline__ void upk2(ull v, float& a, float& b) {
    asm("mov.b64 {%0,%1},%2;" : "=f"(a), "=f"(b) : "l"(v));
}
__device__ __forceinline__ void fma2(ull& d, ull a, ull b) {
    asm("fma.rn.f32x2 %0, %1, %2, %0;" : "+l"(d) : "l"(a), "l"(b));
}
#define GS2(r, AB, U0, U1)            \
    fma2(acc[r][0], AB, U0.x);        \
    fma2(acc[r][1], AB, U0.y);        \
    fma2(acc[r][2], AB, U1.x);        \
    fma2(acc[r][3], AB, U1.y);

__device__ __forceinline__ uint32_t smem_u32(const void* p) {
    uint32_t a;
    asm("{ .reg .u64 t; cvta.to.shared.u64 t, %1; cvt.u32.u64 %0, t; }" : "=r"(a) : "l"(p));
    return a;
}
// ---- HMMA helpers ----
__device__ __forceinline__ void ldsm_x4(uint32_t& r0, uint32_t& r1, uint32_t& r2, uint32_t& r3,
                                        uint32_t addr) {
    asm volatile("ldmatrix.sync.aligned.m8n8.x4.shared.b16 {%0,%1,%2,%3}, [%4];"
                 : "=r"(r0), "=r"(r1), "=r"(r2), "=r"(r3) : "r"(addr));
}
__device__ __forceinline__ void ldsm_x2(uint32_t& r0, uint32_t& r1, uint32_t addr) {
    asm volatile("ldmatrix.sync.aligned.m8n8.x2.shared.b16 {%0,%1}, [%2];"
                 : "=r"(r0), "=r"(r1) : "r"(addr));
}
__device__ __forceinline__ void mma_bf16(float* c, const uint32_t* a, const uint32_t* b) {
    asm volatile(
        "mma.sync.aligned.m16n8k16.row.col.f32.bf16.bf16.f32 "
        "{%0,%1,%2,%3}, {%4,%5,%6,%7}, {%8,%9}, {%0,%1,%2,%3};"
        : "+f"(c[0]), "+f"(c[1]), "+f"(c[2]), "+f"(c[3])
        : "r"(a[0]), "r"(a[1]), "r"(a[2]), "r"(a[3]), "r"(b[0]), "r"(b[1]));
}

// ========================= K0: origin = taskmap(0) =========================
__global__ void k_origin(const float* __restrict__ w1, const float* __restrict__ b1,
                         const float* __restrict__ w2, const float* __restrict__ b2,
                         const float* __restrict__ w3, const float* __restrict__ b3,
                         const float* __restrict__ w4, const float* __restrict__ b4,
                         const float* __restrict__ w5, const float* __restrict__ b5,
                         const float* __restrict__ w6, const float* __restrict__ b6) {
    __shared__ float h[100], h2[100], y1s[2];
    int j = threadIdx.x;
    if (j < 100) h[j] = tanhf(b1[j]);
    __syncthreads();
    if (j < 100) {
        float a = b2[j];
        for (int k = 0; k < 100; k++) a = fmaf(h[k], w2[k * 100 + j], a);
        h2[j] = tanhf(a);
    }
    __syncthreads();
    if (j < 2) {
        float a = b3[j];
        for (int k = 0; k < 100; k++) a = fmaf(h2[k], w3[k * 2 + j], a);
        y1s[j] = a;
    }
    __syncthreads();
    if (j < 100) {
        float a = fmaf(y1s[0], w4[j], fmaf(y1s[1], w4[100 + j], b4[j]));
        h[j] = eluf(a);
    }
    __syncthreads();
    if (j < 100) {
        float a = b5[j];
        for (int k = 0; k < 100; k++) a = fmaf(h[k], w5[k * 100 + j], a);
        h2[j] = eluf(a);
    }
    __syncthreads();
    if (j < 2) {
        float a = b6[j];
        for (int k = 0; k < 100; k++) a = fmaf(h2[k], w6[k * 2 + j], a);
        float s = softplusf(a);
        g_origin[j] = (1.f + s) * y1s[j];
    }
}

// ====== prep: W2 (vv) -> [n][k] bf16 hi/lo ======
__global__ void k_prep(const float* __restrict__ w2) {
    int i = blockIdx.x * blockDim.x + threadIdx.x;
    if (i >= 5 * 304 * 64) return;
    int kc = i / (304 * 64);
    int r = i % (304 * 64);
    int n = r / 64, kl = r % 64;
    int kg = kc * 64 + kl;
    float v = (kg < 300 && n < 300) ? w2[kg * 300 + n] : 0.f;
    __nv_bfloat16 hi, lo; bf16split(v, hi, lo);
    g_BH[kc][n * 72 + kl] = hi;
    g_BL[kc][n * 72 + kl] = lo;
}
// ====== prep2: taskmap L1/L2/L3 weights -> transposed bf16 hi/lo ======
__global__ void k_prep2(const float* __restrict__ w2, const float* __restrict__ w5,
                        const float* __restrict__ w1, const float* __restrict__ w4,
                        const float* __restrict__ w3, const float* __restrict__ w6) {
    int i = blockIdx.x * blockDim.x + threadIdx.x;
    if (i < 24960) {                        // mid: 2 x 104 x 120
        int l = i / 12480, r = i % 12480, n = r / 120, k = r % 120;
        const float* W = l ? w5 : w2;
        float v = (n < 100 && k < 100) ? W[k * 100 + n] : 0.f;
        __nv_bfloat16 hi, lo; bf16split(v, hi, lo);
        g_TH[l * 12480 + n * 120 + k] = hi;
        g_TL[l * 12480 + n * 120 + k] = lo;
    } else if (i < 24960 + 4992) {          // L1: 2 x 104 x 24
        int j = i - 24960;
        int l = j / 2496, r = j % 2496, n = r / 24, k = r % 24;
        const float* W = l ? w4 : w1;
        float v = (n < 100 && k < 2) ? W[k * 100 + n] : 0.f;
        __nv_bfloat16 hi, lo; bf16split(v, hi, lo);
        g_T1H[l * 2496 + n * 24 + k] = hi;
        g_T1L[l * 2496 + n * 24 + k] = lo;
    } else if (i < 24960 + 4992 + 1920) {   // L3: 2 x 8 x 120
        int j = i - 29952;
        int l = j / 960, r = j % 960, n = r / 120, k = r % 120;
        const float* W = l ? w6 : w3;
        float v = (n < 2 && k < 100) ? W[k * 2 + n] : 0.f;
        __nv_bfloat16 hi, lo; bf16split(v, hi, lo);
        g_T3H[l * 960 + n * 120 + k] = hi;
        g_T3L[l * 960 + n * 120 + k] = lo;
    }
}

// ========================= K1: taskmap + Jacobian (all-HMMA, 3 CTA/SM) =====
// 32 pts/block, 96 rows (32 value + 64 tangent), 192 threads = 6 warps.
// Mid-layer W staged in 3 K-chunks (48/48/24 cols) through a 23 KB buffer.
#define OF_AH 0
#define OF_AL 23040
#define OF_WH 46080
#define OF_WL 57728
#define OF_SS  69376
#define OF_SG  69632
#define OF_ACC 69888
#define OF_JS  71424
#define OF_XS  71936
#define OF_V2  72192
#define OF_BP  72960
#define SM1_BYTES 73376

// value epilogue (warps 0-1) + tangent epilogue (warps 2-5); tangent warps
// recompute act'(h) from hi+lo bf16 of h (no hbuf).
template <int ACT>
__device__ __forceinline__ void epilogue(char* smem, const float* c /*13*4*/) {
    const int tid = threadIdx.x;
    const int wid = tid >> 5, lane = tid & 31;
    const int g = lane >> 2, tg = lane & 3;
    float* bp = (float*)(smem + OF_BP);
    __nv_bfloat16* AHp = (__nv_bfloat16*)(smem + OF_AH);
    __nv_bfloat16* ALp = (__nv_bfloat16*)(smem + OF_AL);
    const int mrow = wid * 16;
    if (wid < 2) {
        int r0 = mrow + g, r1 = mrow + g + 8;
#pragma unroll
        for (int nt = 0; nt < 13; nt++) {
#pragma unroll
            for (int q = 0; q < 4; q++) {
                int row = (q < 2) ? r0 : r1;
                int col = nt * 8 + tg * 2 + (q & 1);
                float h = c[nt * 4 + q] + bp[col];
                h = (ACT == 0) ? tanhf(h) : eluf(h);
                __nv_bfloat16 hi, lo; bf16split(h, hi, lo);
                AHp[row * 120 + col] = hi;
                ALp[row * 120 + col] = lo;
            }
        }
    }
    __syncthreads();
    if (wid >= 2) {
        int r0 = mrow + g, r1 = mrow + g + 8;
#pragma unroll
        for (int nt = 0; nt < 13; nt++) {
#pragma unroll
            for (int q = 0; q < 4; q++) {
                int row = (q < 2) ? r0 : r1;
                int col = nt * 8 + tg * 2 + (q & 1);
                int vr = row & 31;
                float h = __bfloat162float(AHp[vr * 120 + col]) +
                          __bfloat162float(ALp[vr * 120 + col]);
                float d = (ACT == 0) ? (1.f - h * h) : (h > 0.f ? 1.f : h + 1.f);
                float v = c[nt * 4 + q] * d;
                __nv_bfloat16 hi, lo; bf16split(v, hi, lo);
                AHp[row * 120 + col] = hi;
                ALp[row * 120 + col] = lo;
            }
        }
    }
    __syncthreads();
}

// L1 layer (2->100): K=16 (1 kt), W staged stride 24.
template <int ACT>
__device__ __forceinline__ void mma_l1(char* smem, uint32_t sbase,
                                       const float* __restrict__ bvec,
                                       const uint4* srcH, const uint4* srcL) {
    const int tid = threadIdx.x;
    const int wid = tid >> 5, lane = tid & 31;
    float* bp = (float*)(smem + OF_BP);
    __syncthreads();   // W buffer free
    {
        uint4* dH = (uint4*)(smem + OF_WH);
        uint4* dL = (uint4*)(smem + OF_WL);
        for (int i = tid; i < 312; i += 192) { dH[i] = srcH[i]; dL[i] = srcL[i]; }
        if (tid < 104) bp[tid] = (tid < 100) ? bvec[tid] : 0.f;
    }
    __syncthreads();

    const int mrow = wid * 16;
    const int at = lane >> 3, ar = lane & 7;
    const int arow = mrow + (at & 1) * 8 + ar;
    const int acol = (at >> 1) * 8;
    const int blx = lane & 15;
    const int brow = blx & 7;
    const int bcol = (blx >> 3) * 8;

    float c[13 * 4];
#pragma unroll
    for (int q = 0; q < 52; q++) c[q] = 0.f;
    uint32_t ah[4], al4[4];
    uint32_t aoff = (uint32_t)((arow * 120 + acol) * 2);
    ldsm_x4(ah[0], ah[1], ah[2], ah[3], sbase + OF_AH + aoff);
    ldsm_x4(al4[0], al4[1], al4[2], al4[3], sbase + OF_AL + aoff);
#pragma unroll
    for (int nt = 0; nt < 13; nt++) {
        uint32_t boff = (uint32_t)(((nt * 8 + brow) * 24 + bcol) * 2);
        uint32_t bh[2], bl2[2];
        ldsm_x2(bh[0], bh[1], sbase + OF_WH + boff);
        ldsm_x2(bl2[0], bl2[1], sbase + OF_WL + boff);
        mma_bf16(c + nt * 4, ah, bh);
        mma_bf16(c + nt * 4, ah, bl2);
        mma_bf16(c + nt * 4, al4, bh);
    }
    __syncthreads();   // A reads done before rewrite
    epilogue<ACT>(smem, c);
}

// Mid layer (100x100): K=112 in 3 W-chunks (kt 0-2, 3-5, 6), W stride 56.
template <int ACT>
__device__ __forceinline__ void mma_mid(char* smem, uint32_t sbase,
                                        const float* __restrict__ bvec,
                                        const uint4* srcH, const uint4* srcL) {
    const int tid = threadIdx.x;
    const int wid = tid >> 5, lane = tid & 31;
    float* bp = (float*)(smem + OF_BP);
    if (tid < 104) bp[tid] = (tid < 100) ? bvec[tid] : 0.f;

    const int mrow = wid * 16;
    const int at = lane >> 3, ar = lane & 7;
    const int arow = mrow + (at & 1) * 8 + ar;
    const int acol = (at >> 1) * 8;
    const int blx = lane & 15;
    const int brow = blx & 7;
    const int bcol = (blx >> 3) * 8;

    float c[13 * 4];
#pragma unroll
    for (int q = 0; q < 52; q++) c[q] = 0.f;

#pragma unroll
    for (int ch = 0; ch < 3; ch++) {
        __syncthreads();   // W buffer free
        {
            uint4* dH = (uint4*)(smem + OF_WH);
            uint4* dL = (uint4*)(smem + OF_WL);
            if (ch < 2) {
                for (int i = tid; i < 624; i += 192) {
                    int n = i / 6, u = i % 6;
                    dH[n * 7 + u] = srcH[n * 15 + 6 * ch + u];
                    dL[n * 7 + u] = srcL[n * 15 + 6 * ch + u];
                }
            } else {
                for (int i = tid; i < 312; i += 192) {
                    int n = i / 3, u = i % 3;
                    dH[n * 7 + u] = srcH[n * 15 + 12 + u];
                    dL[n * 7 + u] = srcL[n * 15 + 12 + u];
                }
            }
        }
        __syncthreads();
        const int nkt = (ch < 2) ? 3 : 1;
        for (int ktl = 0; ktl < nkt; ktl++) {
            int ktg = ch * 3 + ktl;
            uint32_t ah[4], al4[4];
            uint32_t aoff = (uint32_t)((arow * 120 + ktg * 16 + acol) * 2);
            ldsm_x4(ah[0], ah[1], ah[2], ah[3], sbase + OF_AH + aoff);
            ldsm_x4(al4[0], al4[1], al4[2], al4[3], sbase + OF_AL + aoff);
#pragma unroll
            for (int nt = 0; nt < 13; nt++) {
                uint32_t boff = (uint32_t)(((nt * 8 + brow) * 56 + ktl * 16 + bcol) * 2);
                uint32_t bh[2], bl2[2];
                ldsm_x2(bh[0], bh[1], sbase + OF_WH + boff);
                ldsm_x2(bl2[0], bl2[1], sbase + OF_WL + boff);
                mma_bf16(c + nt * 4, ah, bh);
                mma_bf16(c + nt * 4, ah, bl2);
                mma_bf16(c + nt * 4, al4, bh);
            }
        }
    }
    __syncthreads();   // A/W reads done
    epilogue<ACT>(smem, c);
}

// L3 tail: stage 8x120 B hi/lo into WH/WL, N-tile 0 only, K=112.
__device__ __forceinline__ void mma_tail_frag(char* smem, uint32_t sbase,
                                              const uint4* srcH, const uint4* srcL,
                                              float* c3) {
    const int tid = threadIdx.x;
    const int wid = tid >> 5, lane = tid & 31;
    __syncthreads();   // W buffer free
    {
        uint4* dH = (uint4*)(smem + OF_WH);
        uint4* dL = (uint4*)(smem + OF_WL);
        for (int i = tid; i < 120; i += 192) { dH[i] = srcH[i]; dL[i] = srcL[i]; }
    }
    __syncthreads();
    const int mrow = wid * 16;
    const int at = lane >> 3, ar = lane & 7;
    const int arow = mrow + (at & 1) * 8 + ar;
    const int acol = (at >> 1) * 8;
    const int blx = lane & 15;
    const int brow = blx & 7;
    const int bcol = (blx >> 3) * 8;
    c3[0] = c3[1] = c3[2] = c3[3] = 0.f;
#pragma unroll
    for (int kt = 0; kt < 7; kt++) {
        uint32_t ah[4], al4[4];
        uint32_t aoff = (uint32_t)((arow * 120 + kt * 16 + acol) * 2);
        ldsm_x4(ah[0], ah[1], ah[2], ah[3], sbase + OF_AH + aoff);
        ldsm_x4(al4[0], al4[1], al4[2], al4[3], sbase + OF_AL + aoff);
        uint32_t boff = (uint32_t)((brow * 120 + kt * 16 + bcol) * 2);
        uint32_t bh[2], bl2[2];
        ldsm_x2(bh[0], bh[1], sbase + OF_WH + boff);
        ldsm_x2(bl2[0], bl2[1], sbase + OF_WL + boff);
        mma_bf16(c3, ah, bh);
        mma_bf16(c3, ah, bl2);
        mma_bf16(c3, al4, bh);
    }
}

__global__ __launch_bounds__(192, 3) void k_taskmap(
    const float* __restrict__ x,
    const float* __restrict__ b1, const float* __restrict__ b2, const float* __restrict__ b3,
    const float* __restrict__ b4, const float* __restrict__ b5, const float* __restrict__ b6) {
    extern __shared__ char smem[];
    uint32_t sbase = smem_u32(smem);
    __nv_bfloat16* AHp = (__nv_bfloat16*)(smem + OF_AH);
    __nv_bfloat16* ALp = (__nv_bfloat16*)(smem + OF_AL);
    float* xs   = (float*)(smem + OF_XS);
    float* v2   = (float*)(smem + OF_V2);
    float* ss   = (float*)(smem + OF_SS);
    float* sg   = (float*)(smem + OF_SG);
    float* Jsh  = (float*)(smem + OF_JS);
    float* accb = (float*)(smem + OF_ACC);

    const int tid = threadIdx.x;
    const int wid = tid >> 5, lane = tid & 31;
    const int g = lane >> 2, tg = lane & 3;
    const int gbase = blockIdx.x * 32;

    if (tid < 64) xs[tid] = x[blockIdx.x * 64 + tid];
    // zero A pad cols 100..119 (persist across layers)
    for (int i = tid; i < 1920; i += 192) {
        int row = i / 20, col = 100 + i % 20;
        AHp[row * 120 + col] = __float2bfloat16(0.f);
        ALp[row * 120 + col] = __float2bfloat16(0.f);
    }
    __syncthreads();

    // ---- build A for tm1 L1: value rows = [x0,x1,0..], tangent rows = e_c ----
    for (int i = tid; i < 1536; i += 192) {
        int row = i >> 4, col = i & 15;
        float v;
        if (row < 32) v = (col < 2) ? xs[row * 2 + col] : 0.f;
        else v = (col == ((row - 32) >> 5)) ? 1.f : 0.f;
        __nv_bfloat16 hi, lo; bf16split(v, hi, lo);
        AHp[row * 120 + col] = hi;
        ALp[row * 120 + col] = lo;
    }

    // ---- tm1 L1 (2->100, tanh) ----
    mma_l1<0>(smem, sbase, b1, (const uint4*)g_T1H, (const uint4*)g_T1L);
    // ---- tm1 L2 (100x100, tanh) ----
    mma_mid<0>(smem, sbase, b2, (const uint4*)g_TH, (const uint4*)g_TL);

    // ---- tm1 L3 (100->2) + residual / identity ----
    {
        float c3[4];
        mma_tail_frag(smem, sbase, (const uint4*)g_T3H, (const uint4*)g_T3L, c3);
        if (tg == 0) {
            float b30 = b3[0], b31 = b3[1];
#pragma unroll
            for (int hh = 0; hh < 2; hh++) {
                int r = wid * 16 + g + hh * 8;
                float cv0 = c3[hh * 2 + 0], cv1 = c3[hh * 2 + 1];
                if (r < 32) {
                    v2[r * 2 + 0] = cv0 + b30 + xs[r * 2 + 0];
                    v2[r * 2 + 1] = cv1 + b31 + xs[r * 2 + 1];
                } else {
                    int cmp = (r >> 5) - 1;
                    v2[r * 2 + 0] = cv0 + (cmp == 0 ? 1.f : 0.f);
                    v2[r * 2 + 1] = cv1 + (cmp == 1 ? 1.f : 0.f);
                }
            }
        }
        __syncthreads();
    }

    // ---- build A for tm2 L1: all rows = [v2_0, v2_1, 0..] ----
    for (int i = tid; i < 1536; i += 192) {
        int row = i >> 4, col = i & 15;
        float v = (col < 2) ? v2[row * 2 + col] : 0.f;
        __nv_bfloat16 hi, lo; bf16split(v, hi, lo);
        AHp[row * 120 + col] = hi;
        ALp[row * 120 + col] = lo;
    }

    // ---- tm2 L1 (2->100, elu) ----
    mma_l1<1>(smem, sbase, b4,
              (const uint4*)(g_T1H + 2496), (const uint4*)(g_T1L + 2496));
    // ---- tm2 L2 (100x100, elu) ----
    mma_mid<1>(smem, sbase, b5,
               (const uint4*)(g_TH + 12480), (const uint4*)(g_TL + 12480));

    // ---- tm2 L3 (100->2): softplus gate + y / J accumulation ----
    {
        float c3[4];
        mma_tail_frag(smem, sbase, (const uint4*)(g_T3H + 960), (const uint4*)(g_T3L + 960), c3);
        if (tg == 0) {
            float b60 = b6[0], b61 = b6[1];
#pragma unroll
            for (int hh = 0; hh < 2; hh++) {
                int r = wid * 16 + g + hh * 8;
                float cv0 = c3[hh * 2 + 0], cv1 = c3[hh * 2 + 1];
                if (r < 32) {
                    float pv0 = cv0 + b60, pv1 = cv1 + b61;
                    float s0 = softplusf(pv0), s1 = softplusf(pv1);
                    ss[r * 2 + 0] = s0; ss[r * 2 + 1] = s1;
                    sg[r * 2 + 0] = 1.f / (1.f + expf(-pv0));
                    sg[r * 2 + 1] = 1.f / (1.f + expf(-pv1));
                    g_y[(gbase + r) * 2 + 0] = (1.f + s0) * v2[r * 2 + 0] - g_origin[0];
                    g_y[(gbase + r) * 2 + 1] = (1.f + s1) * v2[r * 2 + 1] - g_origin[1];
                } else {
                    accb[r * 2 + 0] = cv0;
                    accb[r * 2 + 1] = cv1;
                }
            }
        }
        __syncthreads();
    }

    // ---- J assembly + 2x2 pinv ----
    if (tid < 128) {
        int r = 32 + (tid >> 1), i = tid & 1;
        int c = (r >> 5) - 1, p = r & 31;
        float acc = accb[r * 2 + i];
        float s = ss[p * 2 + i];
        float ds = sg[p * 2 + i] * acc;
        Jsh[p * 4 + i * 2 + c] = fmaf(ds, v2[p * 2 + i], (1.f + s) * v2[r * 2 + i]);
    }
    __syncthreads();
    if (tid < 32) {
        int p = tid, gp = gbase + p;
        float a = Jsh[p * 4 + 0], b_ = Jsh[p * 4 + 1];
        float c = Jsh[p * 4 + 2], d = Jsh[p * 4 + 3];
        float det = a * d - b_ * c;
        float n2 = a * a + b_ * b_ + c * c + d * d;
        float ia, ib, ic, id;
        if (fabsf(det) > 1e-10f * n2) {
            float inv = 1.f / det;
            ia = d * inv; ib = -b_ * inv; ic = -c * inv; id = a * inv;
        } else {
            float inv = (n2 > 0.f) ? 1.f / n2 : 0.f;
            ia = a * inv; ib = c * inv; ic = b_ * inv; id = d * inv;
        }
        float4 o; o.x = ia; o.y = ib; o.z = ic; o.w = id;
        *reinterpret_cast<float4*>(g_jinv + gp * 4) = o;
    }
}

// ============ K2 (HMMA): vv net via bf16-split mma.sync ====================
__global__ __launch_bounds__(512, 1) void k_vv_mma(
    const float* __restrict__ w1, const float* __restrict__ b1, const float* __restrict__ a1p,
    const float* __restrict__ b2, const float* __restrict__ a2p,
    const float* __restrict__ w3, const float* __restrict__ b3) {
    extern __shared__ char smem[];
    const int OF_AH2 = 0;
    const int OF_AL2 = 18432;
    const int OF_BH2 = 36864;
    const int OF_BL2 = 80640;
    const int OF_YS2 = 124416;
    const int OF_B22 = 125440;
    const int OF_W32 = 126656;
    const int OF_DS2 = 129088;
    uint32_t sbase = smem_u32(smem);
    float* ys  = (float*)(smem + OF_YS2);
    float* b2p = (float*)(smem + OF_B22);
    float* w3p = (float*)(smem + OF_W32);
    float* dsum = (float*)(smem + OF_DS2);

    const int tid = threadIdx.x;
    const int wid = tid >> 5, lane = tid & 31;
    const int wrow = (wid & 7) * 16;
    const int nh = wid >> 3;
    const int g = lane >> 2, tg = lane & 3;

    if (tid < 256) ys[tid] = g_y[blockIdx.x * 256 + tid];
    for (int i = tid; i < 304; i += 512) b2p[i] = (i < 300) ? b2[i] : 0.f;
    for (int i = tid; i < 608; i += 512) w3p[i] = (i < 600) ? w3[i] : 0.f;
    if (tid < 256) dsum[tid] = b3[tid & 1];
    const float al1 = a1p[0];

    const int at = lane >> 3, ar = lane & 7;
    const int arow = wrow + (at & 1) * 8 + ar;
    const int acol = (at >> 1) * 8;
    const int bl = lane & 15;
    const int brow_off = bl & 7;
    const int bcol = (bl >> 3) * 8;

    float c[19][4];
#pragma unroll
    for (int nt = 0; nt < 19; nt++)
#pragma unroll
        for (int q = 0; q < 4; q++) c[nt][q] = 0.f;

    for (int kc = 0; kc < 5; kc++) {
        __syncthreads();
        {
            uint4* dH = (uint4*)(smem + OF_BH2);
            uint4* dL = (uint4*)(smem + OF_BL2);
            const uint4* sH = (const uint4*)g_BH[kc];
            const uint4* sL = (const uint4*)g_BL[kc];
            for (int i = tid; i < 2736; i += 512) { dH[i] = sH[i]; dL[i] = sL[i]; }
        }
        for (int idx = tid; idx < 8192; idx += 512) {
            int p = idx >> 6, kl = idx & 63;
            int kg = kc * 64 + kl;
            float v = 0.f;
            if (kg < 300) {
                v = fmaf(ys[p * 2], w1[kg], fmaf(ys[p * 2 + 1], w1[300 + kg], b1[kg]));
                v = (v >= 0.f) ? v : al1 * v;
            }
            __nv_bfloat16 hi, lo; bf16split(v, hi, lo);
            ((__nv_bfloat16*)(smem + OF_AH2))[p * 72 + kl] = hi;
            ((__nv_bfloat16*)(smem + OF_AL2))[p * 72 + kl] = lo;
        }
        __syncthreads();

#pragma unroll
        for (int kt = 0; kt < 4; kt++) {
            uint32_t ah[4], al4[4];
            uint32_t aoff = (uint32_t)((arow * 72 + kt * 16 + acol) * 2);
            ldsm_x4(ah[0], ah[1], ah[2], ah[3], sbase + OF_AH2 + aoff);
            ldsm_x4(al4[0], al4[1], al4[2], al4[3], sbase + OF_AL2 + aoff);
#pragma unroll
            for (int nt = 0; nt < 19; nt++) {
                int n0 = nh * 152 + nt * 8;
                uint32_t boff = (uint32_t)(((n0 + brow_off) * 72 + kt * 16 + bcol) * 2);
                uint32_t bh[2], bl2[2];
                ldsm_x2(bh[0], bh[1], sbase + OF_BH2 + boff);
                ldsm_x2(bl2[0], bl2[1], sbase + OF_BL2 + boff);
                mma_bf16(c[nt], ah, bh);
                mma_bf16(c[nt], ah, bl2);
                mma_bf16(c[nt], al4, bh);
            }
        }
    }

    {
        const float al2 = a2p[0];
        float d0a = 0.f, d1a = 0.f, d0b = 0.f, d1b = 0.f;
#pragma unroll
        for (int nt = 0; nt < 19; nt++) {
            int n = nh * 152 + nt * 8 + tg * 2;
            float bb0 = b2p[n], bb1 = b2p[n + 1];
            float wa0 = w3p[2 * n + 0], wa1 = w3p[2 * n + 1];
            float wb0 = w3p[2 * n + 2], wb1 = w3p[2 * n + 3];
            float h;
            h = c[nt][0] + bb0; h = (h >= 0.f) ? h : al2 * h;
            d0a = fmaf(h, wa0, d0a); d1a = fmaf(h, wa1, d1a);
            h = c[nt][1] + bb1; h = (h >= 0.f) ? h : al2 * h;
            d0a = fmaf(h, wb0, d0a); d1a = fmaf(h, wb1, d1a);
            h = c[nt][2] + bb0; h = (h >= 0.f) ? h : al2 * h;
            d0b = fmaf(h, wa0, d0b); d1b = fmaf(h, wa1, d1b);
            h = c[nt][3] + bb1; h = (h >= 0.f) ? h : al2 * h;
            d0b = fmaf(h, wb0, d0b); d1b = fmaf(h, wb1, d1b);
        }
        d0a += __shfl_xor_sync(0xffffffffu, d0a, 1); d0a += __shfl_xor_sync(0xffffffffu, d0a, 2);
        d1a += __shfl_xor_sync(0xffffffffu, d1a, 1); d1a += __shfl_xor_sync(0xffffffffu, d1a, 2);
        d0b += __shfl_xor_sync(0xffffffffu, d0b, 1); d0b += __shfl_xor_sync(0xffffffffu, d0b, 2);
        d1b += __shfl_xor_sync(0xffffffffu, d1b, 1); d1b += __shfl_xor_sync(0xffffffffu, d1b, 2);
        if (tg == 0) {
            int r0 = wrow + g, r1 = wrow + g + 8;
            atomicAdd(&dsum[r0 * 2 + 0], d0a); atomicAdd(&dsum[r0 * 2 + 1], d1a);
            atomicAdd(&dsum[r1 * 2 + 0], d0b); atomicAdd(&dsum[r1 * 2 + 1], d1b);
        }
    }
    __syncthreads();

    if (tid < 128) {
        int p = tid, gp = blockIdx.x * 128 + p;
        float d0 = dsum[p * 2 + 0], d1 = dsum[p * 2 + 1];
        float y0 = ys[p * 2 + 0], y1 = ys[p * 2 + 1];
        float lsv = d0 * y0 + d1 * y1;
        float Vy = y0 * y0 + y1 * y1;
        float rl = fmaxf(fmaf(1e-4f, Vy, lsv), 0.f);
        float sc = rl / (Vy + 1e-12f);
        float yd0 = d0 - sc * y0, yd1 = d1 - sc * y1;
        float nrm = sqrtf(yd0 * yd0 + yd1 * yd1);
        float innv = 1.f / fmaxf(nrm, 1e-12f);
        float n0 = yd0 * innv, n1 = yd1 * innv;
        float4 Ji = *reinterpret_cast<const float4*>(g_jinv + gp * 4);
        g_xdh[gp * 2 + 0] = Ji.x * n0 + Ji.y * n1;
        g_xdh[gp * 2 + 1] = Ji.z * n0 + Ji.w * n1;
    }
}

// =================== K3: vel-scalar net + final scaling ====================
__global__ __launch_bounds__(224, 2) void k_vs(
    const float* __restrict__ x,
    const float* __restrict__ w1, const float* __restrict__ b1,
    const float* __restrict__ w2, const float* __restrict__ b2,
    const float* __restrict__ w3, const float* __restrict__ b3,
    float* __restrict__ out) {
    extern __shared__ float sm[];
    float* ws   = sm;
    float* bufA = ws + 10400;
    float* xs   = bufA + 13824;
    float* b2p  = xs + 256;
    ull* w3u    = (ull*)(b2p + 104);
    float* dsum = b2p + 104 + 104;

    const int tid = threadIdx.x;
    const bool active = tid < 208;
    const int rg = tid / 13, og = tid % 13;
    const int row0 = rg * 8, jb = og * 8;
    const int gbase = blockIdx.x * 128;

    for (int i = tid; i < 256; i += 224) xs[i] = x[blockIdx.x * 256 + i];
    for (int i = tid; i < 10400; i += 224) {
        int k = i / 104, j = i % 104;
        ws[i] = (j < 100) ? w2[k * 100 + j] : 0.f;
    }
    if (tid < 104) b2p[tid] = (tid < 100) ? b2[tid] : 0.f;
    if (tid < 52) w3u[tid] = (tid < 50) ? ((const ull*)w3)[tid] : 0ULL;
    if (tid < 128) dsum[tid] = b3[0];
    __syncthreads();

    for (int i = tid; i < 12800; i += 224) {
        int p = i / 100, j = i % 100;
        float v = fmaf(xs[p * 2], w1[j], fmaf(xs[p * 2 + 1], w1[100 + j], b1[j]));
        bufA[p * 108 + j] = (v >= 0.f) ? v : 0.01f * v;
    }
    __syncthreads();

    ull acc[8][4];
#pragma unroll
    for (int r = 0; r < 8; r++)
#pragma unroll
        for (int q = 0; q < 4; q++) acc[r][q] = 0ULL;
    if (active) {
        for (int k = 0; k < 100; k += 4) {
            ulonglong2 wA0 = *(const ulonglong2*)(ws + (k + 0) * 104 + jb);
            ulonglong2 wA1 = *(const ulonglong2*)(ws + (k + 0) * 104 + jb + 4);
            ulonglong2 wB0 = *(const ulonglong2*)(ws + (k + 1) * 104 + jb);
            ulonglong2 wB1 = *(const ulonglong2*)(ws + (k + 1) * 104 + jb + 4);
            ulonglong2 wC0 = *(const ulonglong2*)(ws + (k + 2) * 104 + jb);
            ulonglong2 wC1 = *(const ulonglong2*)(ws + (k + 2) * 104 + jb + 4);
            ulonglong2 wD0 = *(const ulonglong2*)(ws + (k + 3) * 104 + jb);
            ulonglong2 wD1 = *(const ulonglong2*)(ws + (k + 3) * 104 + jb + 4);
#pragma unroll
            for (int r = 0; r < 8; r++) {
                float4 a = *(const float4*)(bufA + (row0 + r) * 108 + k);
                GS2(r, bc2(a.x), wA0, wA1)
                GS2(r, bc2(a.y), wB0, wB1)
                GS2(r, bc2(a.z), wC0, wC1)
                GS2(r, bc2(a.w), wD0, wD1)
            }
        }
#pragma unroll
        for (int r = 0; r < 8; r++) {
            ull dp2 = 0ULL;
#pragma unroll
            for (int q = 0; q < 4; q++) {
                float h0, h1; upk2(acc[r][q], h0, h1);
                int j = jb + 2 * q;
                h0 += b2p[j]; h1 += b2p[j + 1];
                h0 = (h0 >= 0.f) ? h0 : 0.01f * h0;
                h1 = (h1 >= 0.f) ? h1 : 0.01f * h1;
                fma2(dp2, pk2(h0, h1), w3u[j >> 1]);
            }
            float s0, s1; upk2(dp2, s0, s1);
            atomicAdd(&dsum[row0 + r], s0 + s1);
        }
    }
    __syncthreads();

    if (tid < 128) {
        int p = tid, gp = gbase + p;
        float t = dsum[p];
        float x0 = xs[p * 2 + 0], x1 = xs[p * 2 + 1];
        out[gp * 2 + 0] = (expf(t + x0) + 1e-12f) * g_xdh[gp * 2 + 0];
        out[gp * 2 + 1] = (expf(t + x1) + 1e-12f) * g_xdh[gp * 2 + 1];
    }
}

// ============================== launch =====================================
extern "C" void kernel_launch(void* const* d_in, const int* in_sizes, int n_in,
                              void* d_out, int out_size) {
    const float* x     = (const float*)d_in[0];
    const float* t1w1  = (const float*)d_in[1];
    const float* t1b1  = (const float*)d_in[2];
    const float* t1w2  = (const float*)d_in[3];
    const float* t1b2  = (const float*)d_in[4];
    const float* t1w3  = (const float*)d_in[5];
    const float* t1b3  = (const float*)d_in[6];
    const float* t2w1  = (const float*)d_in[7];
    const float* t2b1  = (const float*)d_in[8];
    const float* t2w2  = (const float*)d_in[9];
    const float* t2b2  = (const float*)d_in[10];
    const float* t2w3  = (const float*)d_in[11];
    const float* t2b3  = (const float*)d_in[12];
    const float* vvw1  = (const float*)d_in[13];
    const float* vvb1  = (const float*)d_in[14];
    const float* vva1  = (const float*)d_in[15];
    const float* vvw2  = (const float*)d_in[16];
    const float* vvb2  = (const float*)d_in[17];
    const float* vva2  = (const float*)d_in[18];
    const float* vvw3  = (const float*)d_in[19];
    const float* vvb3  = (const float*)d_in[20];
    const float* vsw1  = (const float*)d_in[21];
    const float* vsb1  = (const float*)d_in[22];
    const float* vsw2  = (const float*)d_in[23];
    const float* vsb2  = (const float*)d_in[24];
    const float* vsw3  = (const float*)d_in[25];
    const float* vsb3  = (const float*)d_in[26];

    const int SM2 = 130112;
    const int SM3 = (10400 + 13824 + 256 + 104 + 104 + 128) * 4;

    cudaFuncSetAttribute(k_taskmap, cudaFuncAttributeMaxDynamicSharedMemorySize, SM1_BYTES);
    cudaFuncSetAttribute(k_vv_mma, cudaFuncAttributeMaxDynamicSharedMemorySize, SM2);
    cudaFuncSetAttribute(k_vs, cudaFuncAttributeMaxDynamicSharedMemorySize, SM3);

    k_origin<<<1, 128>>>(t1w1, t1b1, t1w2, t1b2, t1w3, t1b3,
                         t2w1, t2b1, t2w2, t2b2, t2w3, t2b3);
    k_prep<<<380, 256>>>(vvw2);
    k_prep2<<<125, 256>>>(t1w2, t2w2, t1w1, t2w1, t1w3, t2w3);
    k_taskmap<<<NPTS / 32, 192, SM1_BYTES>>>(x, t1b1, t1b2, t1b3,
                                             t2b1, t2b2, t2b3);
    k_vv_mma<<<NPTS / 128, 512, SM2>>>(vvw1, vvb1, vva1, vvb2, vva2, vvw3, vvb3);
    k_vs<<<NPTS / 128, 224, SM3>>>(x, vsw1, vsb1, vsw2, vsb2, vsw3, vsb3,
                                   (float*)d_out);
}